// round 9
// baseline (speedup 1.0000x reference)
#include <cuda_runtime.h>
#include <cuda_bf16.h>
#include <math.h>
#include <stdint.h>

// ---------------- constants ----------------
#define B_   2
#define L_   2048
#define DM   1024          // D_MODEL
#define NH   16            // NHEAD
#define HD   64            // HD_ATT
#define DI   2048          // D_INNER
#define HS   32            // H_SSM
#define P_   64            // HEADDIM
#define NST  128           // D_STATE
#define CONVD 2304         // CONV_DIM
#define DINP 4384          // D_IN_PROJ
#define CH   256           // CHUNK
#define NC   8             // L/CHUNK
#define DFF  2048
#define ALPHA 1.68f
#define EPSN 1e-5f

#define ROWS (B_*L_)       // 4096

// ---------------- scratch ----------------
static const long long SZ_BIG  = (long long)ROWS*DINP;
static const long long SZ_HB   = (long long)ROWS*DM;
static const long long SZ_XBC  = (long long)ROWS*CONVD;
static const long long SZ_DT   = (long long)ROWS*HS;
static const long long SZ_XDT  = (long long)ROWS*DI;
static const long long SZ_ACS  = (long long)B_*HS*L_;
static const long long SZ_CB   = (long long)B_*NC*CH*CH;
static const long long SZ_ST   = (long long)B_*HS*NC*NST*P_;
static const long long SZ_Y    = (long long)ROWS*DI;

static const long long OFF_BIG = 0;
static const long long OFF_H   = OFF_BIG + SZ_BIG;
static const long long OFF_O   = OFF_H   + SZ_HB;
static const long long OFF_X   = OFF_O   + SZ_HB;
static const long long OFF_XBC = OFF_X   + SZ_HB;
static const long long OFF_DT  = OFF_XBC + SZ_XBC;
static const long long OFF_XDT = OFF_DT  + SZ_DT;
static const long long OFF_ACS = OFF_XDT + SZ_XDT;
static const long long OFF_CB  = OFF_ACS + SZ_ACS;
static const long long OFF_STA = OFF_CB  + SZ_CB;
static const long long OFF_SPR = OFF_STA + SZ_ST;
static const long long OFF_Y   = OFF_SPR + SZ_ST;
static const long long OFF_FF  = OFF_Y   + SZ_Y;
static const long long TOTALF  = OFF_FF  + SZ_Y;

__device__ float g_scratch[74842112]; // == TOTALF floats (~300 MB)

// ---------------- helpers ----------------
__device__ __forceinline__ float silu_f(float x) {
    return x / (1.f + __expf(-x));
}
__device__ __forceinline__ float softplus_f(float x) {
    return (x > 20.f) ? x : log1pf(__expf(x));
}
__device__ __forceinline__ void split_bf16(float x, __nv_bfloat16& hi, __nv_bfloat16& lo) {
    hi = __float2bfloat16_rn(x);
    lo = __float2bfloat16_rn(x - __bfloat162float(hi));
}
__device__ __forceinline__ uint32_t pack2(__nv_bfloat16 a, __nv_bfloat16 b) {
    __nv_bfloat162 h;
    h.x = a; h.y = b;
    return *(uint32_t*)&h;
}
__device__ __forceinline__ void mma_bf16(float* c, const uint32_t* a, const uint32_t* b) {
    asm volatile(
        "mma.sync.aligned.m16n8k16.row.col.f32.bf16.bf16.f32 "
        "{%0,%1,%2,%3}, {%4,%5,%6,%7}, {%8,%9}, {%0,%1,%2,%3};"
        : "+f"(c[0]), "+f"(c[1]), "+f"(c[2]), "+f"(c[3])
        : "r"(a[0]), "r"(a[1]), "r"(a[2]), "r"(a[3]), "r"(b[0]), "r"(b[1]));
}

// ---------------- bf16x2 split tensor-core NT GEMM, static double-buffer ----------------
// C[M,N] = A[M,K] @ W[N,K]^T (+bias), fp32 in/out, ~16-bit effective mantissa.
// CTA tile 128x128, stage = k16, two static stages (48KB exactly), 256 threads.
// One __syncthreads per k16; STS/convert + LDG overlap the MMA phase.
// Requires: M % 128 == 0, K % 32 == 0, rows 16B-aligned.
// GATED: A element = A[r][k] * silu(A[r][k + DFF])  (fused SwiGLU for fc2).
#define SST2 12
template<bool GATED>
__global__ __launch_bounds__(256, 2)
void gemm_tc(const float* __restrict__ A, const float* __restrict__ W,
             const float* __restrict__ bias, float* __restrict__ C,
             int M, int N, int K, int lda, int ldw, int ldc,
             long long sA, long long sW, long long sC)
{
    A += (long long)blockIdx.z * sA;
    W += (long long)blockIdx.z * sW;
    C += (long long)blockIdx.z * sC;

    __shared__ uint32_t Ahi[2][128][SST2];
    __shared__ uint32_t Alo[2][128][SST2];
    __shared__ uint32_t Bhi[2][128][SST2];
    __shared__ uint32_t Blo[2][128][SST2];

    int bm = blockIdx.y * 128, bn = blockIdx.x * 128;
    int tid = threadIdx.x;
    int wid = tid >> 5, lane = tid & 31;
    int wm = (wid >> 2) * 64;
    int wn = (wid & 3) * 32;
    int lr = lane >> 2, lc = lane & 3;

    int srow = tid >> 2;          // 0..63
    int sk4 = (tid & 3) << 2;     // 0,4,8,12 within k16
    int sk2 = sk4 >> 1;           // word offset

    float acc[4][4][4];
    #pragma unroll
    for (int i = 0; i < 4; i++)
        #pragma unroll
        for (int j = 0; j < 4; j++)
            #pragma unroll
            for (int r = 0; r < 4; r++) acc[i][j][r] = 0.f;

    float4 ca0, ca1, cw0, cw1;   // block to STS next
    float4 na0, na1, nw0, nw1;   // prefetched block

#define LOAD_BLK(a0, a1, w0, w1, kc) do { \
    const float* ap0 = A + (long long)(bm + srow) * lda + (kc) + sk4; \
    const float* ap1 = A + (long long)(bm + srow + 64) * lda + (kc) + sk4; \
    a0 = *(const float4*)ap0; \
    a1 = *(const float4*)ap1; \
    if (GATED) { \
        float4 g0 = *(const float4*)(ap0 + DFF); \
        float4 g1 = *(const float4*)(ap1 + DFF); \
        a0.x *= silu_f(g0.x); a0.y *= silu_f(g0.y); a0.z *= silu_f(g0.z); a0.w *= silu_f(g0.w); \
        a1.x *= silu_f(g1.x); a1.y *= silu_f(g1.y); a1.z *= silu_f(g1.z); a1.w *= silu_f(g1.w); \
    } \
    w0 = (bn + srow < N) \
        ? *(const float4*)(W + (long long)(bn + srow) * ldw + (kc) + sk4) \
        : make_float4(0.f, 0.f, 0.f, 0.f); \
    w1 = (bn + srow + 64 < N) \
        ? *(const float4*)(W + (long long)(bn + srow + 64) * ldw + (kc) + sk4) \
        : make_float4(0.f, 0.f, 0.f, 0.f); \
} while (0)

#define STS_ONE(S, v, ARRH, ARRL, row) do { \
    __nv_bfloat16 h0,l0,h1,l1,h2,l2,h3,l3; \
    split_bf16((v).x, h0, l0); split_bf16((v).y, h1, l1); \
    split_bf16((v).z, h2, l2); split_bf16((v).w, h3, l3); \
    ARRH[S][row][sk2]     = pack2(h0, h1); \
    ARRH[S][row][sk2 + 1] = pack2(h2, h3); \
    ARRL[S][row][sk2]     = pack2(l0, l1); \
    ARRL[S][row][sk2 + 1] = pack2(l2, l3); \
} while (0)

#define STS_BLK(S) do { \
    STS_ONE(S, ca0, Ahi, Alo, srow); \
    STS_ONE(S, ca1, Ahi, Alo, (srow + 64)); \
    STS_ONE(S, cw0, Bhi, Blo, srow); \
    STS_ONE(S, cw1, Bhi, Blo, (srow + 64)); \
} while (0)

#define MMA_STAGE(S) do { \
    uint32_t bhf[4][2], blf[4][2]; \
    _Pragma("unroll") \
    for (int jn = 0; jn < 4; jn++) { \
        int cdx = wn + jn * 8 + lr; \
        bhf[jn][0] = Bhi[S][cdx][lc];     bhf[jn][1] = Bhi[S][cdx][lc + 4]; \
        blf[jn][0] = Blo[S][cdx][lc];     blf[jn][1] = Blo[S][cdx][lc + 4]; \
    } \
    _Pragma("unroll") \
    for (int im = 0; im < 4; im++) { \
        int r = wm + im * 16 + lr; \
        uint32_t ah[4], al[4]; \
        ah[0] = Ahi[S][r][lc];     ah[1] = Ahi[S][r + 8][lc]; \
        ah[2] = Ahi[S][r][lc + 4]; ah[3] = Ahi[S][r + 8][lc + 4]; \
        al[0] = Alo[S][r][lc];     al[1] = Alo[S][r + 8][lc]; \
        al[2] = Alo[S][r][lc + 4]; al[3] = Alo[S][r + 8][lc + 4]; \
        _Pragma("unroll") \
        for (int jn = 0; jn < 4; jn++) { \
            mma_bf16(acc[im][jn], ah, blf[jn]); \
            mma_bf16(acc[im][jn], al, bhf[jn]); \
            mma_bf16(acc[im][jn], ah, bhf[jn]); \
        } \
    } \
} while (0)

    // prologue: D0 -> s0, D1 staged in regs
    LOAD_BLK(ca0, ca1, cw0, cw1, 0);
    STS_BLK(0);
    LOAD_BLK(ca0, ca1, cw0, cw1, 16);
    __syncthreads();

    for (int k0 = 0; k0 < K; k0 += 32) {
        bool hn = (k0 + 32) < K;
        // iter A: LDG D_{k0+32}; STS D_{k0+16} -> s1; MMA(s0)
        if (hn) LOAD_BLK(na0, na1, nw0, nw1, k0 + 32);
        STS_BLK(1);
        MMA_STAGE(0);
        __syncthreads();
        // iter B: LDG D_{k0+48}; STS D_{k0+32} -> s0; MMA(s1)
        if (hn) { ca0 = na0; ca1 = na1; cw0 = nw0; cw1 = nw1; }
        bool hn2 = (k0 + 48) < K;
        if (hn2) LOAD_BLK(na0, na1, nw0, nw1, k0 + 48);
        if (hn) STS_BLK(0);
        MMA_STAGE(1);
        __syncthreads();
        if (hn2) { ca0 = na0; ca1 = na1; cw0 = nw0; cw1 = nw1; }
    }

#undef LOAD_BLK
#undef STS_ONE
#undef STS_BLK
#undef MMA_STAGE

    #pragma unroll
    for (int im = 0; im < 4; im++) {
        #pragma unroll
        for (int jn = 0; jn < 4; jn++) {
            int gm = bm + wm + im * 16 + lr;
            int gc = bn + wn + jn * 8 + 2 * lc;
            if (gc < N) {
                float b0 = bias ? bias[gc] : 0.f;
                float b1 = bias ? bias[gc + 1] : 0.f;
                float* p0 = C + (long long)gm * ldc + gc;
                p0[0] = acc[im][jn][0] + b0;
                p0[1] = acc[im][jn][1] + b1;
                float* p1 = C + (long long)(gm + 8) * ldc + gc;
                p1[0] = acc[im][jn][2] + b0;
                p1[1] = acc[im][jn][3] + b1;
            }
        }
    }
}

// ---------------- tensor-core flash attention (non-causal), split-bf16 ----------------
__global__ __launch_bounds__(256)
void attn_tc_kernel(const float* __restrict__ qkv, float* __restrict__ o)
{
    __shared__ uint32_t Khi[64][36];
    __shared__ uint32_t Klo[64][36];
    __shared__ __nv_bfloat16 Vthi[64][72];
    __shared__ __nv_bfloat16 Vtlo[64][72];

    int bh = blockIdx.y;
    int b = bh >> 4, h = bh & 15;
    int tid = threadIdx.x;
    int wid = tid >> 5, lane = tid & 31;
    int lr = lane >> 2, lc = lane & 3;
    int qrow0 = blockIdx.x * 128 + wid * 16;

    uint32_t qhi[4][4], qlo[4][4];
    {
        const float* qp = qkv + (long long)(b * L_) * 3072 + h * 64;
        #pragma unroll
        for (int kc = 0; kc < 4; kc++) {
            #pragma unroll
            for (int half = 0; half < 2; half++) {
                int col = kc * 16 + 2 * lc + half * 8;
                float2 v0 = *(const float2*)(qp + (long long)(qrow0 + lr) * 3072 + col);
                float2 v1 = *(const float2*)(qp + (long long)(qrow0 + lr + 8) * 3072 + col);
                __nv_bfloat16 h0,l0,h1,l1;
                split_bf16(v0.x * 0.125f, h0, l0); split_bf16(v0.y * 0.125f, h1, l1);
                qhi[kc][half * 2]     = pack2(h0, h1);
                qlo[kc][half * 2]     = pack2(l0, l1);
                split_bf16(v1.x * 0.125f, h0, l0); split_bf16(v1.y * 0.125f, h1, l1);
                qhi[kc][half * 2 + 1] = pack2(h0, h1);
                qlo[kc][half * 2 + 1] = pack2(l0, l1);
            }
        }
    }

    float o_acc[8][4];
    #pragma unroll
    for (int j = 0; j < 8; j++)
        #pragma unroll
        for (int r = 0; r < 4; r++) o_acc[j][r] = 0.f;
    float mrow0 = -1e30f, mrow1 = -1e30f;
    float lrow0 = 0.f, lrow1 = 0.f;

    for (int kt = 0; kt < L_ / 64; kt++) {
        const float* kb = qkv + (long long)(b * L_ + kt * 64) * 3072 + 1024 + h * 64;
        const float* vb = kb + 1024;
        #pragma unroll
        for (int i = 0; i < 4; i++) {
            int idx = tid + i * 256;
            int r = idx >> 4, c4 = (idx & 15) << 2;
            float4 kv = *(const float4*)(kb + (long long)r * 3072 + c4);
            __nv_bfloat16 h0,l0,h1,l1,h2,l2,h3,l3;
            split_bf16(kv.x, h0, l0); split_bf16(kv.y, h1, l1);
            split_bf16(kv.z, h2, l2); split_bf16(kv.w, h3, l3);
            int c2 = c4 >> 1;
            Khi[r][c2]     = pack2(h0, h1);
            Khi[r][c2 + 1] = pack2(h2, h3);
            Klo[r][c2]     = pack2(l0, l1);
            Klo[r][c2 + 1] = pack2(l2, l3);
            float4 vv = *(const float4*)(vb + (long long)r * 3072 + c4);
            __nv_bfloat16 vh, vl;
            split_bf16(vv.x, vh, vl); Vthi[c4 + 0][r] = vh; Vtlo[c4 + 0][r] = vl;
            split_bf16(vv.y, vh, vl); Vthi[c4 + 1][r] = vh; Vtlo[c4 + 1][r] = vl;
            split_bf16(vv.z, vh, vl); Vthi[c4 + 2][r] = vh; Vtlo[c4 + 2][r] = vl;
            split_bf16(vv.w, vh, vl); Vthi[c4 + 3][r] = vh; Vtlo[c4 + 3][r] = vl;
        }
        __syncthreads();

        float s[8][4];
        #pragma unroll
        for (int j = 0; j < 8; j++)
            #pragma unroll
            for (int r = 0; r < 4; r++) s[j][r] = 0.f;
        #pragma unroll
        for (int kc = 0; kc < 4; kc++) {
            #pragma unroll
            for (int jn = 0; jn < 8; jn++) {
                int n = jn * 8 + lr;
                uint32_t bhf[2], blf[2];
                bhf[0] = Khi[n][kc * 8 + lc];
                bhf[1] = Khi[n][kc * 8 + lc + 4];
                blf[0] = Klo[n][kc * 8 + lc];
                blf[1] = Klo[n][kc * 8 + lc + 4];
                mma_bf16(s[jn], qhi[kc], blf);
                mma_bf16(s[jn], qlo[kc], bhf);
                mma_bf16(s[jn], qhi[kc], bhf);
            }
        }

        float t0 = -1e30f, t1 = -1e30f;
        #pragma unroll
        for (int jn = 0; jn < 8; jn++) {
            t0 = fmaxf(t0, fmaxf(s[jn][0], s[jn][1]));
            t1 = fmaxf(t1, fmaxf(s[jn][2], s[jn][3]));
        }
        t0 = fmaxf(t0, __shfl_xor_sync(0xffffffffu, t0, 1));
        t0 = fmaxf(t0, __shfl_xor_sync(0xffffffffu, t0, 2));
        t1 = fmaxf(t1, __shfl_xor_sync(0xffffffffu, t1, 1));
        t1 = fmaxf(t1, __shfl_xor_sync(0xffffffffu, t1, 2));
        float m0n = fmaxf(mrow0, t0), m1n = fmaxf(mrow1, t1);
        float sc0 = __expf(mrow0 - m0n), sc1 = __expf(mrow1 - m1n);
        mrow0 = m0n; mrow1 = m1n;
        lrow0 *= sc0; lrow1 *= sc1;
        #pragma unroll
        for (int j = 0; j < 8; j++) {
            o_acc[j][0] *= sc0; o_acc[j][1] *= sc0;
            o_acc[j][2] *= sc1; o_acc[j][3] *= sc1;
        }

        uint32_t phi[4][4], plo[4][4];
        #pragma unroll
        for (int jn = 0; jn < 8; jn++) {
            float p0 = __expf(s[jn][0] - m0n);
            float p1 = __expf(s[jn][1] - m0n);
            float p2 = __expf(s[jn][2] - m1n);
            float p3 = __expf(s[jn][3] - m1n);
            lrow0 += p0 + p1;
            lrow1 += p2 + p3;
            __nv_bfloat16 h0,l0,h1,l1,h2,l2,h3,l3;
            split_bf16(p0, h0, l0); split_bf16(p1, h1, l1);
            split_bf16(p2, h2, l2); split_bf16(p3, h3, l3);
            int kc = jn >> 1;
            int off = (jn & 1) * 2;
            phi[kc][off]     = pack2(h0, h1);
            phi[kc][off + 1] = pack2(h2, h3);
            plo[kc][off]     = pack2(l0, l1);
            plo[kc][off + 1] = pack2(l2, l3);
        }

        #pragma unroll
        for (int kc = 0; kc < 4; kc++) {
            #pragma unroll
            for (int jd = 0; jd < 8; jd++) {
                int d = jd * 8 + lr;
                uint32_t bhf[2], blf[2];
                bhf[0] = *(const uint32_t*)&Vthi[d][2 * (kc * 8 + lc)];
                bhf[1] = *(const uint32_t*)&Vthi[d][2 * (kc * 8 + lc + 4)];
                blf[0] = *(const uint32_t*)&Vtlo[d][2 * (kc * 8 + lc)];
                blf[1] = *(const uint32_t*)&Vtlo[d][2 * (kc * 8 + lc + 4)];
                mma_bf16(o_acc[jd], phi[kc], blf);
                mma_bf16(o_acc[jd], plo[kc], bhf);
                mma_bf16(o_acc[jd], phi[kc], bhf);
            }
        }
        __syncthreads();
    }

    lrow0 += __shfl_xor_sync(0xffffffffu, lrow0, 1);
    lrow0 += __shfl_xor_sync(0xffffffffu, lrow0, 2);
    lrow1 += __shfl_xor_sync(0xffffffffu, lrow1, 1);
    lrow1 += __shfl_xor_sync(0xffffffffu, lrow1, 2);
    float inv0 = 1.f / lrow0, inv1 = 1.f / lrow1;
    #pragma unroll
    for (int jd = 0; jd < 8; jd++) {
        int col = h * 64 + jd * 8 + 2 * lc;
        float* p0 = o + (long long)(b * L_ + qrow0 + lr) * DM + col;
        p0[0] = o_acc[jd][0] * inv0;
        p0[1] = o_acc[jd][1] * inv0;
        float* p1 = o + (long long)(b * L_ + qrow0 + lr + 8) * DM + col;
        p1[0] = o_acc[jd][2] * inv1;
        p1[1] = o_acc[jd][3] * inv1;
    }
}

// ---------------- tensor-core SSD chunk-states ----------------
__global__ __launch_bounds__(256)
void states_tc_kernel(const float* __restrict__ xbc, const float* __restrict__ xdt,
                      const float* __restrict__ Acs, float* __restrict__ states)
{
    extern __shared__ uint32_t dynst[];
    uint32_t* Ah = dynst;
    uint32_t* Al = Ah + 128 * 36;
    uint32_t* Bh = Al + 128 * 36;
    uint32_t* Bl = Bh + 64 * 36;
    float* dec_sh = (float*)(Bl + 64 * 36);
    __nv_bfloat16* Ah_e = (__nv_bfloat16*)Ah;
    __nv_bfloat16* Al_e = (__nv_bfloat16*)Al;
    __nv_bfloat16* Bh_e = (__nv_bfloat16*)Bh;
    __nv_bfloat16* Bl_e = (__nv_bfloat16*)Bl;

    int blk = blockIdx.x;
    int ck = blk & 7;
    int bh = blk >> 3;
    int h = bh & 31, b = bh >> 5;
    int tid = threadIdx.x;
    int wid = tid >> 5, lane = tid & 31;
    int lr = lane >> 2, lc = lane & 3;
    long long rowbase = (long long)(b * L_ + ck * 256);

    dec_sh[tid] = Acs[(long long)bh * L_ + ck * 256 + tid];
    __syncthreads();
    float aLast = dec_sh[255];
    float mya = dec_sh[tid];
    __syncthreads();
    dec_sh[tid] = __expf(aLast - mya);

    float acc[8][4];
    #pragma unroll
    for (int j = 0; j < 8; j++)
        #pragma unroll
        for (int r = 0; r < 4; r++) acc[j][r] = 0.f;

    for (int kt = 0; kt < 4; kt++) {
        int l0 = kt * 64;
        #pragma unroll
        for (int i = 0; i < 32; i++) {
            int idx = tid + i * 256;
            int n = idx & 127;
            int c = idx >> 7;
            float v = xbc[(rowbase + l0 + c) * CONVD + DI + n] * dec_sh[l0 + c];
            __nv_bfloat16 hi, lo; split_bf16(v, hi, lo);
            Ah_e[n * 72 + c] = hi;
            Al_e[n * 72 + c] = lo;
        }
        #pragma unroll
        for (int i = 0; i < 16; i++) {
            int idx = tid + i * 256;
            int p = idx & 63;
            int c = idx >> 6;
            float v = xdt[(rowbase + l0 + c) * DI + h * 64 + p];
            __nv_bfloat16 hi, lo; split_bf16(v, hi, lo);
            Bh_e[p * 72 + c] = hi;
            Bl_e[p * 72 + c] = lo;
        }
        __syncthreads();
        #pragma unroll
        for (int kk2 = 0; kk2 < 32; kk2 += 8) {
            int r = wid * 16 + lr;
            uint32_t ah[4], al[4];
            ah[0] = Ah[r * 36 + kk2 + lc];
            ah[1] = Ah[(r + 8) * 36 + kk2 + lc];
            ah[2] = Ah[r * 36 + kk2 + lc + 4];
            ah[3] = Ah[(r + 8) * 36 + kk2 + lc + 4];
            al[0] = Al[r * 36 + kk2 + lc];
            al[1] = Al[(r + 8) * 36 + kk2 + lc];
            al[2] = Al[r * 36 + kk2 + lc + 4];
            al[3] = Al[(r + 8) * 36 + kk2 + lc + 4];
            #pragma unroll
            for (int jn = 0; jn < 8; jn++) {
                int n = jn * 8 + lr;
                uint32_t bhf[2], blf[2];
                bhf[0] = Bh[n * 36 + kk2 + lc];
                bhf[1] = Bh[n * 36 + kk2 + lc + 4];
                blf[0] = Bl[n * 36 + kk2 + lc];
                blf[1] = Bl[n * 36 + kk2 + lc + 4];
                mma_bf16(acc[jn], ah, blf);
                mma_bf16(acc[jn], al, bhf);
                mma_bf16(acc[jn], ah, bhf);
            }
        }
        __syncthreads();
    }

    float* base = states + (long long)(bh * NC + ck) * 8192;
    int n0 = wid * 16 + lr;
    #pragma unroll
    for (int jn = 0; jn < 8; jn++) {
        int p = jn * 8 + 2 * lc;
        float* p0 = base + n0 * 64 + p;
        p0[0] = acc[jn][0];
        p0[1] = acc[jn][1];
        float* p1 = base + (n0 + 8) * 64 + p;
        p1[0] = acc[jn][2];
        p1[1] = acc[jn][3];
    }
}

// ---------------- tensor-core SSD output ----------------
__global__ __launch_bounds__(256)
void y_tc_kernel(const float* __restrict__ xbc, const float* __restrict__ xdt,
                 const float* __restrict__ Acs, const float* __restrict__ CB,
                 const float* __restrict__ Sprev, const float* __restrict__ Dv,
                 float* __restrict__ Y)
{
    extern __shared__ uint32_t dyny[];
    uint32_t* Ah = dyny;
    uint32_t* Al = Ah + 128 * 36;
    uint32_t* Bh = Al + 128 * 36;
    uint32_t* Bl = Bh + 64 * 36;
    float* acs_sh = (float*)(Bl + 64 * 36);
    float* eA_sh  = acs_sh + 256;
    __nv_bfloat16* Ah_e = (__nv_bfloat16*)Ah;
    __nv_bfloat16* Al_e = (__nv_bfloat16*)Al;
    __nv_bfloat16* Bh_e = (__nv_bfloat16*)Bh;
    __nv_bfloat16* Bl_e = (__nv_bfloat16*)Bl;

    int blk = blockIdx.x;
    int lh = blk & 1;
    int ck = (blk >> 1) & 7;
    int bh = blk >> 4;
    int h = bh & 31, b = bh >> 5;
    int tid = threadIdx.x;
    int wid = tid >> 5, lane = tid & 31;
    int lr = lane >> 2, lc = lane & 3;
    long long rowbase = (long long)(b * L_ + ck * 256);

    acs_sh[tid] = Acs[(long long)bh * L_ + ck * 256 + tid];
    __syncthreads();
    if (tid < 128) eA_sh[tid] = __expf(acs_sh[lh * 128 + tid]);

    float acc[8][4];
    #pragma unroll
    for (int j = 0; j < 8; j++)
        #pragma unroll
        for (int r = 0; r < 4; r++) acc[j][r] = 0.f;

    const float* cbp = CB + (long long)(b * NC + ck) * (CH * CH);
    int ndiag = (lh == 0) ? 2 : 4;

    for (int kt = 0; kt < ndiag + 2; kt++) {
        if (kt < ndiag) {
            int s0 = kt * 64;
            #pragma unroll
            for (int i = 0; i < 32; i++) {
                int idx = tid + i * 256;
                int l = idx & 127;
                int s = idx >> 7;
                int gl = lh * 128 + l;
                int gs = s0 + s;
                float v = 0.f;
                if (gs <= gl) v = cbp[gs * 256 + gl] * __expf(acs_sh[gl] - acs_sh[gs]);
                __nv_bfloat16 hi, lo; split_bf16(v, hi, lo);
                Ah_e[l * 72 + s] = hi;
                Al_e[l * 72 + s] = lo;
            }
            #pragma unroll
            for (int i = 0; i < 16; i++) {
                int idx = tid + i * 256;
                int p = idx & 63;
                int s = idx >> 6;
                float v = xdt[(rowbase + s0 + s) * DI + h * 64 + p];
                __nv_bfloat16 hi, lo; split_bf16(v, hi, lo);
                Bh_e[p * 72 + s] = hi;
                Bl_e[p * 72 + s] = lo;
            }
        } else {
            int n0 = (kt - ndiag) * 64;
            #pragma unroll
            for (int i = 0; i < 32; i++) {
                int idx = tid + i * 256;
                int c = idx & 63;
                int l = idx >> 6;
                float v = xbc[(rowbase + lh * 128 + l) * CONVD + DI + NST + n0 + c] * eA_sh[l];
                __nv_bfloat16 hi, lo; split_bf16(v, hi, lo);
                Ah_e[l * 72 + c] = hi;
                Al_e[l * 72 + c] = lo;
            }
            #pragma unroll
            for (int i = 0; i < 16; i++) {
                int idx = tid + i * 256;
                int p = idx & 63;
                int c = idx >> 6;
                float v = Sprev[(long long)(bh * NC + ck) * 8192 + (n0 + c) * 64 + p];
                __nv_bfloat16 hi, lo; split_bf16(v, hi, lo);
                Bh_e[p * 72 + c] = hi;
                Bl_e[p * 72 + c] = lo;
            }
        }
        __syncthreads();
        #pragma unroll
        for (int kk2 = 0; kk2 < 32; kk2 += 8) {
            int r = wid * 16 + lr;
            uint32_t ah[4], al[4];
            ah[0] = Ah[r * 36 + kk2 + lc];
            ah[1] = Ah[(r + 8) * 36 + kk2 + lc];
            ah[2] = Ah[r * 36 + kk2 + lc + 4];
            ah[3] = Ah[(r + 8) * 36 + kk2 + lc + 4];
            al[0] = Al[r * 36 + kk2 + lc];
            al[1] = Al[(r + 8) * 36 + kk2 + lc];
            al[2] = Al[r * 36 + kk2 + lc + 4];
            al[3] = Al[(r + 8) * 36 + kk2 + lc + 4];
            #pragma unroll
            for (int jn = 0; jn < 8; jn++) {
                int n = jn * 8 + lr;
                uint32_t bhf[2], blf[2];
                bhf[0] = Bh[n * 36 + kk2 + lc];
                bhf[1] = Bh[n * 36 + kk2 + lc + 4];
                blf[0] = Bl[n * 36 + kk2 + lc];
                blf[1] = Bl[n * 36 + kk2 + lc + 4];
                mma_bf16(acc[jn], ah, blf);
                mma_bf16(acc[jn], al, bhf);
                mma_bf16(acc[jn], ah, bhf);
            }
        }
        __syncthreads();
    }

    float Dh = Dv[h];
    int r0 = wid * 16 + lr;
    #pragma unroll
    for (int jn = 0; jn < 8; jn++) {
        int col = jn * 8 + 2 * lc;
        long long grow0 = rowbase + lh * 128 + r0;
        const float* xs0 = xbc + grow0 * CONVD + h * 64 + col;
        float* yp0 = Y + grow0 * DI + h * 64 + col;
        yp0[0] = acc[jn][0] + Dh * xs0[0];
        yp0[1] = acc[jn][1] + Dh * xs0[1];
        long long grow1 = grow0 + 8;
        const float* xs1 = xbc + grow1 * CONVD + h * 64 + col;
        float* yp1 = Y + grow1 * DI + h * 64 + col;
        yp1[0] = acc[jn][2] + Dh * xs1[0];
        yp1[1] = acc[jn][3] + Dh * xs1[1];
    }
}

// ---------------- rmsnorm ----------------
__global__ void rmsnorm_kernel(const float* __restrict__ a, const float* __restrict__ b,
                               float alpha, const float* __restrict__ w,
                               float* __restrict__ out, int D)
{
    long long row = blockIdx.x;
    const float* ap = a + row * D;
    const float* bp = b ? (b + row * D) : nullptr;
    int per = D >> 8;
    float v[8];
    float ss = 0.f;
    for (int j = 0; j < per; j++) {
        int i = threadIdx.x + j * 256;
        float x = ap[i] + (bp ? alpha * bp[i] : 0.f);
        v[j] = x;
        ss += x * x;
    }
    __shared__ float red[256];
    red[threadIdx.x] = ss;
    __syncthreads();
    for (int off = 128; off; off >>= 1) {
        if (threadIdx.x < off) red[threadIdx.x] += red[threadIdx.x + off];
        __syncthreads();
    }
    float scale = rsqrtf(red[0] / D + EPSN);
    float* op = out + row * D;
    for (int j = 0; j < per; j++) {
        int i = threadIdx.x + j * 256;
        op[i] = v[j] * scale * w[i];
    }
}

// ---------------- gated rmsnorm ----------------
__global__ void gated_rmsnorm_kernel(const float* __restrict__ y, const float* __restrict__ z,
                                     int ldz, const float* __restrict__ w,
                                     float* __restrict__ out)
{
    long long row = blockIdx.x;
    const float* yp = y + row * DI;
    const float* zp = z + row * (long long)ldz;
    float v[8];
    float ss = 0.f;
    #pragma unroll
    for (int j = 0; j < 8; j++) {
        int i = threadIdx.x + j * 256;
        float x = yp[i] * silu_f(zp[i]);
        v[j] = x;
        ss += x * x;
    }
    __shared__ float red[256];
    red[threadIdx.x] = ss;
    __syncthreads();
    for (int off = 128; off; off >>= 1) {
        if (threadIdx.x < off) red[threadIdx.x] += red[threadIdx.x + off];
        __syncthreads();
    }
    float scale = rsqrtf(red[0] / DI + EPSN);
    float* op = out + row * DI;
    #pragma unroll
    for (int j = 0; j < 8; j++) {
        int i = threadIdx.x + j * 256;
        op[i] = v[j] * scale * w[i];
    }
}

// ---------------- depthwise causal conv (k=4) + bias + silu ----------------
__global__ void conv_kernel(const float* __restrict__ zx, const float* __restrict__ cw,
                            const float* __restrict__ cb, float* __restrict__ xbc)
{
    int idx = blockIdx.x * 256 + threadIdx.x;
    if (idx >= B_ * L_ * CONVD) return;
    int c = idx % CONVD;
    int t = (idx / CONVD) % L_;
    int b = idx / (CONVD * L_);
    float s = cb[c];
    #pragma unroll
    for (int k = 0; k < 4; k++) {
        int tt = t - 3 + k;
        if (tt >= 0)
            s += zx[((long long)(b * L_ + tt) * DINP) + DI + c] * cw[c * 4 + k];
    }
    xbc[idx] = silu_f(s);
}

// ---------------- dt (softplus) and xdt = xs*dt ----------------
__global__ void dtxdt_kernel(const float* __restrict__ zx, const float* __restrict__ xbc,
                             const float* __restrict__ dt_bias,
                             float* __restrict__ dtb, float* __restrict__ xdt)
{
    int idx = blockIdx.x * 256 + threadIdx.x;
    if (idx >= ROWS * DI) return;
    int p = idx & 63;
    int h = (idx >> 6) & 31;
    long long row = idx >> 11;
    float raw = zx[row * DINP + DI + CONVD + h] + dt_bias[h];
    float d = softplus_f(raw);
    xdt[idx] = xbc[row * CONVD + h * 64 + p] * d;
    if (p == 0) dtb[row * HS + h] = d;
}

// ---------------- per-chunk inclusive cumsum ----------------
__global__ void cumsum_kernel(const float* __restrict__ dtb, const float* __restrict__ A_log,
                              float* __restrict__ Acs)
{
    __shared__ float s[256];
    int blk = blockIdx.x;
    int ck = blk & 7;
    int bh = blk >> 3;
    int h = bh & 31;
    int b = bh >> 5;
    int l = threadIdx.x;
    int gl = ck * 256 + l;
    float a = -__expf(A_log[h]) * dtb[((long long)(b * L_ + gl)) * HS + h];
    s[l] = a;
    __syncthreads();
    for (int off = 1; off < 256; off <<= 1) {
        float t = (l >= off) ? s[l - off] : 0.f;
        __syncthreads();
        s[l] += t;
        __syncthreads();
    }
    Acs[(long long)bh * L_ + gl] = s[l];
}

// ---------------- inter-chunk scan ----------------
__global__ void scan_kernel(const float* __restrict__ states, const float* __restrict__ Acs,
                            float* __restrict__ Sprev)
{
    int bh = blockIdx.x;
    int tid = threadIdx.x;
    float S[32];
    #pragma unroll
    for (int j = 0; j < 32; j++) S[j] = 0.f;
    for (int c = 0; c < NC; c++) {
        float dc = __expf(Acs[(long long)bh * L_ + c * 256 + 255]);
        const float* sp = states + (long long)(bh * NC + c) * 8192;
        float* pp = Sprev + (long long)(bh * NC + c) * 8192;
        #pragma unroll
        for (int j = 0; j < 32; j++) {
            int idx = tid + j * 256;
            pp[idx] = S[j];
            S[j] = S[j] * dc + sp[idx];
        }
    }
}

// ---------------- host launcher ----------------
#define SSD_SMEM 57344

extern "C" void kernel_launch(void* const* d_in, const int* in_sizes, int n_in,
                              void* d_out, int out_size)
{
    const float* x_in       = (const float*)d_in[0];
    const float* attn_norm  = (const float*)d_in[1];
    const float* Wqkv       = (const float*)d_in[2];
    const float* Wqkv_b     = (const float*)d_in[3];
    const float* attn_out_w = (const float*)d_in[4];
    const float* attn_out_b = (const float*)d_in[5];
    const float* normf_w    = (const float*)d_in[6];
    const float* m_in_w     = (const float*)d_in[7];
    const float* m_conv_w   = (const float*)d_in[8];
    const float* m_conv_b   = (const float*)d_in[9];
    const float* m_dt_bias  = (const float*)d_in[10];
    const float* m_A_log    = (const float*)d_in[11];
    const float* m_D        = (const float*)d_in[12];
    const float* m_norm_w   = (const float*)d_in[13];
    const float* m_out_w    = (const float*)d_in[14];
    const float* fc1_w      = (const float*)d_in[15];
    const float* fc2_w      = (const float*)d_in[16];
    const float* final_norm = (const float*)d_in[17];
    float* out = (float*)d_out;

    float* scr = nullptr;
    cudaGetSymbolAddress((void**)&scr, g_scratch);

    cudaFuncSetAttribute(states_tc_kernel, cudaFuncAttributeMaxDynamicSharedMemorySize, SSD_SMEM);
    cudaFuncSetAttribute(y_tc_kernel, cudaFuncAttributeMaxDynamicSharedMemorySize, SSD_SMEM);

    float* bBIG = scr + OFF_BIG;
    float* bH   = scr + OFF_H;
    float* bO   = scr + OFF_O;
    float* bX   = scr + OFF_X;
    float* bXBC = scr + OFF_XBC;
    float* bDT  = scr + OFF_DT;
    float* bXDT = scr + OFF_XDT;
    float* bACS = scr + OFF_ACS;
    float* bCB  = scr + OFF_CB;
    float* bSTA = scr + OFF_STA;
    float* bSPR = scr + OFF_SPR;
    float* bY   = scr + OFF_Y;

    // ---- attention block ----
    rmsnorm_kernel<<<ROWS, 256>>>(x_in, nullptr, 0.f, attn_norm, bH, DM);
    gemm_tc<false><<<dim3(3072/128, ROWS/128, 1), 256>>>(bH, Wqkv, Wqkv_b, bBIG,
        ROWS, 3072, DM, DM, DM, 3072, 0, 0, 0);
    attn_tc_kernel<<<dim3(L_/128, B_*NH), 256>>>(bBIG, bO);
    gemm_tc<false><<<dim3(DM/128, ROWS/128, 1), 256>>>(bO, attn_out_w, attn_out_b, bH,
        ROWS, DM, DM, DM, DM, DM, 0, 0, 0);
    rmsnorm_kernel<<<ROWS, 256>>>(bH, x_in, 1.f, normf_w, bX, DM);

    // ---- mamba layers ----
    for (int i = 0; i < 4; i++) {
        const float* in_w   = m_in_w   + (long long)i * DINP * DM;
        const float* conv_w = m_conv_w + (long long)i * CONVD * 4;
        const float* conv_b = m_conv_b + (long long)i * CONVD;
        const float* dtbias = m_dt_bias+ (long long)i * HS;
        const float* Alog   = m_A_log  + (long long)i * HS;
        const float* Dv     = m_D      + (long long)i * HS;
        const float* nw     = m_norm_w + (long long)i * DI;
        const float* ow     = m_out_w  + (long long)i * DM * DI;

        gemm_tc<false><<<dim3((DINP+127)/128, ROWS/128, 1), 256>>>(bX, in_w, nullptr, bBIG,
            ROWS, DINP, DM, DM, DM, DINP, 0, 0, 0);
        conv_kernel<<<(ROWS*CONVD)/256, 256>>>(bBIG, conv_w, conv_b, bXBC);
        dtxdt_kernel<<<(ROWS*DI)/256, 256>>>(bBIG, bXBC, dtbias, bDT, bXDT);
        cumsum_kernel<<<B_*HS*NC, 256>>>(bDT, Alog, bACS);
        gemm_tc<false><<<dim3(2, 2, B_*NC), 256>>>(
            bXBC + DI, bXBC + DI + NST, nullptr, bCB,
            CH, CH, NST, CONVD, CONVD, CH,
            (long long)CH * CONVD, (long long)CH * CONVD, (long long)CH * CH);
        states_tc_kernel<<<B_*HS*NC, 256, SSD_SMEM>>>(bXBC, bXDT, bACS, bSTA);
        scan_kernel<<<B_*HS, 256>>>(bSTA, bACS, bSPR);
        y_tc_kernel<<<B_*HS*NC*2, 256, SSD_SMEM>>>(bXBC, bXDT, bACS, bCB, bSPR, Dv, bY);
        gated_rmsnorm_kernel<<<ROWS, 256>>>(bY, bBIG, DINP, nw, bY);
        gemm_tc<false><<<dim3(DM/128, ROWS/128, 1), 256>>>(bY, ow, nullptr, bX,
            ROWS, DM, DI, DI, DI, DM, 0, 0, 0);
    }

    // ---- MLP + final norm (SwiGLU fused into fc2 A-staging) ----
    gemm_tc<false><<<dim3((2*DFF)/128, ROWS/128, 1), 256>>>(bX, fc1_w, nullptr, bBIG,
        ROWS, 2*DFF, DM, DM, DM, 2*DFF, 0, 0, 0);
    gemm_tc<true><<<dim3(DM/128, ROWS/128, 1), 256>>>(bBIG, fc2_w, nullptr, bH,
        ROWS, DM, DFF, 2*DFF, DFF, DM, 0, 0, 0);
    rmsnorm_kernel<<<ROWS, 256>>>(bH, bX, ALPHA, final_norm, out, DM);
}

// round 10
// speedup vs baseline: 1.2757x; 1.2757x over previous
#include <cuda_runtime.h>
#include <cuda_bf16.h>
#include <math.h>
#include <stdint.h>

// ---------------- constants ----------------
#define B_   2
#define L_   2048
#define DM   1024          // D_MODEL
#define NH   16            // NHEAD
#define HD   64            // HD_ATT
#define DI   2048          // D_INNER
#define HS   32            // H_SSM
#define P_   64            // HEADDIM
#define NST  128           // D_STATE
#define CONVD 2304         // CONV_DIM
#define DINP 4384          // D_IN_PROJ
#define CH   256           // CHUNK
#define NC   8             // L/CHUNK
#define DFF  2048
#define ALPHA 1.68f
#define EPSN 1e-5f

#define ROWS (B_*L_)       // 4096

// ---------------- scratch ----------------
static const long long SZ_BIG  = (long long)ROWS*DINP;
static const long long SZ_HB   = (long long)ROWS*DM;
static const long long SZ_XBC  = (long long)ROWS*CONVD;
static const long long SZ_DT   = (long long)ROWS*HS;
static const long long SZ_XDT  = (long long)ROWS*DI;
static const long long SZ_ACS  = (long long)B_*HS*L_;
static const long long SZ_CB   = (long long)B_*NC*CH*CH;
static const long long SZ_ST   = (long long)B_*HS*NC*NST*P_;
static const long long SZ_Y    = (long long)ROWS*DI;

static const long long OFF_BIG = 0;
static const long long OFF_H   = OFF_BIG + SZ_BIG;
static const long long OFF_O   = OFF_H   + SZ_HB;
static const long long OFF_X   = OFF_O   + SZ_HB;
static const long long OFF_XBC = OFF_X   + SZ_HB;
static const long long OFF_DT  = OFF_XBC + SZ_XBC;
static const long long OFF_XDT = OFF_DT  + SZ_DT;
static const long long OFF_ACS = OFF_XDT + SZ_XDT;
static const long long OFF_CB  = OFF_ACS + SZ_ACS;
static const long long OFF_STA = OFF_CB  + SZ_CB;
static const long long OFF_SPR = OFF_STA + SZ_ST;
static const long long OFF_Y   = OFF_SPR + SZ_ST;
static const long long OFF_FF  = OFF_Y   + SZ_Y;
static const long long TOTALF  = OFF_FF  + SZ_Y;

__device__ float g_scratch[74842112]; // == TOTALF floats (~300 MB)

// ---------------- helpers ----------------
__device__ __forceinline__ float silu_f(float x) {
    return x / (1.f + __expf(-x));
}
__device__ __forceinline__ float softplus_f(float x) {
    return (x > 20.f) ? x : log1pf(__expf(x));
}
__device__ __forceinline__ void split_bf16(float x, __nv_bfloat16& hi, __nv_bfloat16& lo) {
    hi = __float2bfloat16_rn(x);
    lo = __float2bfloat16_rn(x - __bfloat162float(hi));
}
__device__ __forceinline__ uint32_t pack2(__nv_bfloat16 a, __nv_bfloat16 b) {
    __nv_bfloat162 h;
    h.x = a; h.y = b;
    return *(uint32_t*)&h;
}
__device__ __forceinline__ void mma_bf16(float* c, const uint32_t* a, const uint32_t* b) {
    asm volatile(
        "mma.sync.aligned.m16n8k16.row.col.f32.bf16.bf16.f32 "
        "{%0,%1,%2,%3}, {%4,%5,%6,%7}, {%8,%9}, {%0,%1,%2,%3};"
        : "+f"(c[0]), "+f"(c[1]), "+f"(c[2]), "+f"(c[3])
        : "r"(a[0]), "r"(a[1]), "r"(a[2]), "r"(a[3]), "r"(b[0]), "r"(b[1]));
}

// ---------------- bf16x2 split tensor-core NT GEMM, register-prefetch pipelined ----------------
// C[M,N] = A[M,K] @ W[N,K]^T (+bias), fp32 in/out, ~16-bit effective mantissa.
// CTA tile 128x128, K-tile 32, 256 threads = 8 warps (2x4), warp tile 64x32.
// Static SMEM (40KB), register LDG prefetch. Measured-best configuration (R6/R8).
// GATED: A element = A[r][k] * silu(A[r][k + DFF])  (fused SwiGLU for fc2).
#define SSTR 20
template<bool GATED>
__global__ __launch_bounds__(256, 2)
void gemm_tc(const float* __restrict__ A, const float* __restrict__ W,
             const float* __restrict__ bias, float* __restrict__ C,
             int M, int N, int K, int lda, int ldw, int ldc,
             long long sA, long long sW, long long sC)
{
    A += (long long)blockIdx.z * sA;
    W += (long long)blockIdx.z * sW;
    C += (long long)blockIdx.z * sC;

    __shared__ uint32_t Ahi[128][SSTR];
    __shared__ uint32_t Alo[128][SSTR];
    __shared__ uint32_t Bhi[128][SSTR];
    __shared__ uint32_t Blo[128][SSTR];

    int bm = blockIdx.y * 128, bn = blockIdx.x * 128;
    int tid = threadIdx.x;
    int wid = tid >> 5, lane = tid & 31;
    int wm = (wid >> 2) * 64;
    int wn = (wid & 3) * 32;
    int lr = lane >> 2;
    int lc = lane & 3;

    int sr = tid >> 3;
    int sc4 = (tid & 7) << 2;
    int sc2 = sc4 >> 1;

    float acc[4][4][4];
    #pragma unroll
    for (int i = 0; i < 4; i++)
        #pragma unroll
        for (int j = 0; j < 4; j++)
            #pragma unroll
            for (int r = 0; r < 4; r++) acc[i][j][r] = 0.f;

    float4 pa[4], pw[4];
    #pragma unroll
    for (int i = 0; i < 4; i++) {
        int r = sr + i * 32;
        const float* ap = A + (long long)(bm + r) * lda + sc4;
        float4 a = *(const float4*)ap;
        if (GATED) {
            float4 g = *(const float4*)(ap + DFF);
            a.x *= silu_f(g.x); a.y *= silu_f(g.y);
            a.z *= silu_f(g.z); a.w *= silu_f(g.w);
        }
        pa[i] = a;
        if (bn + r < N) pw[i] = *(const float4*)(W + (long long)(bn + r) * ldw + sc4);
        else            pw[i] = make_float4(0.f, 0.f, 0.f, 0.f);
    }

    for (int k0 = 0; k0 < K; k0 += 32) {
        #pragma unroll
        for (int i = 0; i < 4; i++) {
            int r = sr + i * 32;
            __nv_bfloat16 h0,l0,h1,l1,h2,l2,h3,l3;
            split_bf16(pa[i].x, h0, l0); split_bf16(pa[i].y, h1, l1);
            split_bf16(pa[i].z, h2, l2); split_bf16(pa[i].w, h3, l3);
            Ahi[r][sc2]     = pack2(h0, h1);
            Ahi[r][sc2 + 1] = pack2(h2, h3);
            Alo[r][sc2]     = pack2(l0, l1);
            Alo[r][sc2 + 1] = pack2(l2, l3);
            split_bf16(pw[i].x, h0, l0); split_bf16(pw[i].y, h1, l1);
            split_bf16(pw[i].z, h2, l2); split_bf16(pw[i].w, h3, l3);
            Bhi[r][sc2]     = pack2(h0, h1);
            Bhi[r][sc2 + 1] = pack2(h2, h3);
            Blo[r][sc2]     = pack2(l0, l1);
            Blo[r][sc2 + 1] = pack2(l2, l3);
        }
        __syncthreads();

        if (k0 + 32 < K) {
            int kn = k0 + 32;
            #pragma unroll
            for (int i = 0; i < 4; i++) {
                int r = sr + i * 32;
                const float* ap = A + (long long)(bm + r) * lda + kn + sc4;
                float4 a = *(const float4*)ap;
                if (GATED) {
                    float4 g = *(const float4*)(ap + DFF);
                    a.x *= silu_f(g.x); a.y *= silu_f(g.y);
                    a.z *= silu_f(g.z); a.w *= silu_f(g.w);
                }
                pa[i] = a;
                if (bn + r < N) pw[i] = *(const float4*)(W + (long long)(bn + r) * ldw + kn + sc4);
                else            pw[i] = make_float4(0.f, 0.f, 0.f, 0.f);
            }
        }

        #pragma unroll
        for (int kk2 = 0; kk2 < 16; kk2 += 8) {
            uint32_t bhf[4][2], blf[4][2];
            #pragma unroll
            for (int jn = 0; jn < 4; jn++) {
                int cdx = wn + jn * 8 + lr;
                bhf[jn][0] = Bhi[cdx][kk2 + lc];
                bhf[jn][1] = Bhi[cdx][kk2 + lc + 4];
                blf[jn][0] = Blo[cdx][kk2 + lc];
                blf[jn][1] = Blo[cdx][kk2 + lc + 4];
            }
            #pragma unroll
            for (int im = 0; im < 4; im++) {
                int r = wm + im * 16 + lr;
                uint32_t ah[4], al[4];
                ah[0] = Ahi[r][kk2 + lc];
                ah[1] = Ahi[r + 8][kk2 + lc];
                ah[2] = Ahi[r][kk2 + lc + 4];
                ah[3] = Ahi[r + 8][kk2 + lc + 4];
                al[0] = Alo[r][kk2 + lc];
                al[1] = Alo[r + 8][kk2 + lc];
                al[2] = Alo[r][kk2 + lc + 4];
                al[3] = Alo[r + 8][kk2 + lc + 4];
                #pragma unroll
                for (int jn = 0; jn < 4; jn++) {
                    mma_bf16(acc[im][jn], ah, blf[jn]);
                    mma_bf16(acc[im][jn], al, bhf[jn]);
                    mma_bf16(acc[im][jn], ah, bhf[jn]);
                }
            }
        }
        __syncthreads();
    }

    #pragma unroll
    for (int im = 0; im < 4; im++) {
        #pragma unroll
        for (int jn = 0; jn < 4; jn++) {
            int gm = bm + wm + im * 16 + lr;
            int gc = bn + wn + jn * 8 + 2 * lc;
            if (gc < N) {
                float b0 = bias ? bias[gc] : 0.f;
                float b1 = bias ? bias[gc + 1] : 0.f;
                float* p0 = C + (long long)gm * ldc + gc;
                p0[0] = acc[im][jn][0] + b0;
                p0[1] = acc[im][jn][1] + b1;
                float* p1 = C + (long long)(gm + 8) * ldc + gc;
                p1[0] = acc[im][jn][2] + b0;
                p1[1] = acc[im][jn][3] + b1;
            }
        }
    }
}

// ---------------- tensor-core flash attention (non-causal), split-bf16 ----------------
__global__ __launch_bounds__(256)
void attn_tc_kernel(const float* __restrict__ qkv, float* __restrict__ o)
{
    __shared__ uint32_t Khi[64][36];
    __shared__ uint32_t Klo[64][36];
    __shared__ __nv_bfloat16 Vthi[64][72];
    __shared__ __nv_bfloat16 Vtlo[64][72];

    int bh = blockIdx.y;
    int b = bh >> 4, h = bh & 15;
    int tid = threadIdx.x;
    int wid = tid >> 5, lane = tid & 31;
    int lr = lane >> 2, lc = lane & 3;
    int qrow0 = blockIdx.x * 128 + wid * 16;

    uint32_t qhi[4][4], qlo[4][4];
    {
        const float* qp = qkv + (long long)(b * L_) * 3072 + h * 64;
        #pragma unroll
        for (int kc = 0; kc < 4; kc++) {
            #pragma unroll
            for (int half = 0; half < 2; half++) {
                int col = kc * 16 + 2 * lc + half * 8;
                float2 v0 = *(const float2*)(qp + (long long)(qrow0 + lr) * 3072 + col);
                float2 v1 = *(const float2*)(qp + (long long)(qrow0 + lr + 8) * 3072 + col);
                __nv_bfloat16 h0,l0,h1,l1;
                split_bf16(v0.x * 0.125f, h0, l0); split_bf16(v0.y * 0.125f, h1, l1);
                qhi[kc][half * 2]     = pack2(h0, h1);
                qlo[kc][half * 2]     = pack2(l0, l1);
                split_bf16(v1.x * 0.125f, h0, l0); split_bf16(v1.y * 0.125f, h1, l1);
                qhi[kc][half * 2 + 1] = pack2(h0, h1);
                qlo[kc][half * 2 + 1] = pack2(l0, l1);
            }
        }
    }

    float o_acc[8][4];
    #pragma unroll
    for (int j = 0; j < 8; j++)
        #pragma unroll
        for (int r = 0; r < 4; r++) o_acc[j][r] = 0.f;
    float mrow0 = -1e30f, mrow1 = -1e30f;
    float lrow0 = 0.f, lrow1 = 0.f;

    for (int kt = 0; kt < L_ / 64; kt++) {
        const float* kb = qkv + (long long)(b * L_ + kt * 64) * 3072 + 1024 + h * 64;
        const float* vb = kb + 1024;
        #pragma unroll
        for (int i = 0; i < 4; i++) {
            int idx = tid + i * 256;
            int r = idx >> 4, c4 = (idx & 15) << 2;
            float4 kv = *(const float4*)(kb + (long long)r * 3072 + c4);
            __nv_bfloat16 h0,l0,h1,l1,h2,l2,h3,l3;
            split_bf16(kv.x, h0, l0); split_bf16(kv.y, h1, l1);
            split_bf16(kv.z, h2, l2); split_bf16(kv.w, h3, l3);
            int c2 = c4 >> 1;
            Khi[r][c2]     = pack2(h0, h1);
            Khi[r][c2 + 1] = pack2(h2, h3);
            Klo[r][c2]     = pack2(l0, l1);
            Klo[r][c2 + 1] = pack2(l2, l3);
            float4 vv = *(const float4*)(vb + (long long)r * 3072 + c4);
            __nv_bfloat16 vh, vl;
            split_bf16(vv.x, vh, vl); Vthi[c4 + 0][r] = vh; Vtlo[c4 + 0][r] = vl;
            split_bf16(vv.y, vh, vl); Vthi[c4 + 1][r] = vh; Vtlo[c4 + 1][r] = vl;
            split_bf16(vv.z, vh, vl); Vthi[c4 + 2][r] = vh; Vtlo[c4 + 2][r] = vl;
            split_bf16(vv.w, vh, vl); Vthi[c4 + 3][r] = vh; Vtlo[c4 + 3][r] = vl;
        }
        __syncthreads();

        float s[8][4];
        #pragma unroll
        for (int j = 0; j < 8; j++)
            #pragma unroll
            for (int r = 0; r < 4; r++) s[j][r] = 0.f;
        #pragma unroll
        for (int kc = 0; kc < 4; kc++) {
            #pragma unroll
            for (int jn = 0; jn < 8; jn++) {
                int n = jn * 8 + lr;
                uint32_t bhf[2], blf[2];
                bhf[0] = Khi[n][kc * 8 + lc];
                bhf[1] = Khi[n][kc * 8 + lc + 4];
                blf[0] = Klo[n][kc * 8 + lc];
                blf[1] = Klo[n][kc * 8 + lc + 4];
                mma_bf16(s[jn], qhi[kc], blf);
                mma_bf16(s[jn], qlo[kc], bhf);
                mma_bf16(s[jn], qhi[kc], bhf);
            }
        }

        float t0 = -1e30f, t1 = -1e30f;
        #pragma unroll
        for (int jn = 0; jn < 8; jn++) {
            t0 = fmaxf(t0, fmaxf(s[jn][0], s[jn][1]));
            t1 = fmaxf(t1, fmaxf(s[jn][2], s[jn][3]));
        }
        t0 = fmaxf(t0, __shfl_xor_sync(0xffffffffu, t0, 1));
        t0 = fmaxf(t0, __shfl_xor_sync(0xffffffffu, t0, 2));
        t1 = fmaxf(t1, __shfl_xor_sync(0xffffffffu, t1, 1));
        t1 = fmaxf(t1, __shfl_xor_sync(0xffffffffu, t1, 2));
        float m0n = fmaxf(mrow0, t0), m1n = fmaxf(mrow1, t1);
        float sc0 = __expf(mrow0 - m0n), sc1 = __expf(mrow1 - m1n);
        mrow0 = m0n; mrow1 = m1n;
        lrow0 *= sc0; lrow1 *= sc1;
        #pragma unroll
        for (int j = 0; j < 8; j++) {
            o_acc[j][0] *= sc0; o_acc[j][1] *= sc0;
            o_acc[j][2] *= sc1; o_acc[j][3] *= sc1;
        }

        uint32_t phi[4][4], plo[4][4];
        #pragma unroll
        for (int jn = 0; jn < 8; jn++) {
            float p0 = __expf(s[jn][0] - m0n);
            float p1 = __expf(s[jn][1] - m0n);
            float p2 = __expf(s[jn][2] - m1n);
            float p3 = __expf(s[jn][3] - m1n);
            lrow0 += p0 + p1;
            lrow1 += p2 + p3;
            __nv_bfloat16 h0,l0,h1,l1,h2,l2,h3,l3;
            split_bf16(p0, h0, l0); split_bf16(p1, h1, l1);
            split_bf16(p2, h2, l2); split_bf16(p3, h3, l3);
            int kc = jn >> 1;
            int off = (jn & 1) * 2;
            phi[kc][off]     = pack2(h0, h1);
            phi[kc][off + 1] = pack2(h2, h3);
            plo[kc][off]     = pack2(l0, l1);
            plo[kc][off + 1] = pack2(l2, l3);
        }

        #pragma unroll
        for (int kc = 0; kc < 4; kc++) {
            #pragma unroll
            for (int jd = 0; jd < 8; jd++) {
                int d = jd * 8 + lr;
                uint32_t bhf[2], blf[2];
                bhf[0] = *(const uint32_t*)&Vthi[d][2 * (kc * 8 + lc)];
                bhf[1] = *(const uint32_t*)&Vthi[d][2 * (kc * 8 + lc + 4)];
                blf[0] = *(const uint32_t*)&Vtlo[d][2 * (kc * 8 + lc)];
                blf[1] = *(const uint32_t*)&Vtlo[d][2 * (kc * 8 + lc + 4)];
                mma_bf16(o_acc[jd], phi[kc], blf);
                mma_bf16(o_acc[jd], plo[kc], bhf);
                mma_bf16(o_acc[jd], phi[kc], bhf);
            }
        }
        __syncthreads();
    }

    lrow0 += __shfl_xor_sync(0xffffffffu, lrow0, 1);
    lrow0 += __shfl_xor_sync(0xffffffffu, lrow0, 2);
    lrow1 += __shfl_xor_sync(0xffffffffu, lrow1, 1);
    lrow1 += __shfl_xor_sync(0xffffffffu, lrow1, 2);
    float inv0 = 1.f / lrow0, inv1 = 1.f / lrow1;
    #pragma unroll
    for (int jd = 0; jd < 8; jd++) {
        int col = h * 64 + jd * 8 + 2 * lc;
        float* p0 = o + (long long)(b * L_ + qrow0 + lr) * DM + col;
        p0[0] = o_acc[jd][0] * inv0;
        p0[1] = o_acc[jd][1] * inv0;
        float* p1 = o + (long long)(b * L_ + qrow0 + lr + 8) * DM + col;
        p1[0] = o_acc[jd][2] * inv1;
        p1[1] = o_acc[jd][3] * inv1;
    }
}

// ---------------- tensor-core SSD chunk-states ----------------
__global__ __launch_bounds__(256)
void states_tc_kernel(const float* __restrict__ xbc, const float* __restrict__ xdt,
                      const float* __restrict__ Acs, float* __restrict__ states)
{
    extern __shared__ uint32_t dynst[];
    uint32_t* Ah = dynst;
    uint32_t* Al = Ah + 128 * 36;
    uint32_t* Bh = Al + 128 * 36;
    uint32_t* Bl = Bh + 64 * 36;
    float* dec_sh = (float*)(Bl + 64 * 36);
    __nv_bfloat16* Ah_e = (__nv_bfloat16*)Ah;
    __nv_bfloat16* Al_e = (__nv_bfloat16*)Al;
    __nv_bfloat16* Bh_e = (__nv_bfloat16*)Bh;
    __nv_bfloat16* Bl_e = (__nv_bfloat16*)Bl;

    int blk = blockIdx.x;
    int ck = blk & 7;
    int bh = blk >> 3;
    int h = bh & 31, b = bh >> 5;
    int tid = threadIdx.x;
    int wid = tid >> 5, lane = tid & 31;
    int lr = lane >> 2, lc = lane & 3;
    long long rowbase = (long long)(b * L_ + ck * 256);

    dec_sh[tid] = Acs[(long long)bh * L_ + ck * 256 + tid];
    __syncthreads();
    float aLast = dec_sh[255];
    float mya = dec_sh[tid];
    __syncthreads();
    dec_sh[tid] = __expf(aLast - mya);

    float acc[8][4];
    #pragma unroll
    for (int j = 0; j < 8; j++)
        #pragma unroll
        for (int r = 0; r < 4; r++) acc[j][r] = 0.f;

    for (int kt = 0; kt < 4; kt++) {
        int l0 = kt * 64;
        #pragma unroll
        for (int i = 0; i < 32; i++) {
            int idx = tid + i * 256;
            int n = idx & 127;
            int c = idx >> 7;
            float v = xbc[(rowbase + l0 + c) * CONVD + DI + n] * dec_sh[l0 + c];
            __nv_bfloat16 hi, lo; split_bf16(v, hi, lo);
            Ah_e[n * 72 + c] = hi;
            Al_e[n * 72 + c] = lo;
        }
        #pragma unroll
        for (int i = 0; i < 16; i++) {
            int idx = tid + i * 256;
            int p = idx & 63;
            int c = idx >> 6;
            float v = xdt[(rowbase + l0 + c) * DI + h * 64 + p];
            __nv_bfloat16 hi, lo; split_bf16(v, hi, lo);
            Bh_e[p * 72 + c] = hi;
            Bl_e[p * 72 + c] = lo;
        }
        __syncthreads();
        #pragma unroll
        for (int kk2 = 0; kk2 < 32; kk2 += 8) {
            int r = wid * 16 + lr;
            uint32_t ah[4], al[4];
            ah[0] = Ah[r * 36 + kk2 + lc];
            ah[1] = Ah[(r + 8) * 36 + kk2 + lc];
            ah[2] = Ah[r * 36 + kk2 + lc + 4];
            ah[3] = Ah[(r + 8) * 36 + kk2 + lc + 4];
            al[0] = Al[r * 36 + kk2 + lc];
            al[1] = Al[(r + 8) * 36 + kk2 + lc];
            al[2] = Al[r * 36 + kk2 + lc + 4];
            al[3] = Al[(r + 8) * 36 + kk2 + lc + 4];
            #pragma unroll
            for (int jn = 0; jn < 8; jn++) {
                int n = jn * 8 + lr;
                uint32_t bhf[2], blf[2];
                bhf[0] = Bh[n * 36 + kk2 + lc];
                bhf[1] = Bh[n * 36 + kk2 + lc + 4];
                blf[0] = Bl[n * 36 + kk2 + lc];
                blf[1] = Bl[n * 36 + kk2 + lc + 4];
                mma_bf16(acc[jn], ah, blf);
                mma_bf16(acc[jn], al, bhf);
                mma_bf16(acc[jn], ah, bhf);
            }
        }
        __syncthreads();
    }

    float* base = states + (long long)(bh * NC + ck) * 8192;
    int n0 = wid * 16 + lr;
    #pragma unroll
    for (int jn = 0; jn < 8; jn++) {
        int p = jn * 8 + 2 * lc;
        float* p0 = base + n0 * 64 + p;
        p0[0] = acc[jn][0];
        p0[1] = acc[jn][1];
        float* p1 = base + (n0 + 8) * 64 + p;
        p1[0] = acc[jn][2];
        p1[1] = acc[jn][3];
    }
}

// ---------------- tensor-core SSD output ----------------
__global__ __launch_bounds__(256)
void y_tc_kernel(const float* __restrict__ xbc, const float* __restrict__ xdt,
                 const float* __restrict__ Acs, const float* __restrict__ CB,
                 const float* __restrict__ Sprev, const float* __restrict__ Dv,
                 float* __restrict__ Y)
{
    extern __shared__ uint32_t dyny[];
    uint32_t* Ah = dyny;
    uint32_t* Al = Ah + 128 * 36;
    uint32_t* Bh = Al + 128 * 36;
    uint32_t* Bl = Bh + 64 * 36;
    float* acs_sh = (float*)(Bl + 64 * 36);
    float* eA_sh  = acs_sh + 256;
    __nv_bfloat16* Ah_e = (__nv_bfloat16*)Ah;
    __nv_bfloat16* Al_e = (__nv_bfloat16*)Al;
    __nv_bfloat16* Bh_e = (__nv_bfloat16*)Bh;
    __nv_bfloat16* Bl_e = (__nv_bfloat16*)Bl;

    int blk = blockIdx.x;
    int lh = blk & 1;
    int ck = (blk >> 1) & 7;
    int bh = blk >> 4;
    int h = bh & 31, b = bh >> 5;
    int tid = threadIdx.x;
    int wid = tid >> 5, lane = tid & 31;
    int lr = lane >> 2, lc = lane & 3;
    long long rowbase = (long long)(b * L_ + ck * 256);

    acs_sh[tid] = Acs[(long long)bh * L_ + ck * 256 + tid];
    __syncthreads();
    if (tid < 128) eA_sh[tid] = __expf(acs_sh[lh * 128 + tid]);

    float acc[8][4];
    #pragma unroll
    for (int j = 0; j < 8; j++)
        #pragma unroll
        for (int r = 0; r < 4; r++) acc[j][r] = 0.f;

    const float* cbp = CB + (long long)(b * NC + ck) * (CH * CH);
    int ndiag = (lh == 0) ? 2 : 4;

    for (int kt = 0; kt < ndiag + 2; kt++) {
        if (kt < ndiag) {
            int s0 = kt * 64;
            #pragma unroll
            for (int i = 0; i < 32; i++) {
                int idx = tid + i * 256;
                int l = idx & 127;
                int s = idx >> 7;
                int gl = lh * 128 + l;
                int gs = s0 + s;
                float v = 0.f;
                if (gs <= gl) v = cbp[gs * 256 + gl] * __expf(acs_sh[gl] - acs_sh[gs]);
                __nv_bfloat16 hi, lo; split_bf16(v, hi, lo);
                Ah_e[l * 72 + s] = hi;
                Al_e[l * 72 + s] = lo;
            }
            #pragma unroll
            for (int i = 0; i < 16; i++) {
                int idx = tid + i * 256;
                int p = idx & 63;
                int s = idx >> 6;
                float v = xdt[(rowbase + s0 + s) * DI + h * 64 + p];
                __nv_bfloat16 hi, lo; split_bf16(v, hi, lo);
                Bh_e[p * 72 + s] = hi;
                Bl_e[p * 72 + s] = lo;
            }
        } else {
            int n0 = (kt - ndiag) * 64;
            #pragma unroll
            for (int i = 0; i < 32; i++) {
                int idx = tid + i * 256;
                int c = idx & 63;
                int l = idx >> 6;
                float v = xbc[(rowbase + lh * 128 + l) * CONVD + DI + NST + n0 + c] * eA_sh[l];
                __nv_bfloat16 hi, lo; split_bf16(v, hi, lo);
                Ah_e[l * 72 + c] = hi;
                Al_e[l * 72 + c] = lo;
            }
            #pragma unroll
            for (int i = 0; i < 16; i++) {
                int idx = tid + i * 256;
                int p = idx & 63;
                int c = idx >> 6;
                float v = Sprev[(long long)(bh * NC + ck) * 8192 + (n0 + c) * 64 + p];
                __nv_bfloat16 hi, lo; split_bf16(v, hi, lo);
                Bh_e[p * 72 + c] = hi;
                Bl_e[p * 72 + c] = lo;
            }
        }
        __syncthreads();
        #pragma unroll
        for (int kk2 = 0; kk2 < 32; kk2 += 8) {
            int r = wid * 16 + lr;
            uint32_t ah[4], al[4];
            ah[0] = Ah[r * 36 + kk2 + lc];
            ah[1] = Ah[(r + 8) * 36 + kk2 + lc];
            ah[2] = Ah[r * 36 + kk2 + lc + 4];
            ah[3] = Ah[(r + 8) * 36 + kk2 + lc + 4];
            al[0] = Al[r * 36 + kk2 + lc];
            al[1] = Al[(r + 8) * 36 + kk2 + lc];
            al[2] = Al[r * 36 + kk2 + lc + 4];
            al[3] = Al[(r + 8) * 36 + kk2 + lc + 4];
            #pragma unroll
            for (int jn = 0; jn < 8; jn++) {
                int n = jn * 8 + lr;
                uint32_t bhf[2], blf[2];
                bhf[0] = Bh[n * 36 + kk2 + lc];
                bhf[1] = Bh[n * 36 + kk2 + lc + 4];
                blf[0] = Bl[n * 36 + kk2 + lc];
                blf[1] = Bl[n * 36 + kk2 + lc + 4];
                mma_bf16(acc[jn], ah, blf);
                mma_bf16(acc[jn], al, bhf);
                mma_bf16(acc[jn], ah, bhf);
            }
        }
        __syncthreads();
    }

    float Dh = Dv[h];
    int r0 = wid * 16 + lr;
    #pragma unroll
    for (int jn = 0; jn < 8; jn++) {
        int col = jn * 8 + 2 * lc;
        long long grow0 = rowbase + lh * 128 + r0;
        const float* xs0 = xbc + grow0 * CONVD + h * 64 + col;
        float* yp0 = Y + grow0 * DI + h * 64 + col;
        yp0[0] = acc[jn][0] + Dh * xs0[0];
        yp0[1] = acc[jn][1] + Dh * xs0[1];
        long long grow1 = grow0 + 8;
        const float* xs1 = xbc + grow1 * CONVD + h * 64 + col;
        float* yp1 = Y + grow1 * DI + h * 64 + col;
        yp1[0] = acc[jn][2] + Dh * xs1[0];
        yp1[1] = acc[jn][3] + Dh * xs1[1];
    }
}

// ---------------- rmsnorm ----------------
__global__ void rmsnorm_kernel(const float* __restrict__ a, const float* __restrict__ b,
                               float alpha, const float* __restrict__ w,
                               float* __restrict__ out, int D)
{
    long long row = blockIdx.x;
    const float* ap = a + row * D;
    const float* bp = b ? (b + row * D) : nullptr;
    int per = D >> 8;
    float v[8];
    float ss = 0.f;
    for (int j = 0; j < per; j++) {
        int i = threadIdx.x + j * 256;
        float x = ap[i] + (bp ? alpha * bp[i] : 0.f);
        v[j] = x;
        ss += x * x;
    }
    __shared__ float red[256];
    red[threadIdx.x] = ss;
    __syncthreads();
    for (int off = 128; off; off >>= 1) {
        if (threadIdx.x < off) red[threadIdx.x] += red[threadIdx.x + off];
        __syncthreads();
    }
    float scale = rsqrtf(red[0] / D + EPSN);
    float* op = out + row * D;
    for (int j = 0; j < per; j++) {
        int i = threadIdx.x + j * 256;
        op[i] = v[j] * scale * w[i];
    }
}

// ---------------- gated rmsnorm ----------------
__global__ void gated_rmsnorm_kernel(const float* __restrict__ y, const float* __restrict__ z,
                                     int ldz, const float* __restrict__ w,
                                     float* __restrict__ out)
{
    long long row = blockIdx.x;
    const float* yp = y + row * DI;
    const float* zp = z + row * (long long)ldz;
    float v[8];
    float ss = 0.f;
    #pragma unroll
    for (int j = 0; j < 8; j++) {
        int i = threadIdx.x + j * 256;
        float x = yp[i] * silu_f(zp[i]);
        v[j] = x;
        ss += x * x;
    }
    __shared__ float red[256];
    red[threadIdx.x] = ss;
    __syncthreads();
    for (int off = 128; off; off >>= 1) {
        if (threadIdx.x < off) red[threadIdx.x] += red[threadIdx.x + off];
        __syncthreads();
    }
    float scale = rsqrtf(red[0] / DI + EPSN);
    float* op = out + row * DI;
    #pragma unroll
    for (int j = 0; j < 8; j++) {
        int i = threadIdx.x + j * 256;
        op[i] = v[j] * scale * w[i];
    }
}

// ---------------- depthwise causal conv (k=4) + bias + silu ----------------
__global__ void conv_kernel(const float* __restrict__ zx, const float* __restrict__ cw,
                            const float* __restrict__ cb, float* __restrict__ xbc)
{
    int idx = blockIdx.x * 256 + threadIdx.x;
    if (idx >= B_ * L_ * CONVD) return;
    int c = idx % CONVD;
    int t = (idx / CONVD) % L_;
    int b = idx / (CONVD * L_);
    float s = cb[c];
    #pragma unroll
    for (int k = 0; k < 4; k++) {
        int tt = t - 3 + k;
        if (tt >= 0)
            s += zx[((long long)(b * L_ + tt) * DINP) + DI + c] * cw[c * 4 + k];
    }
    xbc[idx] = silu_f(s);
}

// ---------------- dt (softplus) and xdt = xs*dt ----------------
__global__ void dtxdt_kernel(const float* __restrict__ zx, const float* __restrict__ xbc,
                             const float* __restrict__ dt_bias,
                             float* __restrict__ dtb, float* __restrict__ xdt)
{
    int idx = blockIdx.x * 256 + threadIdx.x;
    if (idx >= ROWS * DI) return;
    int p = idx & 63;
    int h = (idx >> 6) & 31;
    long long row = idx >> 11;
    float raw = zx[row * DINP + DI + CONVD + h] + dt_bias[h];
    float d = softplus_f(raw);
    xdt[idx] = xbc[row * CONVD + h * 64 + p] * d;
    if (p == 0) dtb[row * HS + h] = d;
}

// ---------------- per-chunk inclusive cumsum ----------------
__global__ void cumsum_kernel(const float* __restrict__ dtb, const float* __restrict__ A_log,
                              float* __restrict__ Acs)
{
    __shared__ float s[256];
    int blk = blockIdx.x;
    int ck = blk & 7;
    int bh = blk >> 3;
    int h = bh & 31;
    int b = bh >> 5;
    int l = threadIdx.x;
    int gl = ck * 256 + l;
    float a = -__expf(A_log[h]) * dtb[((long long)(b * L_ + gl)) * HS + h];
    s[l] = a;
    __syncthreads();
    for (int off = 1; off < 256; off <<= 1) {
        float t = (l >= off) ? s[l - off] : 0.f;
        __syncthreads();
        s[l] += t;
        __syncthreads();
    }
    Acs[(long long)bh * L_ + gl] = s[l];
}

// ---------------- inter-chunk scan ----------------
__global__ void scan_kernel(const float* __restrict__ states, const float* __restrict__ Acs,
                            float* __restrict__ Sprev)
{
    int bh = blockIdx.x;
    int tid = threadIdx.x;
    float S[32];
    #pragma unroll
    for (int j = 0; j < 32; j++) S[j] = 0.f;
    for (int c = 0; c < NC; c++) {
        float dc = __expf(Acs[(long long)bh * L_ + c * 256 + 255]);
        const float* sp = states + (long long)(bh * NC + c) * 8192;
        float* pp = Sprev + (long long)(bh * NC + c) * 8192;
        #pragma unroll
        for (int j = 0; j < 32; j++) {
            int idx = tid + j * 256;
            pp[idx] = S[j];
            S[j] = S[j] * dc + sp[idx];
        }
    }
}

// ---------------- host launcher ----------------
#define SSD_SMEM 57344

extern "C" void kernel_launch(void* const* d_in, const int* in_sizes, int n_in,
                              void* d_out, int out_size)
{
    const float* x_in       = (const float*)d_in[0];
    const float* attn_norm  = (const float*)d_in[1];
    const float* Wqkv       = (const float*)d_in[2];
    const float* Wqkv_b     = (const float*)d_in[3];
    const float* attn_out_w = (const float*)d_in[4];
    const float* attn_out_b = (const float*)d_in[5];
    const float* normf_w    = (const float*)d_in[6];
    const float* m_in_w     = (const float*)d_in[7];
    const float* m_conv_w   = (const float*)d_in[8];
    const float* m_conv_b   = (const float*)d_in[9];
    const float* m_dt_bias  = (const float*)d_in[10];
    const float* m_A_log    = (const float*)d_in[11];
    const float* m_D        = (const float*)d_in[12];
    const float* m_norm_w   = (const float*)d_in[13];
    const float* m_out_w    = (const float*)d_in[14];
    const float* fc1_w      = (const float*)d_in[15];
    const float* fc2_w      = (const float*)d_in[16];
    const float* final_norm = (const float*)d_in[17];
    float* out = (float*)d_out;

    float* scr = nullptr;
    cudaGetSymbolAddress((void**)&scr, g_scratch);

    cudaFuncSetAttribute(states_tc_kernel, cudaFuncAttributeMaxDynamicSharedMemorySize, SSD_SMEM);
    cudaFuncSetAttribute(y_tc_kernel, cudaFuncAttributeMaxDynamicSharedMemorySize, SSD_SMEM);

    float* bBIG = scr + OFF_BIG;
    float* bH   = scr + OFF_H;
    float* bO   = scr + OFF_O;
    float* bX   = scr + OFF_X;
    float* bXBC = scr + OFF_XBC;
    float* bDT  = scr + OFF_DT;
    float* bXDT = scr + OFF_XDT;
    float* bACS = scr + OFF_ACS;
    float* bCB  = scr + OFF_CB;
    float* bSTA = scr + OFF_STA;
    float* bSPR = scr + OFF_SPR;
    float* bY   = scr + OFF_Y;

    // ---- attention block ----
    rmsnorm_kernel<<<ROWS, 256>>>(x_in, nullptr, 0.f, attn_norm, bH, DM);
    gemm_tc<false><<<dim3(3072/128, ROWS/128, 1), 256>>>(bH, Wqkv, Wqkv_b, bBIG,
        ROWS, 3072, DM, DM, DM, 3072, 0, 0, 0);
    attn_tc_kernel<<<dim3(L_/128, B_*NH), 256>>>(bBIG, bO);
    gemm_tc<false><<<dim3(DM/128, ROWS/128, 1), 256>>>(bO, attn_out_w, attn_out_b, bH,
        ROWS, DM, DM, DM, DM, DM, 0, 0, 0);
    rmsnorm_kernel<<<ROWS, 256>>>(bH, x_in, 1.f, normf_w, bX, DM);

    // ---- mamba layers ----
    for (int i = 0; i < 4; i++) {
        const float* in_w   = m_in_w   + (long long)i * DINP * DM;
        const float* conv_w = m_conv_w + (long long)i * CONVD * 4;
        const float* conv_b = m_conv_b + (long long)i * CONVD;
        const float* dtbias = m_dt_bias+ (long long)i * HS;
        const float* Alog   = m_A_log  + (long long)i * HS;
        const float* Dv     = m_D      + (long long)i * HS;
        const float* nw     = m_norm_w + (long long)i * DI;
        const float* ow     = m_out_w  + (long long)i * DM * DI;

        gemm_tc<false><<<dim3((DINP+127)/128, ROWS/128, 1), 256>>>(bX, in_w, nullptr, bBIG,
            ROWS, DINP, DM, DM, DM, DINP, 0, 0, 0);
        conv_kernel<<<(ROWS*CONVD)/256, 256>>>(bBIG, conv_w, conv_b, bXBC);
        dtxdt_kernel<<<(ROWS*DI)/256, 256>>>(bBIG, bXBC, dtbias, bDT, bXDT);
        cumsum_kernel<<<B_*HS*NC, 256>>>(bDT, Alog, bACS);
        gemm_tc<false><<<dim3(2, 2, B_*NC), 256>>>(
            bXBC + DI, bXBC + DI + NST, nullptr, bCB,
            CH, CH, NST, CONVD, CONVD, CH,
            (long long)CH * CONVD, (long long)CH * CONVD, (long long)CH * CH);
        states_tc_kernel<<<B_*HS*NC, 256, SSD_SMEM>>>(bXBC, bXDT, bACS, bSTA);
        scan_kernel<<<B_*HS, 256>>>(bSTA, bACS, bSPR);
        y_tc_kernel<<<B_*HS*NC*2, 256, SSD_SMEM>>>(bXBC, bXDT, bACS, bCB, bSPR, Dv, bY);
        gated_rmsnorm_kernel<<<ROWS, 256>>>(bY, bBIG, DINP, nw, bY);
        gemm_tc<false><<<dim3(DM/128, ROWS/128, 1), 256>>>(bY, ow, nullptr, bX,
            ROWS, DM, DI, DI, DI, DM, 0, 0, 0);
    }

    // ---- MLP + final norm (SwiGLU fused into fc2 A-staging) ----
    gemm_tc<false><<<dim3((2*DFF)/128, ROWS/128, 1), 256>>>(bX, fc1_w, nullptr, bBIG,
        ROWS, 2*DFF, DM, DM, DM, 2*DFF, 0, 0, 0);
    gemm_tc<true><<<dim3(DM/128, ROWS/128, 1), 256>>>(bBIG, fc2_w, nullptr, bH,
        ROWS, DM, DFF, 2*DFF, DFF, DM, 0, 0, 0);
    rmsnorm_kernel<<<ROWS, 256>>>(bH, bX, ALPHA, final_norm, out, DM);
}

// round 11
// speedup vs baseline: 1.3462x; 1.0552x over previous
#include <cuda_runtime.h>
#include <cuda_bf16.h>
#include <math.h>
#include <stdint.h>

// ---------------- constants ----------------
#define B_   2
#define L_   2048
#define DM   1024          // D_MODEL
#define NH   16            // NHEAD
#define HD   64            // HD_ATT
#define DI   2048          // D_INNER
#define HS   32            // H_SSM
#define P_   64            // HEADDIM
#define NST  128           // D_STATE
#define CONVD 2304         // CONV_DIM
#define DINP 4384          // D_IN_PROJ
#define CH   256           // CHUNK
#define NC   8             // L/CHUNK
#define DFF  2048
#define ALPHA 1.68f
#define EPSN 1e-5f

#define ROWS (B_*L_)       // 4096

// ---------------- scratch ----------------
static const long long SZ_BIG  = (long long)ROWS*DINP;
static const long long SZ_HB   = (long long)ROWS*DM;
static const long long SZ_XBC  = (long long)ROWS*CONVD;
static const long long SZ_DT   = (long long)ROWS*HS;
static const long long SZ_XDT  = (long long)ROWS*DI;
static const long long SZ_ACS  = (long long)B_*HS*L_;
static const long long SZ_CB   = (long long)B_*NC*CH*CH;
static const long long SZ_ST   = (long long)B_*HS*NC*NST*P_;
static const long long SZ_Y    = (long long)ROWS*DI;

static const long long OFF_BIG = 0;
static const long long OFF_H   = OFF_BIG + SZ_BIG;
static const long long OFF_O   = OFF_H   + SZ_HB;
static const long long OFF_X   = OFF_O   + SZ_HB;
static const long long OFF_XBC = OFF_X   + SZ_HB;
static const long long OFF_DT  = OFF_XBC + SZ_XBC;
static const long long OFF_XDT = OFF_DT  + SZ_DT;
static const long long OFF_ACS = OFF_XDT + SZ_XDT;
static const long long OFF_CB  = OFF_ACS + SZ_ACS;
static const long long OFF_STA = OFF_CB  + SZ_CB;
static const long long OFF_SPR = OFF_STA + SZ_ST;
static const long long OFF_Y   = OFF_SPR + SZ_ST;
static const long long OFF_FF  = OFF_Y   + SZ_Y;
static const long long TOTALF  = OFF_FF  + SZ_Y;

__device__ float g_scratch[74842112]; // == TOTALF floats (~300 MB)

// ---------------- helpers ----------------
__device__ __forceinline__ float silu_f(float x) {
    return x / (1.f + __expf(-x));
}
__device__ __forceinline__ float softplus_f(float x) {
    return (x > 20.f) ? x : log1pf(__expf(x));
}
__device__ __forceinline__ void split_bf16(float x, __nv_bfloat16& hi, __nv_bfloat16& lo) {
    hi = __float2bfloat16_rn(x);
    lo = __float2bfloat16_rn(x - __bfloat162float(hi));
}
__device__ __forceinline__ uint32_t pack2(__nv_bfloat16 a, __nv_bfloat16 b) {
    __nv_bfloat162 h;
    h.x = a; h.y = b;
    return *(uint32_t*)&h;
}
__device__ __forceinline__ void mma_bf16(float* c, const uint32_t* a, const uint32_t* b) {
    asm volatile(
        "mma.sync.aligned.m16n8k16.row.col.f32.bf16.bf16.f32 "
        "{%0,%1,%2,%3}, {%4,%5,%6,%7}, {%8,%9}, {%0,%1,%2,%3};"
        : "+f"(c[0]), "+f"(c[1]), "+f"(c[2]), "+f"(c[3])
        : "r"(a[0]), "r"(a[1]), "r"(a[2]), "r"(a[3]), "r"(b[0]), "r"(b[1]));
}

// ---------------- bf16x2 split tensor-core NT GEMM, register-prefetch pipelined ----------------
// Measured-best configuration (R6): static 40KB SMEM, K-tile 32, register LDG prefetch.
#define SSTR 20
__global__ __launch_bounds__(256, 2)
void gemm_tc(const float* __restrict__ A, const float* __restrict__ W,
             const float* __restrict__ bias, float* __restrict__ C,
             int M, int N, int K, int lda, int ldw, int ldc,
             long long sA, long long sW, long long sC)
{
    A += (long long)blockIdx.z * sA;
    W += (long long)blockIdx.z * sW;
    C += (long long)blockIdx.z * sC;

    __shared__ uint32_t Ahi[128][SSTR];
    __shared__ uint32_t Alo[128][SSTR];
    __shared__ uint32_t Bhi[128][SSTR];
    __shared__ uint32_t Blo[128][SSTR];

    int bm = blockIdx.y * 128, bn = blockIdx.x * 128;
    int tid = threadIdx.x;
    int wid = tid >> 5, lane = tid & 31;
    int wm = (wid >> 2) * 64;
    int wn = (wid & 3) * 32;
    int lr = lane >> 2;
    int lc = lane & 3;

    int sr = tid >> 3;
    int sc4 = (tid & 7) << 2;
    int sc2 = sc4 >> 1;

    float acc[4][4][4];
    #pragma unroll
    for (int i = 0; i < 4; i++)
        #pragma unroll
        for (int j = 0; j < 4; j++)
            #pragma unroll
            for (int r = 0; r < 4; r++) acc[i][j][r] = 0.f;

    float4 pa[4], pw[4];
    #pragma unroll
    for (int i = 0; i < 4; i++) {
        int r = sr + i * 32;
        pa[i] = *(const float4*)(A + (long long)(bm + r) * lda + sc4);
        if (bn + r < N) pw[i] = *(const float4*)(W + (long long)(bn + r) * ldw + sc4);
        else            pw[i] = make_float4(0.f, 0.f, 0.f, 0.f);
    }

    for (int k0 = 0; k0 < K; k0 += 32) {
        #pragma unroll
        for (int i = 0; i < 4; i++) {
            int r = sr + i * 32;
            __nv_bfloat16 h0,l0,h1,l1,h2,l2,h3,l3;
            split_bf16(pa[i].x, h0, l0); split_bf16(pa[i].y, h1, l1);
            split_bf16(pa[i].z, h2, l2); split_bf16(pa[i].w, h3, l3);
            Ahi[r][sc2]     = pack2(h0, h1);
            Ahi[r][sc2 + 1] = pack2(h2, h3);
            Alo[r][sc2]     = pack2(l0, l1);
            Alo[r][sc2 + 1] = pack2(l2, l3);
            split_bf16(pw[i].x, h0, l0); split_bf16(pw[i].y, h1, l1);
            split_bf16(pw[i].z, h2, l2); split_bf16(pw[i].w, h3, l3);
            Bhi[r][sc2]     = pack2(h0, h1);
            Bhi[r][sc2 + 1] = pack2(h2, h3);
            Blo[r][sc2]     = pack2(l0, l1);
            Blo[r][sc2 + 1] = pack2(l2, l3);
        }
        __syncthreads();

        if (k0 + 32 < K) {
            int kn = k0 + 32;
            #pragma unroll
            for (int i = 0; i < 4; i++) {
                int r = sr + i * 32;
                pa[i] = *(const float4*)(A + (long long)(bm + r) * lda + kn + sc4);
                if (bn + r < N) pw[i] = *(const float4*)(W + (long long)(bn + r) * ldw + kn + sc4);
                else            pw[i] = make_float4(0.f, 0.f, 0.f, 0.f);
            }
        }

        #pragma unroll
        for (int kk2 = 0; kk2 < 16; kk2 += 8) {
            uint32_t bhf[4][2], blf[4][2];
            #pragma unroll
            for (int jn = 0; jn < 4; jn++) {
                int cdx = wn + jn * 8 + lr;
                bhf[jn][0] = Bhi[cdx][kk2 + lc];
                bhf[jn][1] = Bhi[cdx][kk2 + lc + 4];
                blf[jn][0] = Blo[cdx][kk2 + lc];
                blf[jn][1] = Blo[cdx][kk2 + lc + 4];
            }
            #pragma unroll
            for (int im = 0; im < 4; im++) {
                int r = wm + im * 16 + lr;
                uint32_t ah[4], al[4];
                ah[0] = Ahi[r][kk2 + lc];
                ah[1] = Ahi[r + 8][kk2 + lc];
                ah[2] = Ahi[r][kk2 + lc + 4];
                ah[3] = Ahi[r + 8][kk2 + lc + 4];
                al[0] = Alo[r][kk2 + lc];
                al[1] = Alo[r + 8][kk2 + lc];
                al[2] = Alo[r][kk2 + lc + 4];
                al[3] = Alo[r + 8][kk2 + lc + 4];
                #pragma unroll
                for (int jn = 0; jn < 4; jn++) {
                    mma_bf16(acc[im][jn], ah, blf[jn]);
                    mma_bf16(acc[im][jn], al, bhf[jn]);
                    mma_bf16(acc[im][jn], ah, bhf[jn]);
                }
            }
        }
        __syncthreads();
    }

    #pragma unroll
    for (int im = 0; im < 4; im++) {
        #pragma unroll
        for (int jn = 0; jn < 4; jn++) {
            int gm = bm + wm + im * 16 + lr;
            int gc = bn + wn + jn * 8 + 2 * lc;
            if (gc < N) {
                float b0 = bias ? bias[gc] : 0.f;
                float b1 = bias ? bias[gc + 1] : 0.f;
                float* p0 = C + (long long)gm * ldc + gc;
                p0[0] = acc[im][jn][0] + b0;
                p0[1] = acc[im][jn][1] + b1;
                float* p1 = C + (long long)(gm + 8) * ldc + gc;
                p1[0] = acc[im][jn][2] + b0;
                p1[1] = acc[im][jn][3] + b1;
            }
        }
    }
}

// ---------------- tensor-core flash attention (non-causal), split-bf16 ----------------
__global__ __launch_bounds__(256)
void attn_tc_kernel(const float* __restrict__ qkv, float* __restrict__ o)
{
    __shared__ uint32_t Khi[64][36];
    __shared__ uint32_t Klo[64][36];
    __shared__ __nv_bfloat16 Vthi[64][72];
    __shared__ __nv_bfloat16 Vtlo[64][72];

    int bh = blockIdx.y;
    int b = bh >> 4, h = bh & 15;
    int tid = threadIdx.x;
    int wid = tid >> 5, lane = tid & 31;
    int lr = lane >> 2, lc = lane & 3;
    int qrow0 = blockIdx.x * 128 + wid * 16;

    uint32_t qhi[4][4], qlo[4][4];
    {
        const float* qp = qkv + (long long)(b * L_) * 3072 + h * 64;
        #pragma unroll
        for (int kc = 0; kc < 4; kc++) {
            #pragma unroll
            for (int half = 0; half < 2; half++) {
                int col = kc * 16 + 2 * lc + half * 8;
                float2 v0 = *(const float2*)(qp + (long long)(qrow0 + lr) * 3072 + col);
                float2 v1 = *(const float2*)(qp + (long long)(qrow0 + lr + 8) * 3072 + col);
                __nv_bfloat16 h0,l0,h1,l1;
                split_bf16(v0.x * 0.125f, h0, l0); split_bf16(v0.y * 0.125f, h1, l1);
                qhi[kc][half * 2]     = pack2(h0, h1);
                qlo[kc][half * 2]     = pack2(l0, l1);
                split_bf16(v1.x * 0.125f, h0, l0); split_bf16(v1.y * 0.125f, h1, l1);
                qhi[kc][half * 2 + 1] = pack2(h0, h1);
                qlo[kc][half * 2 + 1] = pack2(l0, l1);
            }
        }
    }

    float o_acc[8][4];
    #pragma unroll
    for (int j = 0; j < 8; j++)
        #pragma unroll
        for (int r = 0; r < 4; r++) o_acc[j][r] = 0.f;
    float mrow0 = -1e30f, mrow1 = -1e30f;
    float lrow0 = 0.f, lrow1 = 0.f;

    for (int kt = 0; kt < L_ / 64; kt++) {
        const float* kb = qkv + (long long)(b * L_ + kt * 64) * 3072 + 1024 + h * 64;
        const float* vb = kb + 1024;
        #pragma unroll
        for (int i = 0; i < 4; i++) {
            int idx = tid + i * 256;
            int r = idx >> 4, c4 = (idx & 15) << 2;
            float4 kv = *(const float4*)(kb + (long long)r * 3072 + c4);
            __nv_bfloat16 h0,l0,h1,l1,h2,l2,h3,l3;
            split_bf16(kv.x, h0, l0); split_bf16(kv.y, h1, l1);
            split_bf16(kv.z, h2, l2); split_bf16(kv.w, h3, l3);
            int c2 = c4 >> 1;
            Khi[r][c2]     = pack2(h0, h1);
            Khi[r][c2 + 1] = pack2(h2, h3);
            Klo[r][c2]     = pack2(l0, l1);
            Klo[r][c2 + 1] = pack2(l2, l3);
            float4 vv = *(const float4*)(vb + (long long)r * 3072 + c4);
            __nv_bfloat16 vh, vl;
            split_bf16(vv.x, vh, vl); Vthi[c4 + 0][r] = vh; Vtlo[c4 + 0][r] = vl;
            split_bf16(vv.y, vh, vl); Vthi[c4 + 1][r] = vh; Vtlo[c4 + 1][r] = vl;
            split_bf16(vv.z, vh, vl); Vthi[c4 + 2][r] = vh; Vtlo[c4 + 2][r] = vl;
            split_bf16(vv.w, vh, vl); Vthi[c4 + 3][r] = vh; Vtlo[c4 + 3][r] = vl;
        }
        __syncthreads();

        float s[8][4];
        #pragma unroll
        for (int j = 0; j < 8; j++)
            #pragma unroll
            for (int r = 0; r < 4; r++) s[j][r] = 0.f;
        #pragma unroll
        for (int kc = 0; kc < 4; kc++) {
            #pragma unroll
            for (int jn = 0; jn < 8; jn++) {
                int n = jn * 8 + lr;
                uint32_t bhf[2], blf[2];
                bhf[0] = Khi[n][kc * 8 + lc];
                bhf[1] = Khi[n][kc * 8 + lc + 4];
                blf[0] = Klo[n][kc * 8 + lc];
                blf[1] = Klo[n][kc * 8 + lc + 4];
                mma_bf16(s[jn], qhi[kc], blf);
                mma_bf16(s[jn], qlo[kc], bhf);
                mma_bf16(s[jn], qhi[kc], bhf);
            }
        }

        float t0 = -1e30f, t1 = -1e30f;
        #pragma unroll
        for (int jn = 0; jn < 8; jn++) {
            t0 = fmaxf(t0, fmaxf(s[jn][0], s[jn][1]));
            t1 = fmaxf(t1, fmaxf(s[jn][2], s[jn][3]));
        }
        t0 = fmaxf(t0, __shfl_xor_sync(0xffffffffu, t0, 1));
        t0 = fmaxf(t0, __shfl_xor_sync(0xffffffffu, t0, 2));
        t1 = fmaxf(t1, __shfl_xor_sync(0xffffffffu, t1, 1));
        t1 = fmaxf(t1, __shfl_xor_sync(0xffffffffu, t1, 2));
        float m0n = fmaxf(mrow0, t0), m1n = fmaxf(mrow1, t1);
        float sc0 = __expf(mrow0 - m0n), sc1 = __expf(mrow1 - m1n);
        mrow0 = m0n; mrow1 = m1n;
        lrow0 *= sc0; lrow1 *= sc1;
        #pragma unroll
        for (int j = 0; j < 8; j++) {
            o_acc[j][0] *= sc0; o_acc[j][1] *= sc0;
            o_acc[j][2] *= sc1; o_acc[j][3] *= sc1;
        }

        uint32_t phi[4][4], plo[4][4];
        #pragma unroll
        for (int jn = 0; jn < 8; jn++) {
            float p0 = __expf(s[jn][0] - m0n);
            float p1 = __expf(s[jn][1] - m0n);
            float p2 = __expf(s[jn][2] - m1n);
            float p3 = __expf(s[jn][3] - m1n);
            lrow0 += p0 + p1;
            lrow1 += p2 + p3;
            __nv_bfloat16 h0,l0,h1,l1,h2,l2,h3,l3;
            split_bf16(p0, h0, l0); split_bf16(p1, h1, l1);
            split_bf16(p2, h2, l2); split_bf16(p3, h3, l3);
            int kc = jn >> 1;
            int off = (jn & 1) * 2;
            phi[kc][off]     = pack2(h0, h1);
            phi[kc][off + 1] = pack2(h2, h3);
            plo[kc][off]     = pack2(l0, l1);
            plo[kc][off + 1] = pack2(l2, l3);
        }

        #pragma unroll
        for (int kc = 0; kc < 4; kc++) {
            #pragma unroll
            for (int jd = 0; jd < 8; jd++) {
                int d = jd * 8 + lr;
                uint32_t bhf[2], blf[2];
                bhf[0] = *(const uint32_t*)&Vthi[d][2 * (kc * 8 + lc)];
                bhf[1] = *(const uint32_t*)&Vthi[d][2 * (kc * 8 + lc + 4)];
                blf[0] = *(const uint32_t*)&Vtlo[d][2 * (kc * 8 + lc)];
                blf[1] = *(const uint32_t*)&Vtlo[d][2 * (kc * 8 + lc + 4)];
                mma_bf16(o_acc[jd], phi[kc], blf);
                mma_bf16(o_acc[jd], plo[kc], bhf);
                mma_bf16(o_acc[jd], phi[kc], bhf);
            }
        }
        __syncthreads();
    }

    lrow0 += __shfl_xor_sync(0xffffffffu, lrow0, 1);
    lrow0 += __shfl_xor_sync(0xffffffffu, lrow0, 2);
    lrow1 += __shfl_xor_sync(0xffffffffu, lrow1, 1);
    lrow1 += __shfl_xor_sync(0xffffffffu, lrow1, 2);
    float inv0 = 1.f / lrow0, inv1 = 1.f / lrow1;
    #pragma unroll
    for (int jd = 0; jd < 8; jd++) {
        int col = h * 64 + jd * 8 + 2 * lc;
        float* p0 = o + (long long)(b * L_ + qrow0 + lr) * DM + col;
        p0[0] = o_acc[jd][0] * inv0;
        p0[1] = o_acc[jd][1] * inv0;
        float* p1 = o + (long long)(b * L_ + qrow0 + lr + 8) * DM + col;
        p1[0] = o_acc[jd][2] * inv1;
        p1[1] = o_acc[jd][3] * inv1;
    }
}

// ---------------- tensor-core SSD chunk-states ----------------
__global__ __launch_bounds__(256)
void states_tc_kernel(const float* __restrict__ xbc, const float* __restrict__ xdt,
                      const float* __restrict__ Acs, float* __restrict__ states)
{
    extern __shared__ uint32_t dynst[];
    uint32_t* Ah = dynst;
    uint32_t* Al = Ah + 128 * 36;
    uint32_t* Bh = Al + 128 * 36;
    uint32_t* Bl = Bh + 64 * 36;
    float* dec_sh = (float*)(Bl + 64 * 36);
    __nv_bfloat16* Ah_e = (__nv_bfloat16*)Ah;
    __nv_bfloat16* Al_e = (__nv_bfloat16*)Al;
    __nv_bfloat16* Bh_e = (__nv_bfloat16*)Bh;
    __nv_bfloat16* Bl_e = (__nv_bfloat16*)Bl;

    int blk = blockIdx.x;
    int ck = blk & 7;
    int bh = blk >> 3;
    int h = bh & 31, b = bh >> 5;
    int tid = threadIdx.x;
    int wid = tid >> 5, lane = tid & 31;
    int lr = lane >> 2, lc = lane & 3;
    long long rowbase = (long long)(b * L_ + ck * 256);

    dec_sh[tid] = Acs[(long long)bh * L_ + ck * 256 + tid];
    __syncthreads();
    float aLast = dec_sh[255];
    float mya = dec_sh[tid];
    __syncthreads();
    dec_sh[tid] = __expf(aLast - mya);

    float acc[8][4];
    #pragma unroll
    for (int j = 0; j < 8; j++)
        #pragma unroll
        for (int r = 0; r < 4; r++) acc[j][r] = 0.f;

    for (int kt = 0; kt < 4; kt++) {
        int l0 = kt * 64;
        #pragma unroll
        for (int i = 0; i < 32; i++) {
            int idx = tid + i * 256;
            int n = idx & 127;
            int c = idx >> 7;
            float v = xbc[(rowbase + l0 + c) * CONVD + DI + n] * dec_sh[l0 + c];
            __nv_bfloat16 hi, lo; split_bf16(v, hi, lo);
            Ah_e[n * 72 + c] = hi;
            Al_e[n * 72 + c] = lo;
        }
        #pragma unroll
        for (int i = 0; i < 16; i++) {
            int idx = tid + i * 256;
            int p = idx & 63;
            int c = idx >> 6;
            float v = xdt[(rowbase + l0 + c) * DI + h * 64 + p];
            __nv_bfloat16 hi, lo; split_bf16(v, hi, lo);
            Bh_e[p * 72 + c] = hi;
            Bl_e[p * 72 + c] = lo;
        }
        __syncthreads();
        #pragma unroll
        for (int kk2 = 0; kk2 < 32; kk2 += 8) {
            int r = wid * 16 + lr;
            uint32_t ah[4], al[4];
            ah[0] = Ah[r * 36 + kk2 + lc];
            ah[1] = Ah[(r + 8) * 36 + kk2 + lc];
            ah[2] = Ah[r * 36 + kk2 + lc + 4];
            ah[3] = Ah[(r + 8) * 36 + kk2 + lc + 4];
            al[0] = Al[r * 36 + kk2 + lc];
            al[1] = Al[(r + 8) * 36 + kk2 + lc];
            al[2] = Al[r * 36 + kk2 + lc + 4];
            al[3] = Al[(r + 8) * 36 + kk2 + lc + 4];
            #pragma unroll
            for (int jn = 0; jn < 8; jn++) {
                int n = jn * 8 + lr;
                uint32_t bhf[2], blf[2];
                bhf[0] = Bh[n * 36 + kk2 + lc];
                bhf[1] = Bh[n * 36 + kk2 + lc + 4];
                blf[0] = Bl[n * 36 + kk2 + lc];
                blf[1] = Bl[n * 36 + kk2 + lc + 4];
                mma_bf16(acc[jn], ah, blf);
                mma_bf16(acc[jn], al, bhf);
                mma_bf16(acc[jn], ah, bhf);
            }
        }
        __syncthreads();
    }

    float* base = states + (long long)(bh * NC + ck) * 8192;
    int n0 = wid * 16 + lr;
    #pragma unroll
    for (int jn = 0; jn < 8; jn++) {
        int p = jn * 8 + 2 * lc;
        float* p0 = base + n0 * 64 + p;
        p0[0] = acc[jn][0];
        p0[1] = acc[jn][1];
        float* p1 = base + (n0 + 8) * 64 + p;
        p1[0] = acc[jn][2];
        p1[1] = acc[jn][3];
    }
}

// ---------------- tensor-core SSD output ----------------
__global__ __launch_bounds__(256)
void y_tc_kernel(const float* __restrict__ xbc, const float* __restrict__ xdt,
                 const float* __restrict__ Acs, const float* __restrict__ CB,
                 const float* __restrict__ Sprev, const float* __restrict__ Dv,
                 float* __restrict__ Y)
{
    extern __shared__ uint32_t dyny[];
    uint32_t* Ah = dyny;
    uint32_t* Al = Ah + 128 * 36;
    uint32_t* Bh = Al + 128 * 36;
    uint32_t* Bl = Bh + 64 * 36;
    float* acs_sh = (float*)(Bl + 64 * 36);
    float* eA_sh  = acs_sh + 256;
    __nv_bfloat16* Ah_e = (__nv_bfloat16*)Ah;
    __nv_bfloat16* Al_e = (__nv_bfloat16*)Al;
    __nv_bfloat16* Bh_e = (__nv_bfloat16*)Bh;
    __nv_bfloat16* Bl_e = (__nv_bfloat16*)Bl;

    int blk = blockIdx.x;
    int lh = blk & 1;
    int ck = (blk >> 1) & 7;
    int bh = blk >> 4;
    int h = bh & 31, b = bh >> 5;
    int tid = threadIdx.x;
    int wid = tid >> 5, lane = tid & 31;
    int lr = lane >> 2, lc = lane & 3;
    long long rowbase = (long long)(b * L_ + ck * 256);

    acs_sh[tid] = Acs[(long long)bh * L_ + ck * 256 + tid];
    __syncthreads();
    if (tid < 128) eA_sh[tid] = __expf(acs_sh[lh * 128 + tid]);

    float acc[8][4];
    #pragma unroll
    for (int j = 0; j < 8; j++)
        #pragma unroll
        for (int r = 0; r < 4; r++) acc[j][r] = 0.f;

    const float* cbp = CB + (long long)(b * NC + ck) * (CH * CH);
    int ndiag = (lh == 0) ? 2 : 4;

    for (int kt = 0; kt < ndiag + 2; kt++) {
        if (kt < ndiag) {
            int s0 = kt * 64;
            #pragma unroll
            for (int i = 0; i < 32; i++) {
                int idx = tid + i * 256;
                int l = idx & 127;
                int s = idx >> 7;
                int gl = lh * 128 + l;
                int gs = s0 + s;
                float v = 0.f;
                if (gs <= gl) v = cbp[gs * 256 + gl] * __expf(acs_sh[gl] - acs_sh[gs]);
                __nv_bfloat16 hi, lo; split_bf16(v, hi, lo);
                Ah_e[l * 72 + s] = hi;
                Al_e[l * 72 + s] = lo;
            }
            #pragma unroll
            for (int i = 0; i < 16; i++) {
                int idx = tid + i * 256;
                int p = idx & 63;
                int s = idx >> 6;
                float v = xdt[(rowbase + s0 + s) * DI + h * 64 + p];
                __nv_bfloat16 hi, lo; split_bf16(v, hi, lo);
                Bh_e[p * 72 + s] = hi;
                Bl_e[p * 72 + s] = lo;
            }
        } else {
            int n0 = (kt - ndiag) * 64;
            #pragma unroll
            for (int i = 0; i < 32; i++) {
                int idx = tid + i * 256;
                int c = idx & 63;
                int l = idx >> 6;
                float v = xbc[(rowbase + lh * 128 + l) * CONVD + DI + NST + n0 + c] * eA_sh[l];
                __nv_bfloat16 hi, lo; split_bf16(v, hi, lo);
                Ah_e[l * 72 + c] = hi;
                Al_e[l * 72 + c] = lo;
            }
            #pragma unroll
            for (int i = 0; i < 16; i++) {
                int idx = tid + i * 256;
                int p = idx & 63;
                int c = idx >> 6;
                float v = Sprev[(long long)(bh * NC + ck) * 8192 + (n0 + c) * 64 + p];
                __nv_bfloat16 hi, lo; split_bf16(v, hi, lo);
                Bh_e[p * 72 + c] = hi;
                Bl_e[p * 72 + c] = lo;
            }
        }
        __syncthreads();
        #pragma unroll
        for (int kk2 = 0; kk2 < 32; kk2 += 8) {
            int r = wid * 16 + lr;
            uint32_t ah[4], al[4];
            ah[0] = Ah[r * 36 + kk2 + lc];
            ah[1] = Ah[(r + 8) * 36 + kk2 + lc];
            ah[2] = Ah[r * 36 + kk2 + lc + 4];
            ah[3] = Ah[(r + 8) * 36 + kk2 + lc + 4];
            al[0] = Al[r * 36 + kk2 + lc];
            al[1] = Al[(r + 8) * 36 + kk2 + lc];
            al[2] = Al[r * 36 + kk2 + lc + 4];
            al[3] = Al[(r + 8) * 36 + kk2 + lc + 4];
            #pragma unroll
            for (int jn = 0; jn < 8; jn++) {
                int n = jn * 8 + lr;
                uint32_t bhf[2], blf[2];
                bhf[0] = Bh[n * 36 + kk2 + lc];
                bhf[1] = Bh[n * 36 + kk2 + lc + 4];
                blf[0] = Bl[n * 36 + kk2 + lc];
                blf[1] = Bl[n * 36 + kk2 + lc + 4];
                mma_bf16(acc[jn], ah, blf);
                mma_bf16(acc[jn], al, bhf);
                mma_bf16(acc[jn], ah, bhf);
            }
        }
        __syncthreads();
    }

    float Dh = Dv[h];
    int r0 = wid * 16 + lr;
    #pragma unroll
    for (int jn = 0; jn < 8; jn++) {
        int col = jn * 8 + 2 * lc;
        long long grow0 = rowbase + lh * 128 + r0;
        const float* xs0 = xbc + grow0 * CONVD + h * 64 + col;
        float* yp0 = Y + grow0 * DI + h * 64 + col;
        yp0[0] = acc[jn][0] + Dh * xs0[0];
        yp0[1] = acc[jn][1] + Dh * xs0[1];
        long long grow1 = grow0 + 8;
        const float* xs1 = xbc + grow1 * CONVD + h * 64 + col;
        float* yp1 = Y + grow1 * DI + h * 64 + col;
        yp1[0] = acc[jn][2] + Dh * xs1[0];
        yp1[1] = acc[jn][3] + Dh * xs1[1];
    }
}

// ---------------- rmsnorm (float4) ----------------
__global__ void rmsnorm_kernel(const float* __restrict__ a, const float* __restrict__ b,
                               float alpha, const float* __restrict__ w,
                               float* __restrict__ out, int D)
{
    long long row = blockIdx.x;
    const float4* ap = (const float4*)(a + row * D);
    const float4* bp = b ? (const float4*)(b + row * D) : nullptr;
    int per = D >> 10;              // D/(4*256): 1 or 2
    float4 v[2];
    float ss = 0.f;
    for (int j = 0; j < per; j++) {
        int i = threadIdx.x + j * 256;
        float4 x = ap[i];
        if (bp) {
            float4 y = bp[i];
            x.x += alpha * y.x; x.y += alpha * y.y;
            x.z += alpha * y.z; x.w += alpha * y.w;
        }
        v[j] = x;
        ss += x.x * x.x + x.y * x.y + x.z * x.z + x.w * x.w;
    }
    __shared__ float red[256];
    red[threadIdx.x] = ss;
    __syncthreads();
    for (int off = 128; off; off >>= 1) {
        if (threadIdx.x < off) red[threadIdx.x] += red[threadIdx.x + off];
        __syncthreads();
    }
    float scale = rsqrtf(red[0] / D + EPSN);
    const float4* wp = (const float4*)w;
    float4* op = (float4*)(out + row * D);
    for (int j = 0; j < per; j++) {
        int i = threadIdx.x + j * 256;
        float4 x = v[j], ww = wp[i];
        float4 r;
        r.x = x.x * scale * ww.x; r.y = x.y * scale * ww.y;
        r.z = x.z * scale * ww.z; r.w = x.w * scale * ww.w;
        op[i] = r;
    }
}

// ---------------- gated rmsnorm (float4), D=2048 ----------------
__global__ void gated_rmsnorm_kernel(const float* __restrict__ y, const float* __restrict__ z,
                                     int ldz, const float* __restrict__ w,
                                     float* __restrict__ out)
{
    long long row = blockIdx.x;
    const float4* yp = (const float4*)(y + row * DI);
    const float4* zp = (const float4*)(z + row * (long long)ldz);
    float4 v[2];
    float ss = 0.f;
    #pragma unroll
    for (int j = 0; j < 2; j++) {
        int i = threadIdx.x + j * 256;
        float4 yv = yp[i], zv = zp[i];
        float4 x;
        x.x = yv.x * silu_f(zv.x); x.y = yv.y * silu_f(zv.y);
        x.z = yv.z * silu_f(zv.z); x.w = yv.w * silu_f(zv.w);
        v[j] = x;
        ss += x.x * x.x + x.y * x.y + x.z * x.z + x.w * x.w;
    }
    __shared__ float red[256];
    red[threadIdx.x] = ss;
    __syncthreads();
    for (int off = 128; off; off >>= 1) {
        if (threadIdx.x < off) red[threadIdx.x] += red[threadIdx.x + off];
        __syncthreads();
    }
    float scale = rsqrtf(red[0] / DI + EPSN);
    const float4* wp = (const float4*)w;
    float4* op = (float4*)(out + row * DI);
    #pragma unroll
    for (int j = 0; j < 2; j++) {
        int i = threadIdx.x + j * 256;
        float4 x = v[j], ww = wp[i];
        float4 r;
        r.x = x.x * scale * ww.x; r.y = x.y * scale * ww.y;
        r.z = x.z * scale * ww.z; r.w = x.w * scale * ww.w;
        op[i] = r;
    }
}

// ---------------- depthwise causal conv (k=4) + bias + silu, float4 over channels ----------------
__global__ void conv_kernel(const float* __restrict__ zx, const float* __restrict__ cw,
                            const float* __restrict__ cb, float* __restrict__ xbc)
{
    int idx = blockIdx.x * 256 + threadIdx.x;    // over ROWS*CONVD/4
    if (idx >= ROWS * (CONVD / 4)) return;
    int c4 = (idx % (CONVD / 4)) << 2;
    int row = idx / (CONVD / 4);
    int t = row % L_;
    int b = row / L_;
    float4 s = *(const float4*)(cb + c4);
    float4 w0 = *(const float4*)(cw + (c4 + 0) * 4);   // taps of channel c4+0
    float4 w1 = *(const float4*)(cw + (c4 + 1) * 4);
    float4 w2 = *(const float4*)(cw + (c4 + 2) * 4);
    float4 w3 = *(const float4*)(cw + (c4 + 3) * 4);
    const float* wa0 = (const float*)&w0;
    const float* wa1 = (const float*)&w1;
    const float* wa2 = (const float*)&w2;
    const float* wa3 = (const float*)&w3;
    #pragma unroll
    for (int k = 0; k < 4; k++) {
        int tt = t - 3 + k;
        if (tt >= 0) {
            float4 z = *(const float4*)(zx + ((long long)(b * L_ + tt) * DINP) + DI + c4);
            s.x += z.x * wa0[k];
            s.y += z.y * wa1[k];
            s.z += z.z * wa2[k];
            s.w += z.w * wa3[k];
        }
    }
    float4 r;
    r.x = silu_f(s.x); r.y = silu_f(s.y);
    r.z = silu_f(s.z); r.w = silu_f(s.w);
    *(float4*)(xbc + (long long)row * CONVD + c4) = r;
}

// ---------------- dt (softplus) and xdt = xs*dt, float4 ----------------
__global__ void dtxdt_kernel(const float* __restrict__ zx, const float* __restrict__ xbc,
                             const float* __restrict__ dt_bias,
                             float* __restrict__ dtb, float* __restrict__ xdt)
{
    int idx = blockIdx.x * 256 + threadIdx.x;    // over ROWS*DI/4
    if (idx >= ROWS * (DI / 4)) return;
    int c = (idx % (DI / 4)) << 2;               // channel base (4 consecutive, same head)
    long long row = idx / (DI / 4);
    int h = c >> 6;
    float raw = zx[row * DINP + DI + CONVD + h] + dt_bias[h];
    float d = softplus_f(raw);
    float4 xv = *(const float4*)(xbc + row * CONVD + c);
    float4 r;
    r.x = xv.x * d; r.y = xv.y * d; r.z = xv.z * d; r.w = xv.w * d;
    *(float4*)(xdt + row * DI + c) = r;
    if ((c & 63) == 0) dtb[row * HS + h] = d;
}

// ---------------- per-chunk inclusive cumsum ----------------
__global__ void cumsum_kernel(const float* __restrict__ dtb, const float* __restrict__ A_log,
                              float* __restrict__ Acs)
{
    __shared__ float s[256];
    int blk = blockIdx.x;
    int ck = blk & 7;
    int bh = blk >> 3;
    int h = bh & 31;
    int b = bh >> 5;
    int l = threadIdx.x;
    int gl = ck * 256 + l;
    float a = -__expf(A_log[h]) * dtb[((long long)(b * L_ + gl)) * HS + h];
    s[l] = a;
    __syncthreads();
    for (int off = 1; off < 256; off <<= 1) {
        float t = (l >= off) ? s[l - off] : 0.f;
        __syncthreads();
        s[l] += t;
        __syncthreads();
    }
    Acs[(long long)bh * L_ + gl] = s[l];
}

// ---------------- inter-chunk scan ----------------
__global__ void scan_kernel(const float* __restrict__ states, const float* __restrict__ Acs,
                            float* __restrict__ Sprev)
{
    int bh = blockIdx.x;
    int tid = threadIdx.x;
    float S[32];
    #pragma unroll
    for (int j = 0; j < 32; j++) S[j] = 0.f;
    for (int c = 0; c < NC; c++) {
        float dc = __expf(Acs[(long long)bh * L_ + c * 256 + 255]);
        const float* sp = states + (long long)(bh * NC + c) * 8192;
        float* pp = Sprev + (long long)(bh * NC + c) * 8192;
        #pragma unroll
        for (int j = 0; j < 32; j++) {
            int idx = tid + j * 256;
            pp[idx] = S[j];
            S[j] = S[j] * dc + sp[idx];
        }
    }
}

// ---------------- swiglu (float4) ----------------
__global__ void swiglu_kernel(const float* __restrict__ y, float* __restrict__ ff)
{
    int idx = blockIdx.x * 256 + threadIdx.x;    // over ROWS*DFF/4
    if (idx >= ROWS * (DFF / 4)) return;
    long long row = idx / (DFF / 4);
    int f4 = idx % (DFF / 4);
    const float4* yp = (const float4*)(y + row * (2 * DFF));
    float4 a = yp[f4];
    float4 g = yp[f4 + DFF / 4];
    float4 r;
    r.x = a.x * silu_f(g.x); r.y = a.y * silu_f(g.y);
    r.z = a.z * silu_f(g.z); r.w = a.w * silu_f(g.w);
    *(float4*)(ff + row * DFF + f4 * 4) = r;
}

// ---------------- host launcher ----------------
#define SSD_SMEM 57344

extern "C" void kernel_launch(void* const* d_in, const int* in_sizes, int n_in,
                              void* d_out, int out_size)
{
    const float* x_in       = (const float*)d_in[0];
    const float* attn_norm  = (const float*)d_in[1];
    const float* Wqkv       = (const float*)d_in[2];
    const float* Wqkv_b     = (const float*)d_in[3];
    const float* attn_out_w = (const float*)d_in[4];
    const float* attn_out_b = (const float*)d_in[5];
    const float* normf_w    = (const float*)d_in[6];
    const float* m_in_w     = (const float*)d_in[7];
    const float* m_conv_w   = (const float*)d_in[8];
    const float* m_conv_b   = (const float*)d_in[9];
    const float* m_dt_bias  = (const float*)d_in[10];
    const float* m_A_log    = (const float*)d_in[11];
    const float* m_D        = (const float*)d_in[12];
    const float* m_norm_w   = (const float*)d_in[13];
    const float* m_out_w    = (const float*)d_in[14];
    const float* fc1_w      = (const float*)d_in[15];
    const float* fc2_w      = (const float*)d_in[16];
    const float* final_norm = (const float*)d_in[17];
    float* out = (float*)d_out;

    float* scr = nullptr;
    cudaGetSymbolAddress((void**)&scr, g_scratch);

    cudaFuncSetAttribute(states_tc_kernel, cudaFuncAttributeMaxDynamicSharedMemorySize, SSD_SMEM);
    cudaFuncSetAttribute(y_tc_kernel, cudaFuncAttributeMaxDynamicSharedMemorySize, SSD_SMEM);

    float* bBIG = scr + OFF_BIG;
    float* bH   = scr + OFF_H;
    float* bO   = scr + OFF_O;
    float* bX   = scr + OFF_X;
    float* bXBC = scr + OFF_XBC;
    float* bDT  = scr + OFF_DT;
    float* bXDT = scr + OFF_XDT;
    float* bACS = scr + OFF_ACS;
    float* bCB  = scr + OFF_CB;
    float* bSTA = scr + OFF_STA;
    float* bSPR = scr + OFF_SPR;
    float* bY   = scr + OFF_Y;
    float* bFF  = scr + OFF_FF;

    // ---- attention block ----
    rmsnorm_kernel<<<ROWS, 256>>>(x_in, nullptr, 0.f, attn_norm, bH, DM);
    gemm_tc<<<dim3(3072/128, ROWS/128, 1), 256>>>(bH, Wqkv, Wqkv_b, bBIG,
        ROWS, 3072, DM, DM, DM, 3072, 0, 0, 0);
    attn_tc_kernel<<<dim3(L_/128, B_*NH), 256>>>(bBIG, bO);
    gemm_tc<<<dim3(DM/128, ROWS/128, 1), 256>>>(bO, attn_out_w, attn_out_b, bH,
        ROWS, DM, DM, DM, DM, DM, 0, 0, 0);
    rmsnorm_kernel<<<ROWS, 256>>>(bH, x_in, 1.f, normf_w, bX, DM);

    // ---- mamba layers ----
    for (int i = 0; i < 4; i++) {
        const float* in_w   = m_in_w   + (long long)i * DINP * DM;
        const float* conv_w = m_conv_w + (long long)i * CONVD * 4;
        const float* conv_b = m_conv_b + (long long)i * CONVD;
        const float* dtbias = m_dt_bias+ (long long)i * HS;
        const float* Alog   = m_A_log  + (long long)i * HS;
        const float* Dv     = m_D      + (long long)i * HS;
        const float* nw     = m_norm_w + (long long)i * DI;
        const float* ow     = m_out_w  + (long long)i * DM * DI;

        gemm_tc<<<dim3((DINP+127)/128, ROWS/128, 1), 256>>>(bX, in_w, nullptr, bBIG,
            ROWS, DINP, DM, DM, DM, DINP, 0, 0, 0);
        conv_kernel<<<(ROWS*(CONVD/4))/256, 256>>>(bBIG, conv_w, conv_b, bXBC);
        dtxdt_kernel<<<(ROWS*(DI/4))/256, 256>>>(bBIG, bXBC, dtbias, bDT, bXDT);
        cumsum_kernel<<<B_*HS*NC, 256>>>(bDT, Alog, bACS);
        gemm_tc<<<dim3(2, 2, B_*NC), 256>>>(
            bXBC + DI, bXBC + DI + NST, nullptr, bCB,
            CH, CH, NST, CONVD, CONVD, CH,
            (long long)CH * CONVD, (long long)CH * CONVD, (long long)CH * CH);
        states_tc_kernel<<<B_*HS*NC, 256, SSD_SMEM>>>(bXBC, bXDT, bACS, bSTA);
        scan_kernel<<<B_*HS, 256>>>(bSTA, bACS, bSPR);
        y_tc_kernel<<<B_*HS*NC*2, 256, SSD_SMEM>>>(bXBC, bXDT, bACS, bCB, bSPR, Dv, bY);
        gated_rmsnorm_kernel<<<ROWS, 256>>>(bY, bBIG, DINP, nw, bY);
        gemm_tc<<<dim3(DM/128, ROWS/128, 1), 256>>>(bY, ow, nullptr, bX,
            ROWS, DM, DI, DI, DI, DM, 0, 0, 0);
    }

    // ---- MLP + final norm ----
    gemm_tc<<<dim3((2*DFF)/128, ROWS/128, 1), 256>>>(bX, fc1_w, nullptr, bBIG,
        ROWS, 2*DFF, DM, DM, DM, 2*DFF, 0, 0, 0);
    swiglu_kernel<<<(ROWS*(DFF/4))/256, 256>>>(bBIG, bFF);
    gemm_tc<<<dim3(DM/128, ROWS/128, 1), 256>>>(bFF, fc2_w, nullptr, bH,
        ROWS, DM, DFF, DFF, DFF, DM, 0, 0, 0);
    rmsnorm_kernel<<<ROWS, 256>>>(bH, bX, ALPHA, final_norm, out, DM);
}

// round 12
// speedup vs baseline: 1.3620x; 1.0118x over previous
#include <cuda_runtime.h>
#include <cuda_bf16.h>
#include <math.h>
#include <stdint.h>

// ---------------- constants ----------------
#define B_   2
#define L_   2048
#define DM   1024          // D_MODEL
#define NH   16            // NHEAD
#define HD   64            // HD_ATT
#define DI   2048          // D_INNER
#define HS   32            // H_SSM
#define P_   64            // HEADDIM
#define NST  128           // D_STATE
#define CONVD 2304         // CONV_DIM
#define DINP 4384          // D_IN_PROJ
#define CH   256           // CHUNK
#define NC   8             // L/CHUNK
#define DFF  2048
#define ALPHA 1.68f
#define EPSN 1e-5f

#define ROWS (B_*L_)       // 4096

// ---------------- scratch ----------------
static const long long SZ_BIG  = (long long)ROWS*DINP;
static const long long SZ_HB   = (long long)ROWS*DM;
static const long long SZ_XBC  = (long long)ROWS*CONVD;
static const long long SZ_DT   = (long long)ROWS*HS;
static const long long SZ_XDT  = (long long)ROWS*DI;
static const long long SZ_ACS  = (long long)B_*HS*L_;
static const long long SZ_CB   = (long long)B_*NC*CH*CH;
static const long long SZ_ST   = (long long)B_*HS*NC*NST*P_;
static const long long SZ_Y    = (long long)ROWS*DI;

static const long long OFF_BIG = 0;
static const long long OFF_H   = OFF_BIG + SZ_BIG;
static const long long OFF_O   = OFF_H   + SZ_HB;
static const long long OFF_X   = OFF_O   + SZ_HB;
static const long long OFF_XBC = OFF_X   + SZ_HB;
static const long long OFF_DT  = OFF_XBC + SZ_XBC;
static const long long OFF_XDT = OFF_DT  + SZ_DT;
static const long long OFF_ACS = OFF_XDT + SZ_XDT;
static const long long OFF_CB  = OFF_ACS + SZ_ACS;
static const long long OFF_STA = OFF_CB  + SZ_CB;
static const long long OFF_SPR = OFF_STA + SZ_ST;
static const long long OFF_Y   = OFF_SPR + SZ_ST;
static const long long OFF_FF  = OFF_Y   + SZ_Y;
static const long long TOTALF  = OFF_FF  + SZ_Y;

__device__ float g_scratch[74842112]; // == TOTALF floats (~300 MB)

// ---------------- helpers ----------------
__device__ __forceinline__ float silu_f(float x) {
    return x / (1.f + __expf(-x));
}
__device__ __forceinline__ float softplus_f(float x) {
    return (x > 20.f) ? x : log1pf(__expf(x));
}
__device__ __forceinline__ void split_bf16(float x, __nv_bfloat16& hi, __nv_bfloat16& lo) {
    hi = __float2bfloat16_rn(x);
    lo = __float2bfloat16_rn(x - __bfloat162float(hi));
}
__device__ __forceinline__ uint32_t pack2(__nv_bfloat16 a, __nv_bfloat16 b) {
    __nv_bfloat162 h;
    h.x = a; h.y = b;
    return *(uint32_t*)&h;
}
__device__ __forceinline__ void mma_bf16(float* c, const uint32_t* a, const uint32_t* b) {
    asm volatile(
        "mma.sync.aligned.m16n8k16.row.col.f32.bf16.bf16.f32 "
        "{%0,%1,%2,%3}, {%4,%5,%6,%7}, {%8,%9}, {%0,%1,%2,%3};"
        : "+f"(c[0]), "+f"(c[1]), "+f"(c[2]), "+f"(c[3])
        : "r"(a[0]), "r"(a[1]), "r"(a[2]), "r"(a[3]), "r"(b[0]), "r"(b[1]));
}

// ---------------- bf16x2 split tensor-core NT GEMM, register-prefetch pipelined ----------------
// Measured-best configuration (R6): static 40KB SMEM, K-tile 32, register LDG prefetch.
#define SSTR 20
__global__ __launch_bounds__(256, 2)
void gemm_tc(const float* __restrict__ A, const float* __restrict__ W,
             const float* __restrict__ bias, float* __restrict__ C,
             int M, int N, int K, int lda, int ldw, int ldc,
             long long sA, long long sW, long long sC)
{
    A += (long long)blockIdx.z * sA;
    W += (long long)blockIdx.z * sW;
    C += (long long)blockIdx.z * sC;

    __shared__ uint32_t Ahi[128][SSTR];
    __shared__ uint32_t Alo[128][SSTR];
    __shared__ uint32_t Bhi[128][SSTR];
    __shared__ uint32_t Blo[128][SSTR];

    int bm = blockIdx.y * 128, bn = blockIdx.x * 128;
    int tid = threadIdx.x;
    int wid = tid >> 5, lane = tid & 31;
    int wm = (wid >> 2) * 64;
    int wn = (wid & 3) * 32;
    int lr = lane >> 2;
    int lc = lane & 3;

    int sr = tid >> 3;
    int sc4 = (tid & 7) << 2;
    int sc2 = sc4 >> 1;

    float acc[4][4][4];
    #pragma unroll
    for (int i = 0; i < 4; i++)
        #pragma unroll
        for (int j = 0; j < 4; j++)
            #pragma unroll
            for (int r = 0; r < 4; r++) acc[i][j][r] = 0.f;

    float4 pa[4], pw[4];
    #pragma unroll
    for (int i = 0; i < 4; i++) {
        int r = sr + i * 32;
        pa[i] = *(const float4*)(A + (long long)(bm + r) * lda + sc4);
        if (bn + r < N) pw[i] = *(const float4*)(W + (long long)(bn + r) * ldw + sc4);
        else            pw[i] = make_float4(0.f, 0.f, 0.f, 0.f);
    }

    for (int k0 = 0; k0 < K; k0 += 32) {
        #pragma unroll
        for (int i = 0; i < 4; i++) {
            int r = sr + i * 32;
            __nv_bfloat16 h0,l0,h1,l1,h2,l2,h3,l3;
            split_bf16(pa[i].x, h0, l0); split_bf16(pa[i].y, h1, l1);
            split_bf16(pa[i].z, h2, l2); split_bf16(pa[i].w, h3, l3);
            Ahi[r][sc2]     = pack2(h0, h1);
            Ahi[r][sc2 + 1] = pack2(h2, h3);
            Alo[r][sc2]     = pack2(l0, l1);
            Alo[r][sc2 + 1] = pack2(l2, l3);
            split_bf16(pw[i].x, h0, l0); split_bf16(pw[i].y, h1, l1);
            split_bf16(pw[i].z, h2, l2); split_bf16(pw[i].w, h3, l3);
            Bhi[r][sc2]     = pack2(h0, h1);
            Bhi[r][sc2 + 1] = pack2(h2, h3);
            Blo[r][sc2]     = pack2(l0, l1);
            Blo[r][sc2 + 1] = pack2(l2, l3);
        }
        __syncthreads();

        if (k0 + 32 < K) {
            int kn = k0 + 32;
            #pragma unroll
            for (int i = 0; i < 4; i++) {
                int r = sr + i * 32;
                pa[i] = *(const float4*)(A + (long long)(bm + r) * lda + kn + sc4);
                if (bn + r < N) pw[i] = *(const float4*)(W + (long long)(bn + r) * ldw + kn + sc4);
                else            pw[i] = make_float4(0.f, 0.f, 0.f, 0.f);
            }
        }

        #pragma unroll
        for (int kk2 = 0; kk2 < 16; kk2 += 8) {
            uint32_t bhf[4][2], blf[4][2];
            #pragma unroll
            for (int jn = 0; jn < 4; jn++) {
                int cdx = wn + jn * 8 + lr;
                bhf[jn][0] = Bhi[cdx][kk2 + lc];
                bhf[jn][1] = Bhi[cdx][kk2 + lc + 4];
                blf[jn][0] = Blo[cdx][kk2 + lc];
                blf[jn][1] = Blo[cdx][kk2 + lc + 4];
            }
            #pragma unroll
            for (int im = 0; im < 4; im++) {
                int r = wm + im * 16 + lr;
                uint32_t ah[4], al[4];
                ah[0] = Ahi[r][kk2 + lc];
                ah[1] = Ahi[r + 8][kk2 + lc];
                ah[2] = Ahi[r][kk2 + lc + 4];
                ah[3] = Ahi[r + 8][kk2 + lc + 4];
                al[0] = Alo[r][kk2 + lc];
                al[1] = Alo[r + 8][kk2 + lc];
                al[2] = Alo[r][kk2 + lc + 4];
                al[3] = Alo[r + 8][kk2 + lc + 4];
                #pragma unroll
                for (int jn = 0; jn < 4; jn++) {
                    mma_bf16(acc[im][jn], ah, blf[jn]);
                    mma_bf16(acc[im][jn], al, bhf[jn]);
                    mma_bf16(acc[im][jn], ah, bhf[jn]);
                }
            }
        }
        __syncthreads();
    }

    #pragma unroll
    for (int im = 0; im < 4; im++) {
        #pragma unroll
        for (int jn = 0; jn < 4; jn++) {
            int gm = bm + wm + im * 16 + lr;
            int gc = bn + wn + jn * 8 + 2 * lc;
            if (gc < N) {
                float b0 = bias ? bias[gc] : 0.f;
                float b1 = bias ? bias[gc + 1] : 0.f;
                float* p0 = C + (long long)gm * ldc + gc;
                p0[0] = acc[im][jn][0] + b0;
                p0[1] = acc[im][jn][1] + b1;
                float* p1 = C + (long long)(gm + 8) * ldc + gc;
                p1[0] = acc[im][jn][2] + b0;
                p1[1] = acc[im][jn][3] + b1;
            }
        }
    }
}

// ---------------- tensor-core flash attention (non-causal), split-bf16 ----------------
__global__ __launch_bounds__(256)
void attn_tc_kernel(const float* __restrict__ qkv, float* __restrict__ o)
{
    __shared__ uint32_t Khi[64][36];
    __shared__ uint32_t Klo[64][36];
    __shared__ __nv_bfloat16 Vthi[64][72];
    __shared__ __nv_bfloat16 Vtlo[64][72];

    int bh = blockIdx.y;
    int b = bh >> 4, h = bh & 15;
    int tid = threadIdx.x;
    int wid = tid >> 5, lane = tid & 31;
    int lr = lane >> 2, lc = lane & 3;
    int qrow0 = blockIdx.x * 128 + wid * 16;

    uint32_t qhi[4][4], qlo[4][4];
    {
        const float* qp = qkv + (long long)(b * L_) * 3072 + h * 64;
        #pragma unroll
        for (int kc = 0; kc < 4; kc++) {
            #pragma unroll
            for (int half = 0; half < 2; half++) {
                int col = kc * 16 + 2 * lc + half * 8;
                float2 v0 = *(const float2*)(qp + (long long)(qrow0 + lr) * 3072 + col);
                float2 v1 = *(const float2*)(qp + (long long)(qrow0 + lr + 8) * 3072 + col);
                __nv_bfloat16 h0,l0,h1,l1;
                split_bf16(v0.x * 0.125f, h0, l0); split_bf16(v0.y * 0.125f, h1, l1);
                qhi[kc][half * 2]     = pack2(h0, h1);
                qlo[kc][half * 2]     = pack2(l0, l1);
                split_bf16(v1.x * 0.125f, h0, l0); split_bf16(v1.y * 0.125f, h1, l1);
                qhi[kc][half * 2 + 1] = pack2(h0, h1);
                qlo[kc][half * 2 + 1] = pack2(l0, l1);
            }
        }
    }

    float o_acc[8][4];
    #pragma unroll
    for (int j = 0; j < 8; j++)
        #pragma unroll
        for (int r = 0; r < 4; r++) o_acc[j][r] = 0.f;
    float mrow0 = -1e30f, mrow1 = -1e30f;
    float lrow0 = 0.f, lrow1 = 0.f;

    for (int kt = 0; kt < L_ / 64; kt++) {
        const float* kb = qkv + (long long)(b * L_ + kt * 64) * 3072 + 1024 + h * 64;
        const float* vb = kb + 1024;
        #pragma unroll
        for (int i = 0; i < 4; i++) {
            int idx = tid + i * 256;
            int r = idx >> 4, c4 = (idx & 15) << 2;
            float4 kv = *(const float4*)(kb + (long long)r * 3072 + c4);
            __nv_bfloat16 h0,l0,h1,l1,h2,l2,h3,l3;
            split_bf16(kv.x, h0, l0); split_bf16(kv.y, h1, l1);
            split_bf16(kv.z, h2, l2); split_bf16(kv.w, h3, l3);
            int c2 = c4 >> 1;
            Khi[r][c2]     = pack2(h0, h1);
            Khi[r][c2 + 1] = pack2(h2, h3);
            Klo[r][c2]     = pack2(l0, l1);
            Klo[r][c2 + 1] = pack2(l2, l3);
            float4 vv = *(const float4*)(vb + (long long)r * 3072 + c4);
            __nv_bfloat16 vh, vl;
            split_bf16(vv.x, vh, vl); Vthi[c4 + 0][r] = vh; Vtlo[c4 + 0][r] = vl;
            split_bf16(vv.y, vh, vl); Vthi[c4 + 1][r] = vh; Vtlo[c4 + 1][r] = vl;
            split_bf16(vv.z, vh, vl); Vthi[c4 + 2][r] = vh; Vtlo[c4 + 2][r] = vl;
            split_bf16(vv.w, vh, vl); Vthi[c4 + 3][r] = vh; Vtlo[c4 + 3][r] = vl;
        }
        __syncthreads();

        float s[8][4];
        #pragma unroll
        for (int j = 0; j < 8; j++)
            #pragma unroll
            for (int r = 0; r < 4; r++) s[j][r] = 0.f;
        #pragma unroll
        for (int kc = 0; kc < 4; kc++) {
            #pragma unroll
            for (int jn = 0; jn < 8; jn++) {
                int n = jn * 8 + lr;
                uint32_t bhf[2], blf[2];
                bhf[0] = Khi[n][kc * 8 + lc];
                bhf[1] = Khi[n][kc * 8 + lc + 4];
                blf[0] = Klo[n][kc * 8 + lc];
                blf[1] = Klo[n][kc * 8 + lc + 4];
                mma_bf16(s[jn], qhi[kc], blf);
                mma_bf16(s[jn], qlo[kc], bhf);
                mma_bf16(s[jn], qhi[kc], bhf);
            }
        }

        float t0 = -1e30f, t1 = -1e30f;
        #pragma unroll
        for (int jn = 0; jn < 8; jn++) {
            t0 = fmaxf(t0, fmaxf(s[jn][0], s[jn][1]));
            t1 = fmaxf(t1, fmaxf(s[jn][2], s[jn][3]));
        }
        t0 = fmaxf(t0, __shfl_xor_sync(0xffffffffu, t0, 1));
        t0 = fmaxf(t0, __shfl_xor_sync(0xffffffffu, t0, 2));
        t1 = fmaxf(t1, __shfl_xor_sync(0xffffffffu, t1, 1));
        t1 = fmaxf(t1, __shfl_xor_sync(0xffffffffu, t1, 2));
        float m0n = fmaxf(mrow0, t0), m1n = fmaxf(mrow1, t1);
        float sc0 = __expf(mrow0 - m0n), sc1 = __expf(mrow1 - m1n);
        mrow0 = m0n; mrow1 = m1n;
        lrow0 *= sc0; lrow1 *= sc1;
        #pragma unroll
        for (int j = 0; j < 8; j++) {
            o_acc[j][0] *= sc0; o_acc[j][1] *= sc0;
            o_acc[j][2] *= sc1; o_acc[j][3] *= sc1;
        }

        uint32_t phi[4][4], plo[4][4];
        #pragma unroll
        for (int jn = 0; jn < 8; jn++) {
            float p0 = __expf(s[jn][0] - m0n);
            float p1 = __expf(s[jn][1] - m0n);
            float p2 = __expf(s[jn][2] - m1n);
            float p3 = __expf(s[jn][3] - m1n);
            lrow0 += p0 + p1;
            lrow1 += p2 + p3;
            __nv_bfloat16 h0,l0,h1,l1,h2,l2,h3,l3;
            split_bf16(p0, h0, l0); split_bf16(p1, h1, l1);
            split_bf16(p2, h2, l2); split_bf16(p3, h3, l3);
            int kc = jn >> 1;
            int off = (jn & 1) * 2;
            phi[kc][off]     = pack2(h0, h1);
            phi[kc][off + 1] = pack2(h2, h3);
            plo[kc][off]     = pack2(l0, l1);
            plo[kc][off + 1] = pack2(l2, l3);
        }

        #pragma unroll
        for (int kc = 0; kc < 4; kc++) {
            #pragma unroll
            for (int jd = 0; jd < 8; jd++) {
                int d = jd * 8 + lr;
                uint32_t bhf[2], blf[2];
                bhf[0] = *(const uint32_t*)&Vthi[d][2 * (kc * 8 + lc)];
                bhf[1] = *(const uint32_t*)&Vthi[d][2 * (kc * 8 + lc + 4)];
                blf[0] = *(const uint32_t*)&Vtlo[d][2 * (kc * 8 + lc)];
                blf[1] = *(const uint32_t*)&Vtlo[d][2 * (kc * 8 + lc + 4)];
                mma_bf16(o_acc[jd], phi[kc], blf);
                mma_bf16(o_acc[jd], plo[kc], bhf);
                mma_bf16(o_acc[jd], phi[kc], bhf);
            }
        }
        __syncthreads();
    }

    lrow0 += __shfl_xor_sync(0xffffffffu, lrow0, 1);
    lrow0 += __shfl_xor_sync(0xffffffffu, lrow0, 2);
    lrow1 += __shfl_xor_sync(0xffffffffu, lrow1, 1);
    lrow1 += __shfl_xor_sync(0xffffffffu, lrow1, 2);
    float inv0 = 1.f / lrow0, inv1 = 1.f / lrow1;
    #pragma unroll
    for (int jd = 0; jd < 8; jd++) {
        int col = h * 64 + jd * 8 + 2 * lc;
        float* p0 = o + (long long)(b * L_ + qrow0 + lr) * DM + col;
        p0[0] = o_acc[jd][0] * inv0;
        p0[1] = o_acc[jd][1] * inv0;
        float* p1 = o + (long long)(b * L_ + qrow0 + lr + 8) * DM + col;
        p1[0] = o_acc[jd][2] * inv1;
        p1[1] = o_acc[jd][3] * inv1;
    }
}

// ---------------- tensor-core SSD chunk-states ----------------
__global__ __launch_bounds__(256)
void states_tc_kernel(const float* __restrict__ xbc, const float* __restrict__ xdt,
                      const float* __restrict__ Acs, float* __restrict__ states)
{
    extern __shared__ uint32_t dynst[];
    uint32_t* Ah = dynst;
    uint32_t* Al = Ah + 128 * 36;
    uint32_t* Bh = Al + 128 * 36;
    uint32_t* Bl = Bh + 64 * 36;
    float* dec_sh = (float*)(Bl + 64 * 36);
    __nv_bfloat16* Ah_e = (__nv_bfloat16*)Ah;
    __nv_bfloat16* Al_e = (__nv_bfloat16*)Al;
    __nv_bfloat16* Bh_e = (__nv_bfloat16*)Bh;
    __nv_bfloat16* Bl_e = (__nv_bfloat16*)Bl;

    int blk = blockIdx.x;
    int ck = blk & 7;
    int bh = blk >> 3;
    int h = bh & 31, b = bh >> 5;
    int tid = threadIdx.x;
    int wid = tid >> 5, lane = tid & 31;
    int lr = lane >> 2, lc = lane & 3;
    long long rowbase = (long long)(b * L_ + ck * 256);

    dec_sh[tid] = Acs[(long long)bh * L_ + ck * 256 + tid];
    __syncthreads();
    float aLast = dec_sh[255];
    float mya = dec_sh[tid];
    __syncthreads();
    dec_sh[tid] = __expf(aLast - mya);

    float acc[8][4];
    #pragma unroll
    for (int j = 0; j < 8; j++)
        #pragma unroll
        for (int r = 0; r < 4; r++) acc[j][r] = 0.f;

    for (int kt = 0; kt < 4; kt++) {
        int l0 = kt * 64;
        #pragma unroll
        for (int i = 0; i < 32; i++) {
            int idx = tid + i * 256;
            int n = idx & 127;
            int c = idx >> 7;
            float v = xbc[(rowbase + l0 + c) * CONVD + DI + n] * dec_sh[l0 + c];
            __nv_bfloat16 hi, lo; split_bf16(v, hi, lo);
            Ah_e[n * 72 + c] = hi;
            Al_e[n * 72 + c] = lo;
        }
        #pragma unroll
        for (int i = 0; i < 16; i++) {
            int idx = tid + i * 256;
            int p = idx & 63;
            int c = idx >> 6;
            float v = xdt[(rowbase + l0 + c) * DI + h * 64 + p];
            __nv_bfloat16 hi, lo; split_bf16(v, hi, lo);
            Bh_e[p * 72 + c] = hi;
            Bl_e[p * 72 + c] = lo;
        }
        __syncthreads();
        #pragma unroll
        for (int kk2 = 0; kk2 < 32; kk2 += 8) {
            int r = wid * 16 + lr;
            uint32_t ah[4], al[4];
            ah[0] = Ah[r * 36 + kk2 + lc];
            ah[1] = Ah[(r + 8) * 36 + kk2 + lc];
            ah[2] = Ah[r * 36 + kk2 + lc + 4];
            ah[3] = Ah[(r + 8) * 36 + kk2 + lc + 4];
            al[0] = Al[r * 36 + kk2 + lc];
            al[1] = Al[(r + 8) * 36 + kk2 + lc];
            al[2] = Al[r * 36 + kk2 + lc + 4];
            al[3] = Al[(r + 8) * 36 + kk2 + lc + 4];
            #pragma unroll
            for (int jn = 0; jn < 8; jn++) {
                int n = jn * 8 + lr;
                uint32_t bhf[2], blf[2];
                bhf[0] = Bh[n * 36 + kk2 + lc];
                bhf[1] = Bh[n * 36 + kk2 + lc + 4];
                blf[0] = Bl[n * 36 + kk2 + lc];
                blf[1] = Bl[n * 36 + kk2 + lc + 4];
                mma_bf16(acc[jn], ah, blf);
                mma_bf16(acc[jn], al, bhf);
                mma_bf16(acc[jn], ah, bhf);
            }
        }
        __syncthreads();
    }

    float* base = states + (long long)(bh * NC + ck) * 8192;
    int n0 = wid * 16 + lr;
    #pragma unroll
    for (int jn = 0; jn < 8; jn++) {
        int p = jn * 8 + 2 * lc;
        float* p0 = base + n0 * 64 + p;
        p0[0] = acc[jn][0];
        p0[1] = acc[jn][1];
        float* p1 = base + (n0 + 8) * 64 + p;
        p1[0] = acc[jn][2];
        p1[1] = acc[jn][3];
    }
}

// ---------------- tensor-core SSD output ----------------
__global__ __launch_bounds__(256)
void y_tc_kernel(const float* __restrict__ xbc, const float* __restrict__ xdt,
                 const float* __restrict__ Acs, const float* __restrict__ CB,
                 const float* __restrict__ Sprev, const float* __restrict__ Dv,
                 float* __restrict__ Y)
{
    extern __shared__ uint32_t dyny[];
    uint32_t* Ah = dyny;
    uint32_t* Al = Ah + 128 * 36;
    uint32_t* Bh = Al + 128 * 36;
    uint32_t* Bl = Bh + 64 * 36;
    float* acs_sh = (float*)(Bl + 64 * 36);
    float* eA_sh  = acs_sh + 256;
    __nv_bfloat16* Ah_e = (__nv_bfloat16*)Ah;
    __nv_bfloat16* Al_e = (__nv_bfloat16*)Al;
    __nv_bfloat16* Bh_e = (__nv_bfloat16*)Bh;
    __nv_bfloat16* Bl_e = (__nv_bfloat16*)Bl;

    int blk = blockIdx.x;
    int lh = blk & 1;
    int ck = (blk >> 1) & 7;
    int bh = blk >> 4;
    int h = bh & 31, b = bh >> 5;
    int tid = threadIdx.x;
    int wid = tid >> 5, lane = tid & 31;
    int lr = lane >> 2, lc = lane & 3;
    long long rowbase = (long long)(b * L_ + ck * 256);

    acs_sh[tid] = Acs[(long long)bh * L_ + ck * 256 + tid];
    __syncthreads();
    if (tid < 128) eA_sh[tid] = __expf(acs_sh[lh * 128 + tid]);

    float acc[8][4];
    #pragma unroll
    for (int j = 0; j < 8; j++)
        #pragma unroll
        for (int r = 0; r < 4; r++) acc[j][r] = 0.f;

    const float* cbp = CB + (long long)(b * NC + ck) * (CH * CH);
    int ndiag = (lh == 0) ? 2 : 4;

    for (int kt = 0; kt < ndiag + 2; kt++) {
        if (kt < ndiag) {
            int s0 = kt * 64;
            #pragma unroll
            for (int i = 0; i < 32; i++) {
                int idx = tid + i * 256;
                int l = idx & 127;
                int s = idx >> 7;
                int gl = lh * 128 + l;
                int gs = s0 + s;
                float v = 0.f;
                if (gs <= gl) v = cbp[gs * 256 + gl] * __expf(acs_sh[gl] - acs_sh[gs]);
                __nv_bfloat16 hi, lo; split_bf16(v, hi, lo);
                Ah_e[l * 72 + s] = hi;
                Al_e[l * 72 + s] = lo;
            }
            #pragma unroll
            for (int i = 0; i < 16; i++) {
                int idx = tid + i * 256;
                int p = idx & 63;
                int s = idx >> 6;
                float v = xdt[(rowbase + s0 + s) * DI + h * 64 + p];
                __nv_bfloat16 hi, lo; split_bf16(v, hi, lo);
                Bh_e[p * 72 + s] = hi;
                Bl_e[p * 72 + s] = lo;
            }
        } else {
            int n0 = (kt - ndiag) * 64;
            #pragma unroll
            for (int i = 0; i < 32; i++) {
                int idx = tid + i * 256;
                int c = idx & 63;
                int l = idx >> 6;
                float v = xbc[(rowbase + lh * 128 + l) * CONVD + DI + NST + n0 + c] * eA_sh[l];
                __nv_bfloat16 hi, lo; split_bf16(v, hi, lo);
                Ah_e[l * 72 + c] = hi;
                Al_e[l * 72 + c] = lo;
            }
            #pragma unroll
            for (int i = 0; i < 16; i++) {
                int idx = tid + i * 256;
                int p = idx & 63;
                int c = idx >> 6;
                float v = Sprev[(long long)(bh * NC + ck) * 8192 + (n0 + c) * 64 + p];
                __nv_bfloat16 hi, lo; split_bf16(v, hi, lo);
                Bh_e[p * 72 + c] = hi;
                Bl_e[p * 72 + c] = lo;
            }
        }
        __syncthreads();
        #pragma unroll
        for (int kk2 = 0; kk2 < 32; kk2 += 8) {
            int r = wid * 16 + lr;
            uint32_t ah[4], al[4];
            ah[0] = Ah[r * 36 + kk2 + lc];
            ah[1] = Ah[(r + 8) * 36 + kk2 + lc];
            ah[2] = Ah[r * 36 + kk2 + lc + 4];
            ah[3] = Ah[(r + 8) * 36 + kk2 + lc + 4];
            al[0] = Al[r * 36 + kk2 + lc];
            al[1] = Al[(r + 8) * 36 + kk2 + lc];
            al[2] = Al[r * 36 + kk2 + lc + 4];
            al[3] = Al[(r + 8) * 36 + kk2 + lc + 4];
            #pragma unroll
            for (int jn = 0; jn < 8; jn++) {
                int n = jn * 8 + lr;
                uint32_t bhf[2], blf[2];
                bhf[0] = Bh[n * 36 + kk2 + lc];
                bhf[1] = Bh[n * 36 + kk2 + lc + 4];
                blf[0] = Bl[n * 36 + kk2 + lc];
                blf[1] = Bl[n * 36 + kk2 + lc + 4];
                mma_bf16(acc[jn], ah, blf);
                mma_bf16(acc[jn], al, bhf);
                mma_bf16(acc[jn], ah, bhf);
            }
        }
        __syncthreads();
    }

    float Dh = Dv[h];
    int r0 = wid * 16 + lr;
    #pragma unroll
    for (int jn = 0; jn < 8; jn++) {
        int col = jn * 8 + 2 * lc;
        long long grow0 = rowbase + lh * 128 + r0;
        const float* xs0 = xbc + grow0 * CONVD + h * 64 + col;
        float* yp0 = Y + grow0 * DI + h * 64 + col;
        yp0[0] = acc[jn][0] + Dh * xs0[0];
        yp0[1] = acc[jn][1] + Dh * xs0[1];
        long long grow1 = grow0 + 8;
        const float* xs1 = xbc + grow1 * CONVD + h * 64 + col;
        float* yp1 = Y + grow1 * DI + h * 64 + col;
        yp1[0] = acc[jn][2] + Dh * xs1[0];
        yp1[1] = acc[jn][3] + Dh * xs1[1];
    }
}

// ---------------- rmsnorm (float4) ----------------
__global__ void rmsnorm_kernel(const float* __restrict__ a, const float* __restrict__ b,
                               float alpha, const float* __restrict__ w,
                               float* __restrict__ out, int D)
{
    long long row = blockIdx.x;
    const float4* ap = (const float4*)(a + row * D);
    const float4* bp = b ? (const float4*)(b + row * D) : nullptr;
    int per = D >> 10;
    float4 v[2];
    float ss = 0.f;
    for (int j = 0; j < per; j++) {
        int i = threadIdx.x + j * 256;
        float4 x = ap[i];
        if (bp) {
            float4 y = bp[i];
            x.x += alpha * y.x; x.y += alpha * y.y;
            x.z += alpha * y.z; x.w += alpha * y.w;
        }
        v[j] = x;
        ss += x.x * x.x + x.y * x.y + x.z * x.z + x.w * x.w;
    }
    __shared__ float red[256];
    red[threadIdx.x] = ss;
    __syncthreads();
    for (int off = 128; off; off >>= 1) {
        if (threadIdx.x < off) red[threadIdx.x] += red[threadIdx.x + off];
        __syncthreads();
    }
    float scale = rsqrtf(red[0] / D + EPSN);
    const float4* wp = (const float4*)w;
    float4* op = (float4*)(out + row * D);
    for (int j = 0; j < per; j++) {
        int i = threadIdx.x + j * 256;
        float4 x = v[j], ww = wp[i];
        float4 r;
        r.x = x.x * scale * ww.x; r.y = x.y * scale * ww.y;
        r.z = x.z * scale * ww.z; r.w = x.w * scale * ww.w;
        op[i] = r;
    }
}

// ---------------- gated rmsnorm (float4), D=2048 ----------------
__global__ void gated_rmsnorm_kernel(const float* __restrict__ y, const float* __restrict__ z,
                                     int ldz, const float* __restrict__ w,
                                     float* __restrict__ out)
{
    long long row = blockIdx.x;
    const float4* yp = (const float4*)(y + row * DI);
    const float4* zp = (const float4*)(z + row * (long long)ldz);
    float4 v[2];
    float ss = 0.f;
    #pragma unroll
    for (int j = 0; j < 2; j++) {
        int i = threadIdx.x + j * 256;
        float4 yv = yp[i], zv = zp[i];
        float4 x;
        x.x = yv.x * silu_f(zv.x); x.y = yv.y * silu_f(zv.y);
        x.z = yv.z * silu_f(zv.z); x.w = yv.w * silu_f(zv.w);
        v[j] = x;
        ss += x.x * x.x + x.y * x.y + x.z * x.z + x.w * x.w;
    }
    __shared__ float red[256];
    red[threadIdx.x] = ss;
    __syncthreads();
    for (int off = 128; off; off >>= 1) {
        if (threadIdx.x < off) red[threadIdx.x] += red[threadIdx.x + off];
        __syncthreads();
    }
    float scale = rsqrtf(red[0] / DI + EPSN);
    const float4* wp = (const float4*)w;
    float4* op = (float4*)(out + row * DI);
    #pragma unroll
    for (int j = 0; j < 2; j++) {
        int i = threadIdx.x + j * 256;
        float4 x = v[j], ww = wp[i];
        float4 r;
        r.x = x.x * scale * ww.x; r.y = x.y * scale * ww.y;
        r.z = x.z * scale * ww.z; r.w = x.w * scale * ww.w;
        op[i] = r;
    }
}

// ---------------- depthwise causal conv (k=4) + bias + silu, float4 over channels ----------------
__global__ void conv_kernel(const float* __restrict__ zx, const float* __restrict__ cw,
                            const float* __restrict__ cb, float* __restrict__ xbc)
{
    int idx = blockIdx.x * 256 + threadIdx.x;
    if (idx >= ROWS * (CONVD / 4)) return;
    int c4 = (idx % (CONVD / 4)) << 2;
    int row = idx / (CONVD / 4);
    int t = row % L_;
    int b = row / L_;
    float4 s = *(const float4*)(cb + c4);
    float4 w0 = *(const float4*)(cw + (c4 + 0) * 4);
    float4 w1 = *(const float4*)(cw + (c4 + 1) * 4);
    float4 w2 = *(const float4*)(cw + (c4 + 2) * 4);
    float4 w3 = *(const float4*)(cw + (c4 + 3) * 4);
    const float* wa0 = (const float*)&w0;
    const float* wa1 = (const float*)&w1;
    const float* wa2 = (const float*)&w2;
    const float* wa3 = (const float*)&w3;
    #pragma unroll
    for (int k = 0; k < 4; k++) {
        int tt = t - 3 + k;
        if (tt >= 0) {
            float4 z = *(const float4*)(zx + ((long long)(b * L_ + tt) * DINP) + DI + c4);
            s.x += z.x * wa0[k];
            s.y += z.y * wa1[k];
            s.z += z.z * wa2[k];
            s.w += z.w * wa3[k];
        }
    }
    float4 r;
    r.x = silu_f(s.x); r.y = silu_f(s.y);
    r.z = silu_f(s.z); r.w = silu_f(s.w);
    *(float4*)(xbc + (long long)row * CONVD + c4) = r;
}

// ---------------- dt (softplus) and xdt = xs*dt, float4; dtb written TRANSPOSED ----------------
// dtb_t layout: [(b*HS + h)][L]  (coalesced for cumsum)
__global__ void dtxdt_kernel(const float* __restrict__ zx, const float* __restrict__ xbc,
                             const float* __restrict__ dt_bias,
                             float* __restrict__ dtb_t, float* __restrict__ xdt)
{
    int idx = blockIdx.x * 256 + threadIdx.x;
    if (idx >= ROWS * (DI / 4)) return;
    int c = (idx % (DI / 4)) << 2;
    long long row = idx / (DI / 4);
    int h = c >> 6;
    float raw = zx[row * DINP + DI + CONVD + h] + dt_bias[h];
    float d = softplus_f(raw);
    float4 xv = *(const float4*)(xbc + row * CONVD + c);
    float4 r;
    r.x = xv.x * d; r.y = xv.y * d; r.z = xv.z * d; r.w = xv.w * d;
    *(float4*)(xdt + row * DI + c) = r;
    if ((c & 63) == 0) {
        int b = (int)(row / L_);
        int t = (int)(row % L_);
        dtb_t[(long long)(b * HS + h) * L_ + t] = d;
    }
}

// ---------------- per-chunk inclusive cumsum (warp-shuffle scan, coalesced dtb_t) ----------------
__global__ void cumsum_kernel(const float* __restrict__ dtb_t, const float* __restrict__ A_log,
                              float* __restrict__ Acs)
{
    __shared__ float wsum[8];
    int blk = blockIdx.x;
    int ck = blk & 7;
    int bh = blk >> 3;
    int h = bh & 31;
    int l = threadIdx.x;
    int lane = l & 31, wrp = l >> 5;
    float a = -__expf(A_log[h]) * dtb_t[(long long)bh * L_ + ck * 256 + l];
    // warp inclusive scan
    #pragma unroll
    for (int off = 1; off < 32; off <<= 1) {
        float t = __shfl_up_sync(0xffffffffu, a, off);
        if (lane >= off) a += t;
    }
    if (lane == 31) wsum[wrp] = a;
    __syncthreads();
    float pre = 0.f;
    #pragma unroll
    for (int wv = 0; wv < 8; wv++) {
        float sv = wsum[wv];
        pre += (wv < wrp) ? sv : 0.f;
    }
    Acs[(long long)bh * L_ + ck * 256 + l] = a + pre;
}

// ---------------- inter-chunk scan (float4, 8x parallel) ----------------
// grid = B_*HS*8; block (bh, seg) owns float4s [seg*256 + tid] of the 2048-float4 state.
__global__ void scan_kernel(const float* __restrict__ states, const float* __restrict__ Acs,
                            float* __restrict__ Sprev)
{
    __shared__ float dc_sh[NC];
    int g = blockIdx.x;
    int seg = g & 7;
    int bh = g >> 3;
    int tid = threadIdx.x;
    if (tid < NC) dc_sh[tid] = __expf(Acs[(long long)bh * L_ + tid * 256 + 255]);
    __syncthreads();
    int off4 = seg * 256 + tid;           // float4 index within 2048
    float4 S = make_float4(0.f, 0.f, 0.f, 0.f);
    for (int c = 0; c < NC; c++) {
        float dc = dc_sh[c];
        long long base = ((long long)(bh * NC + c) * 8192) >> 2;  // float4 units
        const float4* sp = (const float4*)states + base + off4;
        float4* pp = (float4*)Sprev + base + off4;
        *pp = S;
        float4 sv = *sp;
        S.x = S.x * dc + sv.x;
        S.y = S.y * dc + sv.y;
        S.z = S.z * dc + sv.z;
        S.w = S.w * dc + sv.w;
    }
}

// ---------------- swiglu (float4) ----------------
__global__ void swiglu_kernel(const float* __restrict__ y, float* __restrict__ ff)
{
    int idx = blockIdx.x * 256 + threadIdx.x;
    if (idx >= ROWS * (DFF / 4)) return;
    long long row = idx / (DFF / 4);
    int f4 = idx % (DFF / 4);
    const float4* yp = (const float4*)(y + row * (2 * DFF));
    float4 a = yp[f4];
    float4 g = yp[f4 + DFF / 4];
    float4 r;
    r.x = a.x * silu_f(g.x); r.y = a.y * silu_f(g.y);
    r.z = a.z * silu_f(g.z); r.w = a.w * silu_f(g.w);
    *(float4*)(ff + row * DFF + f4 * 4) = r;
}

// ---------------- host launcher ----------------
#define SSD_SMEM 57344

extern "C" void kernel_launch(void* const* d_in, const int* in_sizes, int n_in,
                              void* d_out, int out_size)
{
    const float* x_in       = (const float*)d_in[0];
    const float* attn_norm  = (const float*)d_in[1];
    const float* Wqkv       = (const float*)d_in[2];
    const float* Wqkv_b     = (const float*)d_in[3];
    const float* attn_out_w = (const float*)d_in[4];
    const float* attn_out_b = (const float*)d_in[5];
    const float* normf_w    = (const float*)d_in[6];
    const float* m_in_w     = (const float*)d_in[7];
    const float* m_conv_w   = (const float*)d_in[8];
    const float* m_conv_b   = (const float*)d_in[9];
    const float* m_dt_bias  = (const float*)d_in[10];
    const float* m_A_log    = (const float*)d_in[11];
    const float* m_D        = (const float*)d_in[12];
    const float* m_norm_w   = (const float*)d_in[13];
    const float* m_out_w    = (const float*)d_in[14];
    const float* fc1_w      = (const float*)d_in[15];
    const float* fc2_w      = (const float*)d_in[16];
    const float* final_norm = (const float*)d_in[17];
    float* out = (float*)d_out;

    float* scr = nullptr;
    cudaGetSymbolAddress((void**)&scr, g_scratch);

    cudaFuncSetAttribute(states_tc_kernel, cudaFuncAttributeMaxDynamicSharedMemorySize, SSD_SMEM);
    cudaFuncSetAttribute(y_tc_kernel, cudaFuncAttributeMaxDynamicSharedMemorySize, SSD_SMEM);

    float* bBIG = scr + OFF_BIG;
    float* bH   = scr + OFF_H;
    float* bO   = scr + OFF_O;
    float* bX   = scr + OFF_X;
    float* bXBC = scr + OFF_XBC;
    float* bDT  = scr + OFF_DT;
    float* bXDT = scr + OFF_XDT;
    float* bACS = scr + OFF_ACS;
    float* bCB  = scr + OFF_CB;
    float* bSTA = scr + OFF_STA;
    float* bSPR = scr + OFF_SPR;
    float* bY   = scr + OFF_Y;
    float* bFF  = scr + OFF_FF;

    // ---- attention block ----
    rmsnorm_kernel<<<ROWS, 256>>>(x_in, nullptr, 0.f, attn_norm, bH, DM);
    gemm_tc<<<dim3(3072/128, ROWS/128, 1), 256>>>(bH, Wqkv, Wqkv_b, bBIG,
        ROWS, 3072, DM, DM, DM, 3072, 0, 0, 0);
    attn_tc_kernel<<<dim3(L_/128, B_*NH), 256>>>(bBIG, bO);
    gemm_tc<<<dim3(DM/128, ROWS/128, 1), 256>>>(bO, attn_out_w, attn_out_b, bH,
        ROWS, DM, DM, DM, DM, DM, 0, 0, 0);
    rmsnorm_kernel<<<ROWS, 256>>>(bH, x_in, 1.f, normf_w, bX, DM);

    // ---- mamba layers ----
    for (int i = 0; i < 4; i++) {
        const float* in_w   = m_in_w   + (long long)i * DINP * DM;
        const float* conv_w = m_conv_w + (long long)i * CONVD * 4;
        const float* conv_b = m_conv_b + (long long)i * CONVD;
        const float* dtbias = m_dt_bias+ (long long)i * HS;
        const float* Alog   = m_A_log  + (long long)i * HS;
        const float* Dv     = m_D      + (long long)i * HS;
        const float* nw     = m_norm_w + (long long)i * DI;
        const float* ow     = m_out_w  + (long long)i * DM * DI;

        gemm_tc<<<dim3((DINP+127)/128, ROWS/128, 1), 256>>>(bX, in_w, nullptr, bBIG,
            ROWS, DINP, DM, DM, DM, DINP, 0, 0, 0);
        conv_kernel<<<(ROWS*(CONVD/4))/256, 256>>>(bBIG, conv_w, conv_b, bXBC);
        dtxdt_kernel<<<(ROWS*(DI/4))/256, 256>>>(bBIG, bXBC, dtbias, bDT, bXDT);
        cumsum_kernel<<<B_*HS*NC, 256>>>(bDT, Alog, bACS);
        gemm_tc<<<dim3(2, 2, B_*NC), 256>>>(
            bXBC + DI, bXBC + DI + NST, nullptr, bCB,
            CH, CH, NST, CONVD, CONVD, CH,
            (long long)CH * CONVD, (long long)CH * CONVD, (long long)CH * CH);
        states_tc_kernel<<<B_*HS*NC, 256, SSD_SMEM>>>(bXBC, bXDT, bACS, bSTA);
        scan_kernel<<<B_*HS*8, 256>>>(bSTA, bACS, bSPR);
        y_tc_kernel<<<B_*HS*NC*2, 256, SSD_SMEM>>>(bXBC, bXDT, bACS, bCB, bSPR, Dv, bY);
        gated_rmsnorm_kernel<<<ROWS, 256>>>(bY, bBIG, DINP, nw, bY);
        gemm_tc<<<dim3(DM/128, ROWS/128, 1), 256>>>(bY, ow, nullptr, bX,
            ROWS, DM, DI, DI, DI, DM, 0, 0, 0);
    }

    // ---- MLP + final norm ----
    gemm_tc<<<dim3((2*DFF)/128, ROWS/128, 1), 256>>>(bX, fc1_w, nullptr, bBIG,
        ROWS, 2*DFF, DM, DM, DM, 2*DFF, 0, 0, 0);
    swiglu_kernel<<<(ROWS*(DFF/4))/256, 256>>>(bBIG, bFF);
    gemm_tc<<<dim3(DM/128, ROWS/128, 1), 256>>>(bFF, fc2_w, nullptr, bH,
        ROWS, DM, DFF, DFF, DFF, DM, 0, 0, 0);
    rmsnorm_kernel<<<ROWS, 256>>>(bH, bX, ALPHA, final_norm, out, DM);
}

// round 13
// speedup vs baseline: 1.3878x; 1.0189x over previous
#include <cuda_runtime.h>
#include <cuda_bf16.h>
#include <math.h>
#include <stdint.h>

// ---------------- constants ----------------
#define B_   2
#define L_   2048
#define DM   1024          // D_MODEL
#define NH   16            // NHEAD
#define HD   64            // HD_ATT
#define DI   2048          // D_INNER
#define HS   32            // H_SSM
#define P_   64            // HEADDIM
#define NST  128           // D_STATE
#define CONVD 2304         // CONV_DIM
#define DINP 4384          // D_IN_PROJ
#define CH   256           // CHUNK
#define NC   8             // L/CHUNK
#define DFF  2048
#define ALPHA 1.68f
#define EPSN 1e-5f

#define ROWS (B_*L_)       // 4096

// ---------------- scratch ----------------
static const long long SZ_BIG  = (long long)ROWS*DINP;
static const long long SZ_HB   = (long long)ROWS*DM;
static const long long SZ_XBC  = (long long)ROWS*CONVD;
static const long long SZ_DT   = (long long)ROWS*HS;
static const long long SZ_XDT  = (long long)ROWS*DI;
static const long long SZ_ACS  = (long long)B_*HS*L_;
static const long long SZ_CB   = (long long)B_*NC*CH*CH;
static const long long SZ_ST   = (long long)B_*HS*NC*NST*P_;
static const long long SZ_Y    = (long long)ROWS*DI;

static const long long OFF_BIG = 0;
static const long long OFF_H   = OFF_BIG + SZ_BIG;
static const long long OFF_O   = OFF_H   + SZ_HB;
static const long long OFF_X   = OFF_O   + SZ_HB;
static const long long OFF_XBC = OFF_X   + SZ_HB;
static const long long OFF_DT  = OFF_XBC + SZ_XBC;
static const long long OFF_XDT = OFF_DT  + SZ_DT;
static const long long OFF_ACS = OFF_XDT + SZ_XDT;
static const long long OFF_CB  = OFF_ACS + SZ_ACS;
static const long long OFF_STA = OFF_CB  + SZ_CB;
static const long long OFF_SPR = OFF_STA + SZ_ST;
static const long long OFF_Y   = OFF_SPR + SZ_ST;
static const long long OFF_FF  = OFF_Y   + SZ_Y;
static const long long TOTALF  = OFF_FF  + SZ_Y;

__device__ float g_scratch[74842112]; // == TOTALF floats (~300 MB)

// ---------------- helpers ----------------
__device__ __forceinline__ float silu_f(float x) {
    return x / (1.f + __expf(-x));
}
__device__ __forceinline__ float softplus_f(float x) {
    return (x > 20.f) ? x : log1pf(__expf(x));
}
__device__ __forceinline__ void split_bf16(float x, __nv_bfloat16& hi, __nv_bfloat16& lo) {
    hi = __float2bfloat16_rn(x);
    lo = __float2bfloat16_rn(x - __bfloat162float(hi));
}
__device__ __forceinline__ uint32_t pack2(__nv_bfloat16 a, __nv_bfloat16 b) {
    __nv_bfloat162 h;
    h.x = a; h.y = b;
    return *(uint32_t*)&h;
}
__device__ __forceinline__ void mma_bf16(float* c, const uint32_t* a, const uint32_t* b) {
    asm volatile(
        "mma.sync.aligned.m16n8k16.row.col.f32.bf16.bf16.f32 "
        "{%0,%1,%2,%3}, {%4,%5,%6,%7}, {%8,%9}, {%0,%1,%2,%3};"
        : "+f"(c[0]), "+f"(c[1]), "+f"(c[2]), "+f"(c[3])
        : "r"(a[0]), "r"(a[1]), "r"(a[2]), "r"(a[3]), "r"(b[0]), "r"(b[1]));
}

// ---------------- bf16x2 split tensor-core NT GEMM, register-prefetch pipelined ----------------
// Measured-best configuration (R6): static 40KB SMEM, K-tile 32, register LDG prefetch.
#define SSTR 20
__global__ __launch_bounds__(256, 2)
void gemm_tc(const float* __restrict__ A, const float* __restrict__ W,
             const float* __restrict__ bias, float* __restrict__ C,
             int M, int N, int K, int lda, int ldw, int ldc,
             long long sA, long long sW, long long sC)
{
    A += (long long)blockIdx.z * sA;
    W += (long long)blockIdx.z * sW;
    C += (long long)blockIdx.z * sC;

    __shared__ uint32_t Ahi[128][SSTR];
    __shared__ uint32_t Alo[128][SSTR];
    __shared__ uint32_t Bhi[128][SSTR];
    __shared__ uint32_t Blo[128][SSTR];

    int bm = blockIdx.y * 128, bn = blockIdx.x * 128;
    int tid = threadIdx.x;
    int wid = tid >> 5, lane = tid & 31;
    int wm = (wid >> 2) * 64;
    int wn = (wid & 3) * 32;
    int lr = lane >> 2;
    int lc = lane & 3;

    int sr = tid >> 3;
    int sc4 = (tid & 7) << 2;
    int sc2 = sc4 >> 1;

    float acc[4][4][4];
    #pragma unroll
    for (int i = 0; i < 4; i++)
        #pragma unroll
        for (int j = 0; j < 4; j++)
            #pragma unroll
            for (int r = 0; r < 4; r++) acc[i][j][r] = 0.f;

    float4 pa[4], pw[4];
    #pragma unroll
    for (int i = 0; i < 4; i++) {
        int r = sr + i * 32;
        pa[i] = *(const float4*)(A + (long long)(bm + r) * lda + sc4);
        if (bn + r < N) pw[i] = *(const float4*)(W + (long long)(bn + r) * ldw + sc4);
        else            pw[i] = make_float4(0.f, 0.f, 0.f, 0.f);
    }

    for (int k0 = 0; k0 < K; k0 += 32) {
        #pragma unroll
        for (int i = 0; i < 4; i++) {
            int r = sr + i * 32;
            __nv_bfloat16 h0,l0,h1,l1,h2,l2,h3,l3;
            split_bf16(pa[i].x, h0, l0); split_bf16(pa[i].y, h1, l1);
            split_bf16(pa[i].z, h2, l2); split_bf16(pa[i].w, h3, l3);
            Ahi[r][sc2]     = pack2(h0, h1);
            Ahi[r][sc2 + 1] = pack2(h2, h3);
            Alo[r][sc2]     = pack2(l0, l1);
            Alo[r][sc2 + 1] = pack2(l2, l3);
            split_bf16(pw[i].x, h0, l0); split_bf16(pw[i].y, h1, l1);
            split_bf16(pw[i].z, h2, l2); split_bf16(pw[i].w, h3, l3);
            Bhi[r][sc2]     = pack2(h0, h1);
            Bhi[r][sc2 + 1] = pack2(h2, h3);
            Blo[r][sc2]     = pack2(l0, l1);
            Blo[r][sc2 + 1] = pack2(l2, l3);
        }
        __syncthreads();

        if (k0 + 32 < K) {
            int kn = k0 + 32;
            #pragma unroll
            for (int i = 0; i < 4; i++) {
                int r = sr + i * 32;
                pa[i] = *(const float4*)(A + (long long)(bm + r) * lda + kn + sc4);
                if (bn + r < N) pw[i] = *(const float4*)(W + (long long)(bn + r) * ldw + kn + sc4);
                else            pw[i] = make_float4(0.f, 0.f, 0.f, 0.f);
            }
        }

        #pragma unroll
        for (int kk2 = 0; kk2 < 16; kk2 += 8) {
            uint32_t bhf[4][2], blf[4][2];
            #pragma unroll
            for (int jn = 0; jn < 4; jn++) {
                int cdx = wn + jn * 8 + lr;
                bhf[jn][0] = Bhi[cdx][kk2 + lc];
                bhf[jn][1] = Bhi[cdx][kk2 + lc + 4];
                blf[jn][0] = Blo[cdx][kk2 + lc];
                blf[jn][1] = Blo[cdx][kk2 + lc + 4];
            }
            #pragma unroll
            for (int im = 0; im < 4; im++) {
                int r = wm + im * 16 + lr;
                uint32_t ah[4], al[4];
                ah[0] = Ahi[r][kk2 + lc];
                ah[1] = Ahi[r + 8][kk2 + lc];
                ah[2] = Ahi[r][kk2 + lc + 4];
                ah[3] = Ahi[r + 8][kk2 + lc + 4];
                al[0] = Alo[r][kk2 + lc];
                al[1] = Alo[r + 8][kk2 + lc];
                al[2] = Alo[r][kk2 + lc + 4];
                al[3] = Alo[r + 8][kk2 + lc + 4];
                #pragma unroll
                for (int jn = 0; jn < 4; jn++) {
                    mma_bf16(acc[im][jn], ah, blf[jn]);
                    mma_bf16(acc[im][jn], al, bhf[jn]);
                    mma_bf16(acc[im][jn], ah, bhf[jn]);
                }
            }
        }
        __syncthreads();
    }

    #pragma unroll
    for (int im = 0; im < 4; im++) {
        #pragma unroll
        for (int jn = 0; jn < 4; jn++) {
            int gm = bm + wm + im * 16 + lr;
            int gc = bn + wn + jn * 8 + 2 * lc;
            if (gc < N) {
                float b0 = bias ? bias[gc] : 0.f;
                float b1 = bias ? bias[gc + 1] : 0.f;
                float* p0 = C + (long long)gm * ldc + gc;
                p0[0] = acc[im][jn][0] + b0;
                p0[1] = acc[im][jn][1] + b1;
                float* p1 = C + (long long)(gm + 8) * ldc + gc;
                p1[0] = acc[im][jn][2] + b0;
                p1[1] = acc[im][jn][3] + b1;
            }
        }
    }
}

// ---------------- tensor-core flash attention (non-causal), split-bf16 ----------------
// 512 threads = 16 warps; block covers 256 q-rows, halving K/V staging redundancy.
__global__ __launch_bounds__(512)
void attn_tc_kernel(const float* __restrict__ qkv, float* __restrict__ o)
{
    __shared__ uint32_t Khi[64][36];
    __shared__ uint32_t Klo[64][36];
    __shared__ __nv_bfloat16 Vthi[64][72];
    __shared__ __nv_bfloat16 Vtlo[64][72];

    int bh = blockIdx.y;
    int b = bh >> 4, h = bh & 15;
    int tid = threadIdx.x;
    int wid = tid >> 5, lane = tid & 31;
    int lr = lane >> 2, lc = lane & 3;
    int qrow0 = blockIdx.x * 256 + wid * 16;

    uint32_t qhi[4][4], qlo[4][4];
    {
        const float* qp = qkv + (long long)(b * L_) * 3072 + h * 64;
        #pragma unroll
        for (int kc = 0; kc < 4; kc++) {
            #pragma unroll
            for (int half = 0; half < 2; half++) {
                int col = kc * 16 + 2 * lc + half * 8;
                float2 v0 = *(const float2*)(qp + (long long)(qrow0 + lr) * 3072 + col);
                float2 v1 = *(const float2*)(qp + (long long)(qrow0 + lr + 8) * 3072 + col);
                __nv_bfloat16 h0,l0,h1,l1;
                split_bf16(v0.x * 0.125f, h0, l0); split_bf16(v0.y * 0.125f, h1, l1);
                qhi[kc][half * 2]     = pack2(h0, h1);
                qlo[kc][half * 2]     = pack2(l0, l1);
                split_bf16(v1.x * 0.125f, h0, l0); split_bf16(v1.y * 0.125f, h1, l1);
                qhi[kc][half * 2 + 1] = pack2(h0, h1);
                qlo[kc][half * 2 + 1] = pack2(l0, l1);
            }
        }
    }

    float o_acc[8][4];
    #pragma unroll
    for (int j = 0; j < 8; j++)
        #pragma unroll
        for (int r = 0; r < 4; r++) o_acc[j][r] = 0.f;
    float mrow0 = -1e30f, mrow1 = -1e30f;
    float lrow0 = 0.f, lrow1 = 0.f;

    for (int kt = 0; kt < L_ / 64; kt++) {
        const float* kb = qkv + (long long)(b * L_ + kt * 64) * 3072 + 1024 + h * 64;
        const float* vb = kb + 1024;
        #pragma unroll
        for (int i = 0; i < 2; i++) {
            int idx = tid + i * 512;
            int r = idx >> 4, c4 = (idx & 15) << 2;
            float4 kv = *(const float4*)(kb + (long long)r * 3072 + c4);
            __nv_bfloat16 h0,l0,h1,l1,h2,l2,h3,l3;
            split_bf16(kv.x, h0, l0); split_bf16(kv.y, h1, l1);
            split_bf16(kv.z, h2, l2); split_bf16(kv.w, h3, l3);
            int c2 = c4 >> 1;
            Khi[r][c2]     = pack2(h0, h1);
            Khi[r][c2 + 1] = pack2(h2, h3);
            Klo[r][c2]     = pack2(l0, l1);
            Klo[r][c2 + 1] = pack2(l2, l3);
            float4 vv = *(const float4*)(vb + (long long)r * 3072 + c4);
            __nv_bfloat16 vh, vl;
            split_bf16(vv.x, vh, vl); Vthi[c4 + 0][r] = vh; Vtlo[c4 + 0][r] = vl;
            split_bf16(vv.y, vh, vl); Vthi[c4 + 1][r] = vh; Vtlo[c4 + 1][r] = vl;
            split_bf16(vv.z, vh, vl); Vthi[c4 + 2][r] = vh; Vtlo[c4 + 2][r] = vl;
            split_bf16(vv.w, vh, vl); Vthi[c4 + 3][r] = vh; Vtlo[c4 + 3][r] = vl;
        }
        __syncthreads();

        float s[8][4];
        #pragma unroll
        for (int j = 0; j < 8; j++)
            #pragma unroll
            for (int r = 0; r < 4; r++) s[j][r] = 0.f;
        #pragma unroll
        for (int kc = 0; kc < 4; kc++) {
            #pragma unroll
            for (int jn = 0; jn < 8; jn++) {
                int n = jn * 8 + lr;
                uint32_t bhf[2], blf[2];
                bhf[0] = Khi[n][kc * 8 + lc];
                bhf[1] = Khi[n][kc * 8 + lc + 4];
                blf[0] = Klo[n][kc * 8 + lc];
                blf[1] = Klo[n][kc * 8 + lc + 4];
                mma_bf16(s[jn], qhi[kc], blf);
                mma_bf16(s[jn], qlo[kc], bhf);
                mma_bf16(s[jn], qhi[kc], bhf);
            }
        }

        float t0 = -1e30f, t1 = -1e30f;
        #pragma unroll
        for (int jn = 0; jn < 8; jn++) {
            t0 = fmaxf(t0, fmaxf(s[jn][0], s[jn][1]));
            t1 = fmaxf(t1, fmaxf(s[jn][2], s[jn][3]));
        }
        t0 = fmaxf(t0, __shfl_xor_sync(0xffffffffu, t0, 1));
        t0 = fmaxf(t0, __shfl_xor_sync(0xffffffffu, t0, 2));
        t1 = fmaxf(t1, __shfl_xor_sync(0xffffffffu, t1, 1));
        t1 = fmaxf(t1, __shfl_xor_sync(0xffffffffu, t1, 2));
        float m0n = fmaxf(mrow0, t0), m1n = fmaxf(mrow1, t1);
        float sc0 = __expf(mrow0 - m0n), sc1 = __expf(mrow1 - m1n);
        mrow0 = m0n; mrow1 = m1n;
        lrow0 *= sc0; lrow1 *= sc1;
        #pragma unroll
        for (int j = 0; j < 8; j++) {
            o_acc[j][0] *= sc0; o_acc[j][1] *= sc0;
            o_acc[j][2] *= sc1; o_acc[j][3] *= sc1;
        }

        uint32_t phi[4][4], plo[4][4];
        #pragma unroll
        for (int jn = 0; jn < 8; jn++) {
            float p0 = __expf(s[jn][0] - m0n);
            float p1 = __expf(s[jn][1] - m0n);
            float p2 = __expf(s[jn][2] - m1n);
            float p3 = __expf(s[jn][3] - m1n);
            lrow0 += p0 + p1;
            lrow1 += p2 + p3;
            __nv_bfloat16 h0,l0,h1,l1,h2,l2,h3,l3;
            split_bf16(p0, h0, l0); split_bf16(p1, h1, l1);
            split_bf16(p2, h2, l2); split_bf16(p3, h3, l3);
            int kc = jn >> 1;
            int off = (jn & 1) * 2;
            phi[kc][off]     = pack2(h0, h1);
            phi[kc][off + 1] = pack2(h2, h3);
            plo[kc][off]     = pack2(l0, l1);
            plo[kc][off + 1] = pack2(l2, l3);
        }

        #pragma unroll
        for (int kc = 0; kc < 4; kc++) {
            #pragma unroll
            for (int jd = 0; jd < 8; jd++) {
                int d = jd * 8 + lr;
                uint32_t bhf[2], blf[2];
                bhf[0] = *(const uint32_t*)&Vthi[d][2 * (kc * 8 + lc)];
                bhf[1] = *(const uint32_t*)&Vthi[d][2 * (kc * 8 + lc + 4)];
                blf[0] = *(const uint32_t*)&Vtlo[d][2 * (kc * 8 + lc)];
                blf[1] = *(const uint32_t*)&Vtlo[d][2 * (kc * 8 + lc + 4)];
                mma_bf16(o_acc[jd], phi[kc], blf);
                mma_bf16(o_acc[jd], plo[kc], bhf);
                mma_bf16(o_acc[jd], phi[kc], bhf);
            }
        }
        __syncthreads();
    }

    lrow0 += __shfl_xor_sync(0xffffffffu, lrow0, 1);
    lrow0 += __shfl_xor_sync(0xffffffffu, lrow0, 2);
    lrow1 += __shfl_xor_sync(0xffffffffu, lrow1, 1);
    lrow1 += __shfl_xor_sync(0xffffffffu, lrow1, 2);
    float inv0 = 1.f / lrow0, inv1 = 1.f / lrow1;
    #pragma unroll
    for (int jd = 0; jd < 8; jd++) {
        int col = h * 64 + jd * 8 + 2 * lc;
        float* p0 = o + (long long)(b * L_ + qrow0 + lr) * DM + col;
        p0[0] = o_acc[jd][0] * inv0;
        p0[1] = o_acc[jd][1] * inv0;
        float* p1 = o + (long long)(b * L_ + qrow0 + lr + 8) * DM + col;
        p1[0] = o_acc[jd][2] * inv1;
        p1[1] = o_acc[jd][3] * inv1;
    }
}

// ---------------- tensor-core SSD chunk-states ----------------
__global__ __launch_bounds__(256)
void states_tc_kernel(const float* __restrict__ xbc, const float* __restrict__ xdt,
                      const float* __restrict__ Acs, float* __restrict__ states)
{
    extern __shared__ uint32_t dynst[];
    uint32_t* Ah = dynst;
    uint32_t* Al = Ah + 128 * 36;
    uint32_t* Bh = Al + 128 * 36;
    uint32_t* Bl = Bh + 64 * 36;
    float* dec_sh = (float*)(Bl + 64 * 36);
    __nv_bfloat16* Ah_e = (__nv_bfloat16*)Ah;
    __nv_bfloat16* Al_e = (__nv_bfloat16*)Al;
    __nv_bfloat16* Bh_e = (__nv_bfloat16*)Bh;
    __nv_bfloat16* Bl_e = (__nv_bfloat16*)Bl;

    int blk = blockIdx.x;
    int ck = blk & 7;
    int bh = blk >> 3;
    int h = bh & 31, b = bh >> 5;
    int tid = threadIdx.x;
    int wid = tid >> 5, lane = tid & 31;
    int lr = lane >> 2, lc = lane & 3;
    long long rowbase = (long long)(b * L_ + ck * 256);

    dec_sh[tid] = Acs[(long long)bh * L_ + ck * 256 + tid];
    __syncthreads();
    float aLast = dec_sh[255];
    float mya = dec_sh[tid];
    __syncthreads();
    dec_sh[tid] = __expf(aLast - mya);

    float acc[8][4];
    #pragma unroll
    for (int j = 0; j < 8; j++)
        #pragma unroll
        for (int r = 0; r < 4; r++) acc[j][r] = 0.f;

    for (int kt = 0; kt < 4; kt++) {
        int l0 = kt * 64;
        #pragma unroll
        for (int i = 0; i < 32; i++) {
            int idx = tid + i * 256;
            int n = idx & 127;
            int c = idx >> 7;
            float v = xbc[(rowbase + l0 + c) * CONVD + DI + n] * dec_sh[l0 + c];
            __nv_bfloat16 hi, lo; split_bf16(v, hi, lo);
            Ah_e[n * 72 + c] = hi;
            Al_e[n * 72 + c] = lo;
        }
        #pragma unroll
        for (int i = 0; i < 16; i++) {
            int idx = tid + i * 256;
            int p = idx & 63;
            int c = idx >> 6;
            float v = xdt[(rowbase + l0 + c) * DI + h * 64 + p];
            __nv_bfloat16 hi, lo; split_bf16(v, hi, lo);
            Bh_e[p * 72 + c] = hi;
            Bl_e[p * 72 + c] = lo;
        }
        __syncthreads();
        #pragma unroll
        for (int kk2 = 0; kk2 < 32; kk2 += 8) {
            int r = wid * 16 + lr;
            uint32_t ah[4], al[4];
            ah[0] = Ah[r * 36 + kk2 + lc];
            ah[1] = Ah[(r + 8) * 36 + kk2 + lc];
            ah[2] = Ah[r * 36 + kk2 + lc + 4];
            ah[3] = Ah[(r + 8) * 36 + kk2 + lc + 4];
            al[0] = Al[r * 36 + kk2 + lc];
            al[1] = Al[(r + 8) * 36 + kk2 + lc];
            al[2] = Al[r * 36 + kk2 + lc + 4];
            al[3] = Al[(r + 8) * 36 + kk2 + lc + 4];
            #pragma unroll
            for (int jn = 0; jn < 8; jn++) {
                int n = jn * 8 + lr;
                uint32_t bhf[2], blf[2];
                bhf[0] = Bh[n * 36 + kk2 + lc];
                bhf[1] = Bh[n * 36 + kk2 + lc + 4];
                blf[0] = Bl[n * 36 + kk2 + lc];
                blf[1] = Bl[n * 36 + kk2 + lc + 4];
                mma_bf16(acc[jn], ah, blf);
                mma_bf16(acc[jn], al, bhf);
                mma_bf16(acc[jn], ah, bhf);
            }
        }
        __syncthreads();
    }

    float* base = states + (long long)(bh * NC + ck) * 8192;
    int n0 = wid * 16 + lr;
    #pragma unroll
    for (int jn = 0; jn < 8; jn++) {
        int p = jn * 8 + 2 * lc;
        float* p0 = base + n0 * 64 + p;
        p0[0] = acc[jn][0];
        p0[1] = acc[jn][1];
        float* p1 = base + (n0 + 8) * 64 + p;
        p1[0] = acc[jn][2];
        p1[1] = acc[jn][3];
    }
}

// ---------------- tensor-core SSD output ----------------
__global__ __launch_bounds__(256)
void y_tc_kernel(const float* __restrict__ xbc, const float* __restrict__ xdt,
                 const float* __restrict__ Acs, const float* __restrict__ CB,
                 const float* __restrict__ Sprev, const float* __restrict__ Dv,
                 float* __restrict__ Y)
{
    extern __shared__ uint32_t dyny[];
    uint32_t* Ah = dyny;
    uint32_t* Al = Ah + 128 * 36;
    uint32_t* Bh = Al + 128 * 36;
    uint32_t* Bl = Bh + 64 * 36;
    float* acs_sh = (float*)(Bl + 64 * 36);
    float* eA_sh  = acs_sh + 256;
    __nv_bfloat16* Ah_e = (__nv_bfloat16*)Ah;
    __nv_bfloat16* Al_e = (__nv_bfloat16*)Al;
    __nv_bfloat16* Bh_e = (__nv_bfloat16*)Bh;
    __nv_bfloat16* Bl_e = (__nv_bfloat16*)Bl;

    int blk = blockIdx.x;
    int lh = blk & 1;
    int ck = (blk >> 1) & 7;
    int bh = blk >> 4;
    int h = bh & 31, b = bh >> 5;
    int tid = threadIdx.x;
    int wid = tid >> 5, lane = tid & 31;
    int lr = lane >> 2, lc = lane & 3;
    long long rowbase = (long long)(b * L_ + ck * 256);

    acs_sh[tid] = Acs[(long long)bh * L_ + ck * 256 + tid];
    __syncthreads();
    if (tid < 128) eA_sh[tid] = __expf(acs_sh[lh * 128 + tid]);

    float acc[8][4];
    #pragma unroll
    for (int j = 0; j < 8; j++)
        #pragma unroll
        for (int r = 0; r < 4; r++) acc[j][r] = 0.f;

    const float* cbp = CB + (long long)(b * NC + ck) * (CH * CH);
    int ndiag = (lh == 0) ? 2 : 4;

    for (int kt = 0; kt < ndiag + 2; kt++) {
        if (kt < ndiag) {
            int s0 = kt * 64;
            #pragma unroll
            for (int i = 0; i < 32; i++) {
                int idx = tid + i * 256;
                int l = idx & 127;
                int s = idx >> 7;
                int gl = lh * 128 + l;
                int gs = s0 + s;
                float v = 0.f;
                if (gs <= gl) v = cbp[gs * 256 + gl] * __expf(acs_sh[gl] - acs_sh[gs]);
                __nv_bfloat16 hi, lo; split_bf16(v, hi, lo);
                Ah_e[l * 72 + s] = hi;
                Al_e[l * 72 + s] = lo;
            }
            #pragma unroll
            for (int i = 0; i < 16; i++) {
                int idx = tid + i * 256;
                int p = idx & 63;
                int s = idx >> 6;
                float v = xdt[(rowbase + s0 + s) * DI + h * 64 + p];
                __nv_bfloat16 hi, lo; split_bf16(v, hi, lo);
                Bh_e[p * 72 + s] = hi;
                Bl_e[p * 72 + s] = lo;
            }
        } else {
            int n0 = (kt - ndiag) * 64;
            #pragma unroll
            for (int i = 0; i < 32; i++) {
                int idx = tid + i * 256;
                int c = idx & 63;
                int l = idx >> 6;
                float v = xbc[(rowbase + lh * 128 + l) * CONVD + DI + NST + n0 + c] * eA_sh[l];
                __nv_bfloat16 hi, lo; split_bf16(v, hi, lo);
                Ah_e[l * 72 + c] = hi;
                Al_e[l * 72 + c] = lo;
            }
            #pragma unroll
            for (int i = 0; i < 16; i++) {
                int idx = tid + i * 256;
                int p = idx & 63;
                int c = idx >> 6;
                float v = Sprev[(long long)(bh * NC + ck) * 8192 + (n0 + c) * 64 + p];
                __nv_bfloat16 hi, lo; split_bf16(v, hi, lo);
                Bh_e[p * 72 + c] = hi;
                Bl_e[p * 72 + c] = lo;
            }
        }
        __syncthreads();
        #pragma unroll
        for (int kk2 = 0; kk2 < 32; kk2 += 8) {
            int r = wid * 16 + lr;
            uint32_t ah[4], al[4];
            ah[0] = Ah[r * 36 + kk2 + lc];
            ah[1] = Ah[(r + 8) * 36 + kk2 + lc];
            ah[2] = Ah[r * 36 + kk2 + lc + 4];
            ah[3] = Ah[(r + 8) * 36 + kk2 + lc + 4];
            al[0] = Al[r * 36 + kk2 + lc];
            al[1] = Al[(r + 8) * 36 + kk2 + lc];
            al[2] = Al[r * 36 + kk2 + lc + 4];
            al[3] = Al[(r + 8) * 36 + kk2 + lc + 4];
            #pragma unroll
            for (int jn = 0; jn < 8; jn++) {
                int n = jn * 8 + lr;
                uint32_t bhf[2], blf[2];
                bhf[0] = Bh[n * 36 + kk2 + lc];
                bhf[1] = Bh[n * 36 + kk2 + lc + 4];
                blf[0] = Bl[n * 36 + kk2 + lc];
                blf[1] = Bl[n * 36 + kk2 + lc + 4];
                mma_bf16(acc[jn], ah, blf);
                mma_bf16(acc[jn], al, bhf);
                mma_bf16(acc[jn], ah, bhf);
            }
        }
        __syncthreads();
    }

    float Dh = Dv[h];
    int r0 = wid * 16 + lr;
    #pragma unroll
    for (int jn = 0; jn < 8; jn++) {
        int col = jn * 8 + 2 * lc;
        long long grow0 = rowbase + lh * 128 + r0;
        const float* xs0 = xbc + grow0 * CONVD + h * 64 + col;
        float* yp0 = Y + grow0 * DI + h * 64 + col;
        yp0[0] = acc[jn][0] + Dh * xs0[0];
        yp0[1] = acc[jn][1] + Dh * xs0[1];
        long long grow1 = grow0 + 8;
        const float* xs1 = xbc + grow1 * CONVD + h * 64 + col;
        float* yp1 = Y + grow1 * DI + h * 64 + col;
        yp1[0] = acc[jn][2] + Dh * xs1[0];
        yp1[1] = acc[jn][3] + Dh * xs1[1];
    }
}

// ---------------- rmsnorm (float4) ----------------
__global__ void rmsnorm_kernel(const float* __restrict__ a, const float* __restrict__ b,
                               float alpha, const float* __restrict__ w,
                               float* __restrict__ out, int D)
{
    long long row = blockIdx.x;
    const float4* ap = (const float4*)(a + row * D);
    const float4* bp = b ? (const float4*)(b + row * D) : nullptr;
    int per = D >> 10;
    float4 v[2];
    float ss = 0.f;
    for (int j = 0; j < per; j++) {
        int i = threadIdx.x + j * 256;
        float4 x = ap[i];
        if (bp) {
            float4 y = bp[i];
            x.x += alpha * y.x; x.y += alpha * y.y;
            x.z += alpha * y.z; x.w += alpha * y.w;
        }
        v[j] = x;
        ss += x.x * x.x + x.y * x.y + x.z * x.z + x.w * x.w;
    }
    __shared__ float red[256];
    red[threadIdx.x] = ss;
    __syncthreads();
    for (int off = 128; off; off >>= 1) {
        if (threadIdx.x < off) red[threadIdx.x] += red[threadIdx.x + off];
        __syncthreads();
    }
    float scale = rsqrtf(red[0] / D + EPSN);
    const float4* wp = (const float4*)w;
    float4* op = (float4*)(out + row * D);
    for (int j = 0; j < per; j++) {
        int i = threadIdx.x + j * 256;
        float4 x = v[j], ww = wp[i];
        float4 r;
        r.x = x.x * scale * ww.x; r.y = x.y * scale * ww.y;
        r.z = x.z * scale * ww.z; r.w = x.w * scale * ww.w;
        op[i] = r;
    }
}

// ---------------- gated rmsnorm (float4), D=2048 ----------------
__global__ void gated_rmsnorm_kernel(const float* __restrict__ y, const float* __restrict__ z,
                                     int ldz, const float* __restrict__ w,
                                     float* __restrict__ out)
{
    long long row = blockIdx.x;
    const float4* yp = (const float4*)(y + row * DI);
    const float4* zp = (const float4*)(z + row * (long long)ldz);
    float4 v[2];
    float ss = 0.f;
    #pragma unroll
    for (int j = 0; j < 2; j++) {
        int i = threadIdx.x + j * 256;
        float4 yv = yp[i], zv = zp[i];
        float4 x;
        x.x = yv.x * silu_f(zv.x); x.y = yv.y * silu_f(zv.y);
        x.z = yv.z * silu_f(zv.z); x.w = yv.w * silu_f(zv.w);
        v[j] = x;
        ss += x.x * x.x + x.y * x.y + x.z * x.z + x.w * x.w;
    }
    __shared__ float red[256];
    red[threadIdx.x] = ss;
    __syncthreads();
    for (int off = 128; off; off >>= 1) {
        if (threadIdx.x < off) red[threadIdx.x] += red[threadIdx.x + off];
        __syncthreads();
    }
    float scale = rsqrtf(red[0] / DI + EPSN);
    const float4* wp = (const float4*)w;
    float4* op = (float4*)(out + row * DI);
    #pragma unroll
    for (int j = 0; j < 2; j++) {
        int i = threadIdx.x + j * 256;
        float4 x = v[j], ww = wp[i];
        float4 r;
        r.x = x.x * scale * ww.x; r.y = x.y * scale * ww.y;
        r.z = x.z * scale * ww.z; r.w = x.w * scale * ww.w;
        op[i] = r;
    }
}

// ---------------- depthwise causal conv (k=4) + bias + silu, float4 over channels ----------------
__global__ void conv_kernel(const float* __restrict__ zx, const float* __restrict__ cw,
                            const float* __restrict__ cb, float* __restrict__ xbc)
{
    int idx = blockIdx.x * 256 + threadIdx.x;
    if (idx >= ROWS * (CONVD / 4)) return;
    int c4 = (idx % (CONVD / 4)) << 2;
    int row = idx / (CONVD / 4);
    int t = row % L_;
    int b = row / L_;
    float4 s = *(const float4*)(cb + c4);
    float4 w0 = *(const float4*)(cw + (c4 + 0) * 4);
    float4 w1 = *(const float4*)(cw + (c4 + 1) * 4);
    float4 w2 = *(const float4*)(cw + (c4 + 2) * 4);
    float4 w3 = *(const float4*)(cw + (c4 + 3) * 4);
    const float* wa0 = (const float*)&w0;
    const float* wa1 = (const float*)&w1;
    const float* wa2 = (const float*)&w2;
    const float* wa3 = (const float*)&w3;
    #pragma unroll
    for (int k = 0; k < 4; k++) {
        int tt = t - 3 + k;
        if (tt >= 0) {
            float4 z = *(const float4*)(zx + ((long long)(b * L_ + tt) * DINP) + DI + c4);
            s.x += z.x * wa0[k];
            s.y += z.y * wa1[k];
            s.z += z.z * wa2[k];
            s.w += z.w * wa3[k];
        }
    }
    float4 r;
    r.x = silu_f(s.x); r.y = silu_f(s.y);
    r.z = silu_f(s.z); r.w = silu_f(s.w);
    *(float4*)(xbc + (long long)row * CONVD + c4) = r;
}

// ---------------- dt (softplus) and xdt = xs*dt, float4; dtb written TRANSPOSED ----------------
__global__ void dtxdt_kernel(const float* __restrict__ zx, const float* __restrict__ xbc,
                             const float* __restrict__ dt_bias,
                             float* __restrict__ dtb_t, float* __restrict__ xdt)
{
    int idx = blockIdx.x * 256 + threadIdx.x;
    if (idx >= ROWS * (DI / 4)) return;
    int c = (idx % (DI / 4)) << 2;
    long long row = idx / (DI / 4);
    int h = c >> 6;
    float raw = zx[row * DINP + DI + CONVD + h] + dt_bias[h];
    float d = softplus_f(raw);
    float4 xv = *(const float4*)(xbc + row * CONVD + c);
    float4 r;
    r.x = xv.x * d; r.y = xv.y * d; r.z = xv.z * d; r.w = xv.w * d;
    *(float4*)(xdt + row * DI + c) = r;
    if ((c & 63) == 0) {
        int b = (int)(row / L_);
        int t = (int)(row % L_);
        dtb_t[(long long)(b * HS + h) * L_ + t] = d;
    }
}

// ---------------- per-chunk inclusive cumsum (warp-shuffle scan, coalesced dtb_t) ----------------
__global__ void cumsum_kernel(const float* __restrict__ dtb_t, const float* __restrict__ A_log,
                              float* __restrict__ Acs)
{
    __shared__ float wsum[8];
    int blk = blockIdx.x;
    int ck = blk & 7;
    int bh = blk >> 3;
    int h = bh & 31;
    int l = threadIdx.x;
    int lane = l & 31, wrp = l >> 5;
    float a = -__expf(A_log[h]) * dtb_t[(long long)bh * L_ + ck * 256 + l];
    #pragma unroll
    for (int off = 1; off < 32; off <<= 1) {
        float t = __shfl_up_sync(0xffffffffu, a, off);
        if (lane >= off) a += t;
    }
    if (lane == 31) wsum[wrp] = a;
    __syncthreads();
    float pre = 0.f;
    #pragma unroll
    for (int wv = 0; wv < 8; wv++) {
        float sv = wsum[wv];
        pre += (wv < wrp) ? sv : 0.f;
    }
    Acs[(long long)bh * L_ + ck * 256 + l] = a + pre;
}

// ---------------- inter-chunk scan (float4, 8x parallel) ----------------
__global__ void scan_kernel(const float* __restrict__ states, const float* __restrict__ Acs,
                            float* __restrict__ Sprev)
{
    __shared__ float dc_sh[NC];
    int g = blockIdx.x;
    int seg = g & 7;
    int bh = g >> 3;
    int tid = threadIdx.x;
    if (tid < NC) dc_sh[tid] = __expf(Acs[(long long)bh * L_ + tid * 256 + 255]);
    __syncthreads();
    int off4 = seg * 256 + tid;
    float4 S = make_float4(0.f, 0.f, 0.f, 0.f);
    for (int c = 0; c < NC; c++) {
        float dc = dc_sh[c];
        long long base = ((long long)(bh * NC + c) * 8192) >> 2;
        const float4* sp = (const float4*)states + base + off4;
        float4* pp = (float4*)Sprev + base + off4;
        *pp = S;
        float4 sv = *sp;
        S.x = S.x * dc + sv.x;
        S.y = S.y * dc + sv.y;
        S.z = S.z * dc + sv.z;
        S.w = S.w * dc + sv.w;
    }
}

// ---------------- swiglu (float4) ----------------
__global__ void swiglu_kernel(const float* __restrict__ y, float* __restrict__ ff)
{
    int idx = blockIdx.x * 256 + threadIdx.x;
    if (idx >= ROWS * (DFF / 4)) return;
    long long row = idx / (DFF / 4);
    int f4 = idx % (DFF / 4);
    const float4* yp = (const float4*)(y + row * (2 * DFF));
    float4 a = yp[f4];
    float4 g = yp[f4 + DFF / 4];
    float4 r;
    r.x = a.x * silu_f(g.x); r.y = a.y * silu_f(g.y);
    r.z = a.z * silu_f(g.z); r.w = a.w * silu_f(g.w);
    *(float4*)(ff + row * DFF + f4 * 4) = r;
}

// ---------------- host launcher ----------------
#define SSD_SMEM 57344

extern "C" void kernel_launch(void* const* d_in, const int* in_sizes, int n_in,
                              void* d_out, int out_size)
{
    const float* x_in       = (const float*)d_in[0];
    const float* attn_norm  = (const float*)d_in[1];
    const float* Wqkv       = (const float*)d_in[2];
    const float* Wqkv_b     = (const float*)d_in[3];
    const float* attn_out_w = (const float*)d_in[4];
    const float* attn_out_b = (const float*)d_in[5];
    const float* normf_w    = (const float*)d_in[6];
    const float* m_in_w     = (const float*)d_in[7];
    const float* m_conv_w   = (const float*)d_in[8];
    const float* m_conv_b   = (const float*)d_in[9];
    const float* m_dt_bias  = (const float*)d_in[10];
    const float* m_A_log    = (const float*)d_in[11];
    const float* m_D        = (const float*)d_in[12];
    const float* m_norm_w   = (const float*)d_in[13];
    const float* m_out_w    = (const float*)d_in[14];
    const float* fc1_w      = (const float*)d_in[15];
    const float* fc2_w      = (const float*)d_in[16];
    const float* final_norm = (const float*)d_in[17];
    float* out = (float*)d_out;

    float* scr = nullptr;
    cudaGetSymbolAddress((void**)&scr, g_scratch);

    cudaFuncSetAttribute(states_tc_kernel, cudaFuncAttributeMaxDynamicSharedMemorySize, SSD_SMEM);
    cudaFuncSetAttribute(y_tc_kernel, cudaFuncAttributeMaxDynamicSharedMemorySize, SSD_SMEM);

    float* bBIG = scr + OFF_BIG;
    float* bH   = scr + OFF_H;
    float* bO   = scr + OFF_O;
    float* bX   = scr + OFF_X;
    float* bXBC = scr + OFF_XBC;
    float* bDT  = scr + OFF_DT;
    float* bXDT = scr + OFF_XDT;
    float* bACS = scr + OFF_ACS;
    float* bCB  = scr + OFF_CB;
    float* bSTA = scr + OFF_STA;
    float* bSPR = scr + OFF_SPR;
    float* bY   = scr + OFF_Y;
    float* bFF  = scr + OFF_FF;

    // ---- attention block ----
    rmsnorm_kernel<<<ROWS, 256>>>(x_in, nullptr, 0.f, attn_norm, bH, DM);
    gemm_tc<<<dim3(3072/128, ROWS/128, 1), 256>>>(bH, Wqkv, Wqkv_b, bBIG,
        ROWS, 3072, DM, DM, DM, 3072, 0, 0, 0);
    attn_tc_kernel<<<dim3(L_/256, B_*NH), 512>>>(bBIG, bO);
    gemm_tc<<<dim3(DM/128, ROWS/128, 1), 256>>>(bO, attn_out_w, attn_out_b, bH,
        ROWS, DM, DM, DM, DM, DM, 0, 0, 0);
    rmsnorm_kernel<<<ROWS, 256>>>(bH, x_in, 1.f, normf_w, bX, DM);

    // ---- mamba layers ----
    for (int i = 0; i < 4; i++) {
        const float* in_w   = m_in_w   + (long long)i * DINP * DM;
        const float* conv_w = m_conv_w + (long long)i * CONVD * 4;
        const float* conv_b = m_conv_b + (long long)i * CONVD;
        const float* dtbias = m_dt_bias+ (long long)i * HS;
        const float* Alog   = m_A_log  + (long long)i * HS;
        const float* Dv     = m_D      + (long long)i * HS;
        const float* nw     = m_norm_w + (long long)i * DI;
        const float* ow     = m_out_w  + (long long)i * DM * DI;

        gemm_tc<<<dim3((DINP+127)/128, ROWS/128, 1), 256>>>(bX, in_w, nullptr, bBIG,
            ROWS, DINP, DM, DM, DM, DINP, 0, 0, 0);
        conv_kernel<<<(ROWS*(CONVD/4))/256, 256>>>(bBIG, conv_w, conv_b, bXBC);
        dtxdt_kernel<<<(ROWS*(DI/4))/256, 256>>>(bBIG, bXBC, dtbias, bDT, bXDT);
        cumsum_kernel<<<B_*HS*NC, 256>>>(bDT, Alog, bACS);
        gemm_tc<<<dim3(2, 2, B_*NC), 256>>>(
            bXBC + DI, bXBC + DI + NST, nullptr, bCB,
            CH, CH, NST, CONVD, CONVD, CH,
            (long long)CH * CONVD, (long long)CH * CONVD, (long long)CH * CH);
        states_tc_kernel<<<B_*HS*NC, 256, SSD_SMEM>>>(bXBC, bXDT, bACS, bSTA);
        scan_kernel<<<B_*HS*8, 256>>>(bSTA, bACS, bSPR);
        y_tc_kernel<<<B_*HS*NC*2, 256, SSD_SMEM>>>(bXBC, bXDT, bACS, bCB, bSPR, Dv, bY);
        gated_rmsnorm_kernel<<<ROWS, 256>>>(bY, bBIG, DINP, nw, bY);
        gemm_tc<<<dim3(DM/128, ROWS/128, 1), 256>>>(bY, ow, nullptr, bX,
            ROWS, DM, DI, DI, DI, DM, 0, 0, 0);
    }

    // ---- MLP + final norm ----
    gemm_tc<<<dim3((2*DFF)/128, ROWS/128, 1), 256>>>(bX, fc1_w, nullptr, bBIG,
        ROWS, 2*DFF, DM, DM, DM, 2*DFF, 0, 0, 0);
    swiglu_kernel<<<(ROWS*(DFF/4))/256, 256>>>(bBIG, bFF);
    gemm_tc<<<dim3(DM/128, ROWS/128, 1), 256>>>(bFF, fc2_w, nullptr, bH,
        ROWS, DM, DFF, DFF, DFF, DM, 0, 0, 0);
    rmsnorm_kernel<<<ROWS, 256>>>(bH, bX, ALPHA, final_norm, out, DM);
}

// round 14
// speedup vs baseline: 1.4029x; 1.0109x over previous
#include <cuda_runtime.h>
#include <cuda_bf16.h>
#include <math.h>
#include <stdint.h>

// ---------------- constants ----------------
#define B_   2
#define L_   2048
#define DM   1024          // D_MODEL
#define NH   16            // NHEAD
#define HD   64            // HD_ATT
#define DI   2048          // D_INNER
#define HS   32            // H_SSM
#define P_   64            // HEADDIM
#define NST  128           // D_STATE
#define CONVD 2304         // CONV_DIM
#define DINP 4384          // D_IN_PROJ
#define CH   256           // CHUNK
#define NC   8             // L/CHUNK
#define DFF  2048
#define ALPHA 1.68f
#define EPSN 1e-5f

#define ROWS (B_*L_)       // 4096

// ---------------- scratch ----------------
static const long long SZ_BIG  = (long long)ROWS*DINP;
static const long long SZ_HB   = (long long)ROWS*DM;
static const long long SZ_XBC  = (long long)ROWS*CONVD;
static const long long SZ_DT   = (long long)ROWS*HS;
static const long long SZ_XDT  = (long long)ROWS*DI;
static const long long SZ_ACS  = (long long)B_*HS*L_;
static const long long SZ_CB   = (long long)B_*NC*CH*CH;
static const long long SZ_ST   = (long long)B_*HS*NC*NST*P_;
static const long long SZ_Y    = (long long)ROWS*DI;

static const long long OFF_BIG = 0;
static const long long OFF_H   = OFF_BIG + SZ_BIG;
static const long long OFF_O   = OFF_H   + SZ_HB;
static const long long OFF_X   = OFF_O   + SZ_HB;
static const long long OFF_XBC = OFF_X   + SZ_HB;
static const long long OFF_DT  = OFF_XBC + SZ_XBC;
static const long long OFF_XDT = OFF_DT  + SZ_DT;
static const long long OFF_ACS = OFF_XDT + SZ_XDT;
static const long long OFF_CB  = OFF_ACS + SZ_ACS;
static const long long OFF_STA = OFF_CB  + SZ_CB;
static const long long OFF_SPR = OFF_STA + SZ_ST;
static const long long OFF_Y   = OFF_SPR + SZ_ST;
static const long long OFF_FF  = OFF_Y   + SZ_Y;
static const long long TOTALF  = OFF_FF  + SZ_Y;

__device__ float g_scratch[74842112]; // == TOTALF floats (~300 MB)

// ---------------- helpers ----------------
__device__ __forceinline__ float silu_f(float x) {
    return x / (1.f + __expf(-x));
}
__device__ __forceinline__ float softplus_f(float x) {
    return (x > 20.f) ? x : log1pf(__expf(x));
}
__device__ __forceinline__ void split_bf16(float x, __nv_bfloat16& hi, __nv_bfloat16& lo) {
    hi = __float2bfloat16_rn(x);
    lo = __float2bfloat16_rn(x - __bfloat162float(hi));
}
__device__ __forceinline__ uint32_t pack2(__nv_bfloat16 a, __nv_bfloat16 b) {
    __nv_bfloat162 h;
    h.x = a; h.y = b;
    return *(uint32_t*)&h;
}
__device__ __forceinline__ void mma_bf16(float* c, const uint32_t* a, const uint32_t* b) {
    asm volatile(
        "mma.sync.aligned.m16n8k16.row.col.f32.bf16.bf16.f32 "
        "{%0,%1,%2,%3}, {%4,%5,%6,%7}, {%8,%9}, {%0,%1,%2,%3};"
        : "+f"(c[0]), "+f"(c[1]), "+f"(c[2]), "+f"(c[3])
        : "r"(a[0]), "r"(a[1]), "r"(a[2]), "r"(a[3]), "r"(b[0]), "r"(b[1]));
}

// ---------------- bf16x2 split tensor-core NT GEMM, register-prefetch pipelined ----------------
// Measured-best configuration (R6): static 40KB SMEM, K-tile 32, register LDG prefetch.
#define SSTR 20
__global__ __launch_bounds__(256, 2)
void gemm_tc(const float* __restrict__ A, const float* __restrict__ W,
             const float* __restrict__ bias, float* __restrict__ C,
             int M, int N, int K, int lda, int ldw, int ldc,
             long long sA, long long sW, long long sC)
{
    A += (long long)blockIdx.z * sA;
    W += (long long)blockIdx.z * sW;
    C += (long long)blockIdx.z * sC;

    __shared__ uint32_t Ahi[128][SSTR];
    __shared__ uint32_t Alo[128][SSTR];
    __shared__ uint32_t Bhi[128][SSTR];
    __shared__ uint32_t Blo[128][SSTR];

    int bm = blockIdx.y * 128, bn = blockIdx.x * 128;
    int tid = threadIdx.x;
    int wid = tid >> 5, lane = tid & 31;
    int wm = (wid >> 2) * 64;
    int wn = (wid & 3) * 32;
    int lr = lane >> 2;
    int lc = lane & 3;

    int sr = tid >> 3;
    int sc4 = (tid & 7) << 2;
    int sc2 = sc4 >> 1;

    float acc[4][4][4];
    #pragma unroll
    for (int i = 0; i < 4; i++)
        #pragma unroll
        for (int j = 0; j < 4; j++)
            #pragma unroll
            for (int r = 0; r < 4; r++) acc[i][j][r] = 0.f;

    float4 pa[4], pw[4];
    #pragma unroll
    for (int i = 0; i < 4; i++) {
        int r = sr + i * 32;
        pa[i] = *(const float4*)(A + (long long)(bm + r) * lda + sc4);
        if (bn + r < N) pw[i] = *(const float4*)(W + (long long)(bn + r) * ldw + sc4);
        else            pw[i] = make_float4(0.f, 0.f, 0.f, 0.f);
    }

    for (int k0 = 0; k0 < K; k0 += 32) {
        #pragma unroll
        for (int i = 0; i < 4; i++) {
            int r = sr + i * 32;
            __nv_bfloat16 h0,l0,h1,l1,h2,l2,h3,l3;
            split_bf16(pa[i].x, h0, l0); split_bf16(pa[i].y, h1, l1);
            split_bf16(pa[i].z, h2, l2); split_bf16(pa[i].w, h3, l3);
            Ahi[r][sc2]     = pack2(h0, h1);
            Ahi[r][sc2 + 1] = pack2(h2, h3);
            Alo[r][sc2]     = pack2(l0, l1);
            Alo[r][sc2 + 1] = pack2(l2, l3);
            split_bf16(pw[i].x, h0, l0); split_bf16(pw[i].y, h1, l1);
            split_bf16(pw[i].z, h2, l2); split_bf16(pw[i].w, h3, l3);
            Bhi[r][sc2]     = pack2(h0, h1);
            Bhi[r][sc2 + 1] = pack2(h2, h3);
            Blo[r][sc2]     = pack2(l0, l1);
            Blo[r][sc2 + 1] = pack2(l2, l3);
        }
        __syncthreads();

        if (k0 + 32 < K) {
            int kn = k0 + 32;
            #pragma unroll
            for (int i = 0; i < 4; i++) {
                int r = sr + i * 32;
                pa[i] = *(const float4*)(A + (long long)(bm + r) * lda + kn + sc4);
                if (bn + r < N) pw[i] = *(const float4*)(W + (long long)(bn + r) * ldw + kn + sc4);
                else            pw[i] = make_float4(0.f, 0.f, 0.f, 0.f);
            }
        }

        #pragma unroll
        for (int kk2 = 0; kk2 < 16; kk2 += 8) {
            uint32_t bhf[4][2], blf[4][2];
            #pragma unroll
            for (int jn = 0; jn < 4; jn++) {
                int cdx = wn + jn * 8 + lr;
                bhf[jn][0] = Bhi[cdx][kk2 + lc];
                bhf[jn][1] = Bhi[cdx][kk2 + lc + 4];
                blf[jn][0] = Blo[cdx][kk2 + lc];
                blf[jn][1] = Blo[cdx][kk2 + lc + 4];
            }
            #pragma unroll
            for (int im = 0; im < 4; im++) {
                int r = wm + im * 16 + lr;
                uint32_t ah[4], al[4];
                ah[0] = Ahi[r][kk2 + lc];
                ah[1] = Ahi[r + 8][kk2 + lc];
                ah[2] = Ahi[r][kk2 + lc + 4];
                ah[3] = Ahi[r + 8][kk2 + lc + 4];
                al[0] = Alo[r][kk2 + lc];
                al[1] = Alo[r + 8][kk2 + lc];
                al[2] = Alo[r][kk2 + lc + 4];
                al[3] = Alo[r + 8][kk2 + lc + 4];
                #pragma unroll
                for (int jn = 0; jn < 4; jn++) {
                    mma_bf16(acc[im][jn], ah, blf[jn]);
                    mma_bf16(acc[im][jn], al, bhf[jn]);
                    mma_bf16(acc[im][jn], ah, bhf[jn]);
                }
            }
        }
        __syncthreads();
    }

    #pragma unroll
    for (int im = 0; im < 4; im++) {
        #pragma unroll
        for (int jn = 0; jn < 4; jn++) {
            int gm = bm + wm + im * 16 + lr;
            int gc = bn + wn + jn * 8 + 2 * lc;
            if (gc < N) {
                float b0 = bias ? bias[gc] : 0.f;
                float b1 = bias ? bias[gc + 1] : 0.f;
                float* p0 = C + (long long)gm * ldc + gc;
                p0[0] = acc[im][jn][0] + b0;
                p0[1] = acc[im][jn][1] + b1;
                float* p1 = C + (long long)(gm + 8) * ldc + gc;
                p1[0] = acc[im][jn][2] + b0;
                p1[1] = acc[im][jn][3] + b1;
            }
        }
    }
}

// ---------------- tensor-core flash attention (non-causal), split-bf16 ----------------
// 512 threads = 16 warps; block covers 256 q-rows (halved K/V staging redundancy).
__global__ __launch_bounds__(512)
void attn_tc_kernel(const float* __restrict__ qkv, float* __restrict__ o)
{
    __shared__ uint32_t Khi[64][36];
    __shared__ uint32_t Klo[64][36];
    __shared__ __nv_bfloat16 Vthi[64][72];
    __shared__ __nv_bfloat16 Vtlo[64][72];

    int bh = blockIdx.y;
    int b = bh >> 4, h = bh & 15;
    int tid = threadIdx.x;
    int wid = tid >> 5, lane = tid & 31;
    int lr = lane >> 2, lc = lane & 3;
    int qrow0 = blockIdx.x * 256 + wid * 16;

    uint32_t qhi[4][4], qlo[4][4];
    {
        const float* qp = qkv + (long long)(b * L_) * 3072 + h * 64;
        #pragma unroll
        for (int kc = 0; kc < 4; kc++) {
            #pragma unroll
            for (int half = 0; half < 2; half++) {
                int col = kc * 16 + 2 * lc + half * 8;
                float2 v0 = *(const float2*)(qp + (long long)(qrow0 + lr) * 3072 + col);
                float2 v1 = *(const float2*)(qp + (long long)(qrow0 + lr + 8) * 3072 + col);
                __nv_bfloat16 h0,l0,h1,l1;
                split_bf16(v0.x * 0.125f, h0, l0); split_bf16(v0.y * 0.125f, h1, l1);
                qhi[kc][half * 2]     = pack2(h0, h1);
                qlo[kc][half * 2]     = pack2(l0, l1);
                split_bf16(v1.x * 0.125f, h0, l0); split_bf16(v1.y * 0.125f, h1, l1);
                qhi[kc][half * 2 + 1] = pack2(h0, h1);
                qlo[kc][half * 2 + 1] = pack2(l0, l1);
            }
        }
    }

    float o_acc[8][4];
    #pragma unroll
    for (int j = 0; j < 8; j++)
        #pragma unroll
        for (int r = 0; r < 4; r++) o_acc[j][r] = 0.f;
    float mrow0 = -1e30f, mrow1 = -1e30f;
    float lrow0 = 0.f, lrow1 = 0.f;

    for (int kt = 0; kt < L_ / 64; kt++) {
        const float* kb = qkv + (long long)(b * L_ + kt * 64) * 3072 + 1024 + h * 64;
        const float* vb = kb + 1024;
        #pragma unroll
        for (int i = 0; i < 2; i++) {
            int idx = tid + i * 512;
            int r = idx >> 4, c4 = (idx & 15) << 2;
            float4 kv = *(const float4*)(kb + (long long)r * 3072 + c4);
            __nv_bfloat16 h0,l0,h1,l1,h2,l2,h3,l3;
            split_bf16(kv.x, h0, l0); split_bf16(kv.y, h1, l1);
            split_bf16(kv.z, h2, l2); split_bf16(kv.w, h3, l3);
            int c2 = c4 >> 1;
            Khi[r][c2]     = pack2(h0, h1);
            Khi[r][c2 + 1] = pack2(h2, h3);
            Klo[r][c2]     = pack2(l0, l1);
            Klo[r][c2 + 1] = pack2(l2, l3);
            float4 vv = *(const float4*)(vb + (long long)r * 3072 + c4);
            __nv_bfloat16 vh, vl;
            split_bf16(vv.x, vh, vl); Vthi[c4 + 0][r] = vh; Vtlo[c4 + 0][r] = vl;
            split_bf16(vv.y, vh, vl); Vthi[c4 + 1][r] = vh; Vtlo[c4 + 1][r] = vl;
            split_bf16(vv.z, vh, vl); Vthi[c4 + 2][r] = vh; Vtlo[c4 + 2][r] = vl;
            split_bf16(vv.w, vh, vl); Vthi[c4 + 3][r] = vh; Vtlo[c4 + 3][r] = vl;
        }
        __syncthreads();

        float s[8][4];
        #pragma unroll
        for (int j = 0; j < 8; j++)
            #pragma unroll
            for (int r = 0; r < 4; r++) s[j][r] = 0.f;
        #pragma unroll
        for (int kc = 0; kc < 4; kc++) {
            #pragma unroll
            for (int jn = 0; jn < 8; jn++) {
                int n = jn * 8 + lr;
                uint32_t bhf[2], blf[2];
                bhf[0] = Khi[n][kc * 8 + lc];
                bhf[1] = Khi[n][kc * 8 + lc + 4];
                blf[0] = Klo[n][kc * 8 + lc];
                blf[1] = Klo[n][kc * 8 + lc + 4];
                mma_bf16(s[jn], qhi[kc], blf);
                mma_bf16(s[jn], qlo[kc], bhf);
                mma_bf16(s[jn], qhi[kc], bhf);
            }
        }

        float t0 = -1e30f, t1 = -1e30f;
        #pragma unroll
        for (int jn = 0; jn < 8; jn++) {
            t0 = fmaxf(t0, fmaxf(s[jn][0], s[jn][1]));
            t1 = fmaxf(t1, fmaxf(s[jn][2], s[jn][3]));
        }
        t0 = fmaxf(t0, __shfl_xor_sync(0xffffffffu, t0, 1));
        t0 = fmaxf(t0, __shfl_xor_sync(0xffffffffu, t0, 2));
        t1 = fmaxf(t1, __shfl_xor_sync(0xffffffffu, t1, 1));
        t1 = fmaxf(t1, __shfl_xor_sync(0xffffffffu, t1, 2));
        float m0n = fmaxf(mrow0, t0), m1n = fmaxf(mrow1, t1);
        float sc0 = __expf(mrow0 - m0n), sc1 = __expf(mrow1 - m1n);
        mrow0 = m0n; mrow1 = m1n;
        lrow0 *= sc0; lrow1 *= sc1;
        #pragma unroll
        for (int j = 0; j < 8; j++) {
            o_acc[j][0] *= sc0; o_acc[j][1] *= sc0;
            o_acc[j][2] *= sc1; o_acc[j][3] *= sc1;
        }

        uint32_t phi[4][4], plo[4][4];
        #pragma unroll
        for (int jn = 0; jn < 8; jn++) {
            float p0 = __expf(s[jn][0] - m0n);
            float p1 = __expf(s[jn][1] - m0n);
            float p2 = __expf(s[jn][2] - m1n);
            float p3 = __expf(s[jn][3] - m1n);
            lrow0 += p0 + p1;
            lrow1 += p2 + p3;
            __nv_bfloat16 h0,l0,h1,l1,h2,l2,h3,l3;
            split_bf16(p0, h0, l0); split_bf16(p1, h1, l1);
            split_bf16(p2, h2, l2); split_bf16(p3, h3, l3);
            int kc = jn >> 1;
            int off = (jn & 1) * 2;
            phi[kc][off]     = pack2(h0, h1);
            phi[kc][off + 1] = pack2(h2, h3);
            plo[kc][off]     = pack2(l0, l1);
            plo[kc][off + 1] = pack2(l2, l3);
        }

        #pragma unroll
        for (int kc = 0; kc < 4; kc++) {
            #pragma unroll
            for (int jd = 0; jd < 8; jd++) {
                int d = jd * 8 + lr;
                uint32_t bhf[2], blf[2];
                bhf[0] = *(const uint32_t*)&Vthi[d][2 * (kc * 8 + lc)];
                bhf[1] = *(const uint32_t*)&Vthi[d][2 * (kc * 8 + lc + 4)];
                blf[0] = *(const uint32_t*)&Vtlo[d][2 * (kc * 8 + lc)];
                blf[1] = *(const uint32_t*)&Vtlo[d][2 * (kc * 8 + lc + 4)];
                mma_bf16(o_acc[jd], phi[kc], blf);
                mma_bf16(o_acc[jd], plo[kc], bhf);
                mma_bf16(o_acc[jd], phi[kc], bhf);
            }
        }
        __syncthreads();
    }

    lrow0 += __shfl_xor_sync(0xffffffffu, lrow0, 1);
    lrow0 += __shfl_xor_sync(0xffffffffu, lrow0, 2);
    lrow1 += __shfl_xor_sync(0xffffffffu, lrow1, 1);
    lrow1 += __shfl_xor_sync(0xffffffffu, lrow1, 2);
    float inv0 = 1.f / lrow0, inv1 = 1.f / lrow1;
    #pragma unroll
    for (int jd = 0; jd < 8; jd++) {
        int col = h * 64 + jd * 8 + 2 * lc;
        float* p0 = o + (long long)(b * L_ + qrow0 + lr) * DM + col;
        p0[0] = o_acc[jd][0] * inv0;
        p0[1] = o_acc[jd][1] * inv0;
        float* p1 = o + (long long)(b * L_ + qrow0 + lr + 8) * DM + col;
        p1[0] = o_acc[jd][2] * inv1;
        p1[1] = o_acc[jd][3] * inv1;
    }
}

// ---------------- tensor-core SSD chunk-states + fused chunk cumsum ----------------
// Prologue computes the chunk's Acs (identical warp-shuffle scan as the old
// cumsum_kernel), stores it for scan/y consumers, and derives dec in-place.
__global__ __launch_bounds__(256)
void states_tc_kernel(const float* __restrict__ xbc, const float* __restrict__ xdt,
                      const float* __restrict__ dtb_t, const float* __restrict__ A_log,
                      float* __restrict__ Acs, float* __restrict__ states)
{
    extern __shared__ uint32_t dynst[];
    uint32_t* Ah = dynst;
    uint32_t* Al = Ah + 128 * 36;
    uint32_t* Bh = Al + 128 * 36;
    uint32_t* Bl = Bh + 64 * 36;
    float* dec_sh = (float*)(Bl + 64 * 36);       // 256
    float* wsum   = dec_sh + 256;                 // 8
    __nv_bfloat16* Ah_e = (__nv_bfloat16*)Ah;
    __nv_bfloat16* Al_e = (__nv_bfloat16*)Al;
    __nv_bfloat16* Bh_e = (__nv_bfloat16*)Bh;
    __nv_bfloat16* Bl_e = (__nv_bfloat16*)Bl;

    int blk = blockIdx.x;
    int ck = blk & 7;
    int bh = blk >> 3;
    int h = bh & 31, b = bh >> 5;
    int tid = threadIdx.x;
    int wid = tid >> 5, lane = tid & 31;
    int lr = lane >> 2, lc = lane & 3;
    long long rowbase = (long long)(b * L_ + ck * 256);

    // ---- fused chunk cumsum (same math as old cumsum_kernel) ----
    {
        int wrp = tid >> 5;
        float a = -__expf(A_log[h]) * dtb_t[(long long)bh * L_ + ck * 256 + tid];
        #pragma unroll
        for (int off = 1; off < 32; off <<= 1) {
            float t = __shfl_up_sync(0xffffffffu, a, off);
            if (lane >= off) a += t;
        }
        if (lane == 31) wsum[wrp] = a;
        __syncthreads();
        float pre = 0.f, total = 0.f;
        #pragma unroll
        for (int wv = 0; wv < 8; wv++) {
            float sv = wsum[wv];
            pre += (wv < wrp) ? sv : 0.f;
            total += sv;
        }
        float acs = a + pre;
        Acs[(long long)bh * L_ + ck * 256 + tid] = acs;
        dec_sh[tid] = __expf(total - acs);
    }
    __syncthreads();

    float acc[8][4];
    #pragma unroll
    for (int j = 0; j < 8; j++)
        #pragma unroll
        for (int r = 0; r < 4; r++) acc[j][r] = 0.f;

    for (int kt = 0; kt < 4; kt++) {
        int l0 = kt * 64;
        #pragma unroll
        for (int i = 0; i < 32; i++) {
            int idx = tid + i * 256;
            int n = idx & 127;
            int c = idx >> 7;
            float v = xbc[(rowbase + l0 + c) * CONVD + DI + n] * dec_sh[l0 + c];
            __nv_bfloat16 hi, lo; split_bf16(v, hi, lo);
            Ah_e[n * 72 + c] = hi;
            Al_e[n * 72 + c] = lo;
        }
        #pragma unroll
        for (int i = 0; i < 16; i++) {
            int idx = tid + i * 256;
            int p = idx & 63;
            int c = idx >> 6;
            float v = xdt[(rowbase + l0 + c) * DI + h * 64 + p];
            __nv_bfloat16 hi, lo; split_bf16(v, hi, lo);
            Bh_e[p * 72 + c] = hi;
            Bl_e[p * 72 + c] = lo;
        }
        __syncthreads();
        #pragma unroll
        for (int kk2 = 0; kk2 < 32; kk2 += 8) {
            int r = wid * 16 + lr;
            uint32_t ah[4], al[4];
            ah[0] = Ah[r * 36 + kk2 + lc];
            ah[1] = Ah[(r + 8) * 36 + kk2 + lc];
            ah[2] = Ah[r * 36 + kk2 + lc + 4];
            ah[3] = Ah[(r + 8) * 36 + kk2 + lc + 4];
            al[0] = Al[r * 36 + kk2 + lc];
            al[1] = Al[(r + 8) * 36 + kk2 + lc];
            al[2] = Al[r * 36 + kk2 + lc + 4];
            al[3] = Al[(r + 8) * 36 + kk2 + lc + 4];
            #pragma unroll
            for (int jn = 0; jn < 8; jn++) {
                int n = jn * 8 + lr;
                uint32_t bhf[2], blf[2];
                bhf[0] = Bh[n * 36 + kk2 + lc];
                bhf[1] = Bh[n * 36 + kk2 + lc + 4];
                blf[0] = Bl[n * 36 + kk2 + lc];
                blf[1] = Bl[n * 36 + kk2 + lc + 4];
                mma_bf16(acc[jn], ah, blf);
                mma_bf16(acc[jn], al, bhf);
                mma_bf16(acc[jn], ah, bhf);
            }
        }
        __syncthreads();
    }

    float* base = states + (long long)(bh * NC + ck) * 8192;
    int n0 = wid * 16 + lr;
    #pragma unroll
    for (int jn = 0; jn < 8; jn++) {
        int p = jn * 8 + 2 * lc;
        float* p0 = base + n0 * 64 + p;
        p0[0] = acc[jn][0];
        p0[1] = acc[jn][1];
        float* p1 = base + (n0 + 8) * 64 + p;
        p1[0] = acc[jn][2];
        p1[1] = acc[jn][3];
    }
}

// ---------------- tensor-core SSD output ----------------
__global__ __launch_bounds__(256)
void y_tc_kernel(const float* __restrict__ xbc, const float* __restrict__ xdt,
                 const float* __restrict__ Acs, const float* __restrict__ CB,
                 const float* __restrict__ Sprev, const float* __restrict__ Dv,
                 float* __restrict__ Y)
{
    extern __shared__ uint32_t dyny[];
    uint32_t* Ah = dyny;
    uint32_t* Al = Ah + 128 * 36;
    uint32_t* Bh = Al + 128 * 36;
    uint32_t* Bl = Bh + 64 * 36;
    float* acs_sh = (float*)(Bl + 64 * 36);
    float* eA_sh  = acs_sh + 256;
    __nv_bfloat16* Ah_e = (__nv_bfloat16*)Ah;
    __nv_bfloat16* Al_e = (__nv_bfloat16*)Al;
    __nv_bfloat16* Bh_e = (__nv_bfloat16*)Bh;
    __nv_bfloat16* Bl_e = (__nv_bfloat16*)Bl;

    int blk = blockIdx.x;
    int lh = blk & 1;
    int ck = (blk >> 1) & 7;
    int bh = blk >> 4;
    int h = bh & 31, b = bh >> 5;
    int tid = threadIdx.x;
    int wid = tid >> 5, lane = tid & 31;
    int lr = lane >> 2, lc = lane & 3;
    long long rowbase = (long long)(b * L_ + ck * 256);

    acs_sh[tid] = Acs[(long long)bh * L_ + ck * 256 + tid];
    __syncthreads();
    if (tid < 128) eA_sh[tid] = __expf(acs_sh[lh * 128 + tid]);

    float acc[8][4];
    #pragma unroll
    for (int j = 0; j < 8; j++)
        #pragma unroll
        for (int r = 0; r < 4; r++) acc[j][r] = 0.f;

    const float* cbp = CB + (long long)(b * NC + ck) * (CH * CH);
    int ndiag = (lh == 0) ? 2 : 4;

    for (int kt = 0; kt < ndiag + 2; kt++) {
        if (kt < ndiag) {
            int s0 = kt * 64;
            #pragma unroll
            for (int i = 0; i < 32; i++) {
                int idx = tid + i * 256;
                int l = idx & 127;
                int s = idx >> 7;
                int gl = lh * 128 + l;
                int gs = s0 + s;
                float v = 0.f;
                if (gs <= gl) v = cbp[gs * 256 + gl] * __expf(acs_sh[gl] - acs_sh[gs]);
                __nv_bfloat16 hi, lo; split_bf16(v, hi, lo);
                Ah_e[l * 72 + s] = hi;
                Al_e[l * 72 + s] = lo;
            }
            #pragma unroll
            for (int i = 0; i < 16; i++) {
                int idx = tid + i * 256;
                int p = idx & 63;
                int s = idx >> 6;
                float v = xdt[(rowbase + s0 + s) * DI + h * 64 + p];
                __nv_bfloat16 hi, lo; split_bf16(v, hi, lo);
                Bh_e[p * 72 + s] = hi;
                Bl_e[p * 72 + s] = lo;
            }
        } else {
            int n0 = (kt - ndiag) * 64;
            #pragma unroll
            for (int i = 0; i < 32; i++) {
                int idx = tid + i * 256;
                int c = idx & 63;
                int l = idx >> 6;
                float v = xbc[(rowbase + lh * 128 + l) * CONVD + DI + NST + n0 + c] * eA_sh[l];
                __nv_bfloat16 hi, lo; split_bf16(v, hi, lo);
                Ah_e[l * 72 + c] = hi;
                Al_e[l * 72 + c] = lo;
            }
            #pragma unroll
            for (int i = 0; i < 16; i++) {
                int idx = tid + i * 256;
                int p = idx & 63;
                int c = idx >> 6;
                float v = Sprev[(long long)(bh * NC + ck) * 8192 + (n0 + c) * 64 + p];
                __nv_bfloat16 hi, lo; split_bf16(v, hi, lo);
                Bh_e[p * 72 + c] = hi;
                Bl_e[p * 72 + c] = lo;
            }
        }
        __syncthreads();
        #pragma unroll
        for (int kk2 = 0; kk2 < 32; kk2 += 8) {
            int r = wid * 16 + lr;
            uint32_t ah[4], al[4];
            ah[0] = Ah[r * 36 + kk2 + lc];
            ah[1] = Ah[(r + 8) * 36 + kk2 + lc];
            ah[2] = Ah[r * 36 + kk2 + lc + 4];
            ah[3] = Ah[(r + 8) * 36 + kk2 + lc + 4];
            al[0] = Al[r * 36 + kk2 + lc];
            al[1] = Al[(r + 8) * 36 + kk2 + lc];
            al[2] = Al[r * 36 + kk2 + lc + 4];
            al[3] = Al[(r + 8) * 36 + kk2 + lc + 4];
            #pragma unroll
            for (int jn = 0; jn < 8; jn++) {
                int n = jn * 8 + lr;
                uint32_t bhf[2], blf[2];
                bhf[0] = Bh[n * 36 + kk2 + lc];
                bhf[1] = Bh[n * 36 + kk2 + lc + 4];
                blf[0] = Bl[n * 36 + kk2 + lc];
                blf[1] = Bl[n * 36 + kk2 + lc + 4];
                mma_bf16(acc[jn], ah, blf);
                mma_bf16(acc[jn], al, bhf);
                mma_bf16(acc[jn], ah, bhf);
            }
        }
        __syncthreads();
    }

    float Dh = Dv[h];
    int r0 = wid * 16 + lr;
    #pragma unroll
    for (int jn = 0; jn < 8; jn++) {
        int col = jn * 8 + 2 * lc;
        long long grow0 = rowbase + lh * 128 + r0;
        const float* xs0 = xbc + grow0 * CONVD + h * 64 + col;
        float* yp0 = Y + grow0 * DI + h * 64 + col;
        yp0[0] = acc[jn][0] + Dh * xs0[0];
        yp0[1] = acc[jn][1] + Dh * xs0[1];
        long long grow1 = grow0 + 8;
        const float* xs1 = xbc + grow1 * CONVD + h * 64 + col;
        float* yp1 = Y + grow1 * DI + h * 64 + col;
        yp1[0] = acc[jn][2] + Dh * xs1[0];
        yp1[1] = acc[jn][3] + Dh * xs1[1];
    }
}

// ---------------- rmsnorm (float4) ----------------
__global__ void rmsnorm_kernel(const float* __restrict__ a, const float* __restrict__ b,
                               float alpha, const float* __restrict__ w,
                               float* __restrict__ out, int D)
{
    long long row = blockIdx.x;
    const float4* ap = (const float4*)(a + row * D);
    const float4* bp = b ? (const float4*)(b + row * D) : nullptr;
    int per = D >> 10;
    float4 v[2];
    float ss = 0.f;
    for (int j = 0; j < per; j++) {
        int i = threadIdx.x + j * 256;
        float4 x = ap[i];
        if (bp) {
            float4 y = bp[i];
            x.x += alpha * y.x; x.y += alpha * y.y;
            x.z += alpha * y.z; x.w += alpha * y.w;
        }
        v[j] = x;
        ss += x.x * x.x + x.y * x.y + x.z * x.z + x.w * x.w;
    }
    __shared__ float red[256];
    red[threadIdx.x] = ss;
    __syncthreads();
    for (int off = 128; off; off >>= 1) {
        if (threadIdx.x < off) red[threadIdx.x] += red[threadIdx.x + off];
        __syncthreads();
    }
    float scale = rsqrtf(red[0] / D + EPSN);
    const float4* wp = (const float4*)w;
    float4* op = (float4*)(out + row * D);
    for (int j = 0; j < per; j++) {
        int i = threadIdx.x + j * 256;
        float4 x = v[j], ww = wp[i];
        float4 r;
        r.x = x.x * scale * ww.x; r.y = x.y * scale * ww.y;
        r.z = x.z * scale * ww.z; r.w = x.w * scale * ww.w;
        op[i] = r;
    }
}

// ---------------- gated rmsnorm (float4), D=2048 ----------------
__global__ void gated_rmsnorm_kernel(const float* __restrict__ y, const float* __restrict__ z,
                                     int ldz, const float* __restrict__ w,
                                     float* __restrict__ out)
{
    long long row = blockIdx.x;
    const float4* yp = (const float4*)(y + row * DI);
    const float4* zp = (const float4*)(z + row * (long long)ldz);
    float4 v[2];
    float ss = 0.f;
    #pragma unroll
    for (int j = 0; j < 2; j++) {
        int i = threadIdx.x + j * 256;
        float4 yv = yp[i], zv = zp[i];
        float4 x;
        x.x = yv.x * silu_f(zv.x); x.y = yv.y * silu_f(zv.y);
        x.z = yv.z * silu_f(zv.z); x.w = yv.w * silu_f(zv.w);
        v[j] = x;
        ss += x.x * x.x + x.y * x.y + x.z * x.z + x.w * x.w;
    }
    __shared__ float red[256];
    red[threadIdx.x] = ss;
    __syncthreads();
    for (int off = 128; off; off >>= 1) {
        if (threadIdx.x < off) red[threadIdx.x] += red[threadIdx.x + off];
        __syncthreads();
    }
    float scale = rsqrtf(red[0] / DI + EPSN);
    const float4* wp = (const float4*)w;
    float4* op = (float4*)(out + row * DI);
    #pragma unroll
    for (int j = 0; j < 2; j++) {
        int i = threadIdx.x + j * 256;
        float4 x = v[j], ww = wp[i];
        float4 r;
        r.x = x.x * scale * ww.x; r.y = x.y * scale * ww.y;
        r.z = x.z * scale * ww.z; r.w = x.w * scale * ww.w;
        op[i] = r;
    }
}

// ---------------- depthwise causal conv (k=4) + bias + silu, float4 over channels ----------------
__global__ void conv_kernel(const float* __restrict__ zx, const float* __restrict__ cw,
                            const float* __restrict__ cb, float* __restrict__ xbc)
{
    int idx = blockIdx.x * 256 + threadIdx.x;
    if (idx >= ROWS * (CONVD / 4)) return;
    int c4 = (idx % (CONVD / 4)) << 2;
    int row = idx / (CONVD / 4);
    int t = row % L_;
    int b = row / L_;
    float4 s = *(const float4*)(cb + c4);
    float4 w0 = *(const float4*)(cw + (c4 + 0) * 4);
    float4 w1 = *(const float4*)(cw + (c4 + 1) * 4);
    float4 w2 = *(const float4*)(cw + (c4 + 2) * 4);
    float4 w3 = *(const float4*)(cw + (c4 + 3) * 4);
    const float* wa0 = (const float*)&w0;
    const float* wa1 = (const float*)&w1;
    const float* wa2 = (const float*)&w2;
    const float* wa3 = (const float*)&w3;
    #pragma unroll
    for (int k = 0; k < 4; k++) {
        int tt = t - 3 + k;
        if (tt >= 0) {
            float4 z = *(const float4*)(zx + ((long long)(b * L_ + tt) * DINP) + DI + c4);
            s.x += z.x * wa0[k];
            s.y += z.y * wa1[k];
            s.z += z.z * wa2[k];
            s.w += z.w * wa3[k];
        }
    }
    float4 r;
    r.x = silu_f(s.x); r.y = silu_f(s.y);
    r.z = silu_f(s.z); r.w = silu_f(s.w);
    *(float4*)(xbc + (long long)row * CONVD + c4) = r;
}

// ---------------- dt (softplus) and xdt = xs*dt, float4; dtb written TRANSPOSED ----------------
__global__ void dtxdt_kernel(const float* __restrict__ zx, const float* __restrict__ xbc,
                             const float* __restrict__ dt_bias,
                             float* __restrict__ dtb_t, float* __restrict__ xdt)
{
    int idx = blockIdx.x * 256 + threadIdx.x;
    if (idx >= ROWS * (DI / 4)) return;
    int c = (idx % (DI / 4)) << 2;
    long long row = idx / (DI / 4);
    int h = c >> 6;
    float raw = zx[row * DINP + DI + CONVD + h] + dt_bias[h];
    float d = softplus_f(raw);
    float4 xv = *(const float4*)(xbc + row * CONVD + c);
    float4 r;
    r.x = xv.x * d; r.y = xv.y * d; r.z = xv.z * d; r.w = xv.w * d;
    *(float4*)(xdt + row * DI + c) = r;
    if ((c & 63) == 0) {
        int b = (int)(row / L_);
        int t = (int)(row % L_);
        dtb_t[(long long)(b * HS + h) * L_ + t] = d;
    }
}

// ---------------- inter-chunk scan (float4, 8x parallel) ----------------
__global__ void scan_kernel(const float* __restrict__ states, const float* __restrict__ Acs,
                            float* __restrict__ Sprev)
{
    __shared__ float dc_sh[NC];
    int g = blockIdx.x;
    int seg = g & 7;
    int bh = g >> 3;
    int tid = threadIdx.x;
    if (tid < NC) dc_sh[tid] = __expf(Acs[(long long)bh * L_ + tid * 256 + 255]);
    __syncthreads();
    int off4 = seg * 256 + tid;
    float4 S = make_float4(0.f, 0.f, 0.f, 0.f);
    for (int c = 0; c < NC; c++) {
        float dc = dc_sh[c];
        long long base = ((long long)(bh * NC + c) * 8192) >> 2;
        const float4* sp = (const float4*)states + base + off4;
        float4* pp = (float4*)Sprev + base + off4;
        *pp = S;
        float4 sv = *sp;
        S.x = S.x * dc + sv.x;
        S.y = S.y * dc + sv.y;
        S.z = S.z * dc + sv.z;
        S.w = S.w * dc + sv.w;
    }
}

// ---------------- swiglu (float4) ----------------
__global__ void swiglu_kernel(const float* __restrict__ y, float* __restrict__ ff)
{
    int idx = blockIdx.x * 256 + threadIdx.x;
    if (idx >= ROWS * (DFF / 4)) return;
    long long row = idx / (DFF / 4);
    int f4 = idx % (DFF / 4);
    const float4* yp = (const float4*)(y + row * (2 * DFF));
    float4 a = yp[f4];
    float4 g = yp[f4 + DFF / 4];
    float4 r;
    r.x = a.x * silu_f(g.x); r.y = a.y * silu_f(g.y);
    r.z = a.z * silu_f(g.z); r.w = a.w * silu_f(g.w);
    *(float4*)(ff + row * DFF + f4 * 4) = r;
}

// ---------------- host launcher ----------------
#define SSD_SMEM 57344

extern "C" void kernel_launch(void* const* d_in, const int* in_sizes, int n_in,
                              void* d_out, int out_size)
{
    const float* x_in       = (const float*)d_in[0];
    const float* attn_norm  = (const float*)d_in[1];
    const float* Wqkv       = (const float*)d_in[2];
    const float* Wqkv_b     = (const float*)d_in[3];
    const float* attn_out_w = (const float*)d_in[4];
    const float* attn_out_b = (const float*)d_in[5];
    const float* normf_w    = (const float*)d_in[6];
    const float* m_in_w     = (const float*)d_in[7];
    const float* m_conv_w   = (const float*)d_in[8];
    const float* m_conv_b   = (const float*)d_in[9];
    const float* m_dt_bias  = (const float*)d_in[10];
    const float* m_A_log    = (const float*)d_in[11];
    const float* m_D        = (const float*)d_in[12];
    const float* m_norm_w   = (const float*)d_in[13];
    const float* m_out_w    = (const float*)d_in[14];
    const float* fc1_w      = (const float*)d_in[15];
    const float* fc2_w      = (const float*)d_in[16];
    const float* final_norm = (const float*)d_in[17];
    float* out = (float*)d_out;

    float* scr = nullptr;
    cudaGetSymbolAddress((void**)&scr, g_scratch);

    cudaFuncSetAttribute(states_tc_kernel, cudaFuncAttributeMaxDynamicSharedMemorySize, SSD_SMEM);
    cudaFuncSetAttribute(y_tc_kernel, cudaFuncAttributeMaxDynamicSharedMemorySize, SSD_SMEM);

    float* bBIG = scr + OFF_BIG;
    float* bH   = scr + OFF_H;
    float* bO   = scr + OFF_O;
    float* bX   = scr + OFF_X;
    float* bXBC = scr + OFF_XBC;
    float* bDT  = scr + OFF_DT;
    float* bXDT = scr + OFF_XDT;
    float* bACS = scr + OFF_ACS;
    float* bCB  = scr + OFF_CB;
    float* bSTA = scr + OFF_STA;
    float* bSPR = scr + OFF_SPR;
    float* bY   = scr + OFF_Y;
    float* bFF  = scr + OFF_FF;

    // ---- attention block ----
    rmsnorm_kernel<<<ROWS, 256>>>(x_in, nullptr, 0.f, attn_norm, bH, DM);
    gemm_tc<<<dim3(3072/128, ROWS/128, 1), 256>>>(bH, Wqkv, Wqkv_b, bBIG,
        ROWS, 3072, DM, DM, DM, 3072, 0, 0, 0);
    attn_tc_kernel<<<dim3(L_/256, B_*NH), 512>>>(bBIG, bO);
    gemm_tc<<<dim3(DM/128, ROWS/128, 1), 256>>>(bO, attn_out_w, attn_out_b, bH,
        ROWS, DM, DM, DM, DM, DM, 0, 0, 0);
    rmsnorm_kernel<<<ROWS, 256>>>(bH, x_in, 1.f, normf_w, bX, DM);

    // ---- mamba layers ----
    for (int i = 0; i < 4; i++) {
        const float* in_w   = m_in_w   + (long long)i * DINP * DM;
        const float* conv_w = m_conv_w + (long long)i * CONVD * 4;
        const float* conv_b = m_conv_b + (long long)i * CONVD;
        const float* dtbias = m_dt_bias+ (long long)i * HS;
        const float* Alog   = m_A_log  + (long long)i * HS;
        const float* Dv     = m_D      + (long long)i * HS;
        const float* nw     = m_norm_w + (long long)i * DI;
        const float* ow     = m_out_w  + (long long)i * DM * DI;

        gemm_tc<<<dim3((DINP+127)/128, ROWS/128, 1), 256>>>(bX, in_w, nullptr, bBIG,
            ROWS, DINP, DM, DM, DM, DINP, 0, 0, 0);
        conv_kernel<<<(ROWS*(CONVD/4))/256, 256>>>(bBIG, conv_w, conv_b, bXBC);
        dtxdt_kernel<<<(ROWS*(DI/4))/256, 256>>>(bBIG, bXBC, dtbias, bDT, bXDT);
        gemm_tc<<<dim3(2, 2, B_*NC), 256>>>(
            bXBC + DI, bXBC + DI + NST, nullptr, bCB,
            CH, CH, NST, CONVD, CONVD, CH,
            (long long)CH * CONVD, (long long)CH * CONVD, (long long)CH * CH);
        states_tc_kernel<<<B_*HS*NC, 256, SSD_SMEM>>>(bXBC, bXDT, bDT, Alog, bACS, bSTA);
        scan_kernel<<<B_*HS*8, 256>>>(bSTA, bACS, bSPR);
        y_tc_kernel<<<B_*HS*NC*2, 256, SSD_SMEM>>>(bXBC, bXDT, bACS, bCB, bSPR, Dv, bY);
        gated_rmsnorm_kernel<<<ROWS, 256>>>(bY, bBIG, DINP, nw, bY);
        gemm_tc<<<dim3(DM/128, ROWS/128, 1), 256>>>(bY, ow, nullptr, bX,
            ROWS, DM, DI, DI, DI, DM, 0, 0, 0);
    }

    // ---- MLP + final norm ----
    gemm_tc<<<dim3((2*DFF)/128, ROWS/128, 1), 256>>>(bX, fc1_w, nullptr, bBIG,
        ROWS, 2*DFF, DM, DM, DM, 2*DFF, 0, 0, 0);
    swiglu_kernel<<<(ROWS*(DFF/4))/256, 256>>>(bBIG, bFF);
    gemm_tc<<<dim3(DM/128, ROWS/128, 1), 256>>>(bFF, fc2_w, nullptr, bH,
        ROWS, DM, DFF, DFF, DFF, DM, 0, 0, 0);
    rmsnorm_kernel<<<ROWS, 256>>>(bH, bX, ALPHA, final_norm, out, DM);
}

// round 16
// speedup vs baseline: 1.4239x; 1.0150x over previous
#include <cuda_runtime.h>
#include <cuda_bf16.h>
#include <math.h>
#include <stdint.h>

// ---------------- constants ----------------
#define B_   2
#define L_   2048
#define DM   1024          // D_MODEL
#define NH   16            // NHEAD
#define HD   64            // HD_ATT
#define DI   2048          // D_INNER
#define HS   32            // H_SSM
#define P_   64            // HEADDIM
#define NST  128           // D_STATE
#define CONVD 2304         // CONV_DIM
#define DINP 4384          // D_IN_PROJ
#define CH   256           // CHUNK
#define NC   8             // L/CHUNK
#define DFF  2048
#define ALPHA 1.68f
#define EPSN 1e-5f

#define ROWS (B_*L_)       // 4096

// ---------------- scratch ----------------
static const long long SZ_BIG  = (long long)ROWS*DINP;
static const long long SZ_HB   = (long long)ROWS*DM;
static const long long SZ_XBC  = (long long)ROWS*CONVD;
static const long long SZ_DT   = (long long)ROWS*HS;
static const long long SZ_XDT  = (long long)ROWS*DI;
static const long long SZ_ACS  = (long long)B_*HS*L_;
static const long long SZ_CB   = (long long)B_*NC*CH*CH;
static const long long SZ_ST   = (long long)B_*HS*NC*NST*P_;
static const long long SZ_Y    = (long long)ROWS*DI;

static const long long OFF_BIG = 0;
static const long long OFF_H   = OFF_BIG + SZ_BIG;
static const long long OFF_O   = OFF_H   + SZ_HB;
static const long long OFF_X   = OFF_O   + SZ_HB;
static const long long OFF_XBC = OFF_X   + SZ_HB;
static const long long OFF_DT  = OFF_XBC + SZ_XBC;
static const long long OFF_XDT = OFF_DT  + SZ_DT;
static const long long OFF_ACS = OFF_XDT + SZ_XDT;
static const long long OFF_CB  = OFF_ACS + SZ_ACS;
static const long long OFF_STA = OFF_CB  + SZ_CB;
static const long long OFF_SPR = OFF_STA + SZ_ST;
static const long long OFF_Y   = OFF_SPR + SZ_ST;
static const long long OFF_FF  = OFF_Y   + SZ_Y;
static const long long TOTALF  = OFF_FF  + SZ_Y;

__device__ float g_scratch[74842112]; // == TOTALF floats (~300 MB)

// ---------------- helpers ----------------
__device__ __forceinline__ float silu_f(float x) {
    return x / (1.f + __expf(-x));
}
__device__ __forceinline__ float softplus_f(float x) {
    return (x > 20.f) ? x : log1pf(__expf(x));
}
__device__ __forceinline__ void split_bf16(float x, __nv_bfloat16& hi, __nv_bfloat16& lo) {
    hi = __float2bfloat16_rn(x);
    lo = __float2bfloat16_rn(x - __bfloat162float(hi));
}
__device__ __forceinline__ uint32_t pack2(__nv_bfloat16 a, __nv_bfloat16 b) {
    __nv_bfloat162 h;
    h.x = a; h.y = b;
    return *(uint32_t*)&h;
}
__device__ __forceinline__ void mma_bf16(float* c, const uint32_t* a, const uint32_t* b) {
    asm volatile(
        "mma.sync.aligned.m16n8k16.row.col.f32.bf16.bf16.f32 "
        "{%0,%1,%2,%3}, {%4,%5,%6,%7}, {%8,%9}, {%0,%1,%2,%3};"
        : "+f"(c[0]), "+f"(c[1]), "+f"(c[2]), "+f"(c[3])
        : "r"(a[0]), "r"(a[1]), "r"(a[2]), "r"(a[3]), "r"(b[0]), "r"(b[1]));
}

// ---------------- bf16x2 split tensor-core NT GEMM, register-prefetch pipelined ----------------
// Measured-best configuration (R6): static 40KB SMEM, K-tile 32, register LDG prefetch.
#define SSTR 20
__global__ __launch_bounds__(256, 2)
void gemm_tc(const float* __restrict__ A, const float* __restrict__ W,
             const float* __restrict__ bias, float* __restrict__ C,
             int M, int N, int K, int lda, int ldw, int ldc,
             long long sA, long long sW, long long sC)
{
    A += (long long)blockIdx.z * sA;
    W += (long long)blockIdx.z * sW;
    C += (long long)blockIdx.z * sC;

    __shared__ uint32_t Ahi[128][SSTR];
    __shared__ uint32_t Alo[128][SSTR];
    __shared__ uint32_t Bhi[128][SSTR];
    __shared__ uint32_t Blo[128][SSTR];

    int bm = blockIdx.y * 128, bn = blockIdx.x * 128;
    int tid = threadIdx.x;
    int wid = tid >> 5, lane = tid & 31;
    int wm = (wid >> 2) * 64;
    int wn = (wid & 3) * 32;
    int lr = lane >> 2;
    int lc = lane & 3;

    int sr = tid >> 3;
    int sc4 = (tid & 7) << 2;
    int sc2 = sc4 >> 1;

    float acc[4][4][4];
    #pragma unroll
    for (int i = 0; i < 4; i++)
        #pragma unroll
        for (int j = 0; j < 4; j++)
            #pragma unroll
            for (int r = 0; r < 4; r++) acc[i][j][r] = 0.f;

    float4 pa[4], pw[4];
    #pragma unroll
    for (int i = 0; i < 4; i++) {
        int r = sr + i * 32;
        pa[i] = *(const float4*)(A + (long long)(bm + r) * lda + sc4);
        if (bn + r < N) pw[i] = *(const float4*)(W + (long long)(bn + r) * ldw + sc4);
        else            pw[i] = make_float4(0.f, 0.f, 0.f, 0.f);
    }

    for (int k0 = 0; k0 < K; k0 += 32) {
        #pragma unroll
        for (int i = 0; i < 4; i++) {
            int r = sr + i * 32;
            __nv_bfloat16 h0,l0,h1,l1,h2,l2,h3,l3;
            split_bf16(pa[i].x, h0, l0); split_bf16(pa[i].y, h1, l1);
            split_bf16(pa[i].z, h2, l2); split_bf16(pa[i].w, h3, l3);
            Ahi[r][sc2]     = pack2(h0, h1);
            Ahi[r][sc2 + 1] = pack2(h2, h3);
            Alo[r][sc2]     = pack2(l0, l1);
            Alo[r][sc2 + 1] = pack2(l2, l3);
            split_bf16(pw[i].x, h0, l0); split_bf16(pw[i].y, h1, l1);
            split_bf16(pw[i].z, h2, l2); split_bf16(pw[i].w, h3, l3);
            Bhi[r][sc2]     = pack2(h0, h1);
            Bhi[r][sc2 + 1] = pack2(h2, h3);
            Blo[r][sc2]     = pack2(l0, l1);
            Blo[r][sc2 + 1] = pack2(l2, l3);
        }
        __syncthreads();

        if (k0 + 32 < K) {
            int kn = k0 + 32;
            #pragma unroll
            for (int i = 0; i < 4; i++) {
                int r = sr + i * 32;
                pa[i] = *(const float4*)(A + (long long)(bm + r) * lda + kn + sc4);
                if (bn + r < N) pw[i] = *(const float4*)(W + (long long)(bn + r) * ldw + kn + sc4);
                else            pw[i] = make_float4(0.f, 0.f, 0.f, 0.f);
            }
        }

        #pragma unroll
        for (int kk2 = 0; kk2 < 16; kk2 += 8) {
            uint32_t bhf[4][2], blf[4][2];
            #pragma unroll
            for (int jn = 0; jn < 4; jn++) {
                int cdx = wn + jn * 8 + lr;
                bhf[jn][0] = Bhi[cdx][kk2 + lc];
                bhf[jn][1] = Bhi[cdx][kk2 + lc + 4];
                blf[jn][0] = Blo[cdx][kk2 + lc];
                blf[jn][1] = Blo[cdx][kk2 + lc + 4];
            }
            #pragma unroll
            for (int im = 0; im < 4; im++) {
                int r = wm + im * 16 + lr;
                uint32_t ah[4], al[4];
                ah[0] = Ahi[r][kk2 + lc];
                ah[1] = Ahi[r + 8][kk2 + lc];
                ah[2] = Ahi[r][kk2 + lc + 4];
                ah[3] = Ahi[r + 8][kk2 + lc + 4];
                al[0] = Alo[r][kk2 + lc];
                al[1] = Alo[r + 8][kk2 + lc];
                al[2] = Alo[r][kk2 + lc + 4];
                al[3] = Alo[r + 8][kk2 + lc + 4];
                #pragma unroll
                for (int jn = 0; jn < 4; jn++) {
                    mma_bf16(acc[im][jn], ah, blf[jn]);
                    mma_bf16(acc[im][jn], al, bhf[jn]);
                    mma_bf16(acc[im][jn], ah, bhf[jn]);
                }
            }
        }
        __syncthreads();
    }

    #pragma unroll
    for (int im = 0; im < 4; im++) {
        #pragma unroll
        for (int jn = 0; jn < 4; jn++) {
            int gm = bm + wm + im * 16 + lr;
            int gc = bn + wn + jn * 8 + 2 * lc;
            if (gc < N) {
                float b0 = bias ? bias[gc] : 0.f;
                float b1 = bias ? bias[gc + 1] : 0.f;
                float* p0 = C + (long long)gm * ldc + gc;
                p0[0] = acc[im][jn][0] + b0;
                p0[1] = acc[im][jn][1] + b1;
                float* p1 = C + (long long)(gm + 8) * ldc + gc;
                p1[0] = acc[im][jn][2] + b0;
                p1[1] = acc[im][jn][3] + b1;
            }
        }
    }
}

// ---------------- tensor-core flash attention (non-causal), split-bf16 ----------------
// 512 threads = 16 warps; block covers 256 q-rows (halved K/V staging redundancy).
__global__ __launch_bounds__(512)
void attn_tc_kernel(const float* __restrict__ qkv, float* __restrict__ o)
{
    __shared__ uint32_t Khi[64][36];
    __shared__ uint32_t Klo[64][36];
    __shared__ __nv_bfloat16 Vthi[64][72];
    __shared__ __nv_bfloat16 Vtlo[64][72];

    int bh = blockIdx.y;
    int b = bh >> 4, h = bh & 15;
    int tid = threadIdx.x;
    int wid = tid >> 5, lane = tid & 31;
    int lr = lane >> 2, lc = lane & 3;
    int qrow0 = blockIdx.x * 256 + wid * 16;

    uint32_t qhi[4][4], qlo[4][4];
    {
        const float* qp = qkv + (long long)(b * L_) * 3072 + h * 64;
        #pragma unroll
        for (int kc = 0; kc < 4; kc++) {
            #pragma unroll
            for (int half = 0; half < 2; half++) {
                int col = kc * 16 + 2 * lc + half * 8;
                float2 v0 = *(const float2*)(qp + (long long)(qrow0 + lr) * 3072 + col);
                float2 v1 = *(const float2*)(qp + (long long)(qrow0 + lr + 8) * 3072 + col);
                __nv_bfloat16 h0,l0,h1,l1;
                split_bf16(v0.x * 0.125f, h0, l0); split_bf16(v0.y * 0.125f, h1, l1);
                qhi[kc][half * 2]     = pack2(h0, h1);
                qlo[kc][half * 2]     = pack2(l0, l1);
                split_bf16(v1.x * 0.125f, h0, l0); split_bf16(v1.y * 0.125f, h1, l1);
                qhi[kc][half * 2 + 1] = pack2(h0, h1);
                qlo[kc][half * 2 + 1] = pack2(l0, l1);
            }
        }
    }

    float o_acc[8][4];
    #pragma unroll
    for (int j = 0; j < 8; j++)
        #pragma unroll
        for (int r = 0; r < 4; r++) o_acc[j][r] = 0.f;
    float mrow0 = -1e30f, mrow1 = -1e30f;
    float lrow0 = 0.f, lrow1 = 0.f;

    for (int kt = 0; kt < L_ / 64; kt++) {
        const float* kb = qkv + (long long)(b * L_ + kt * 64) * 3072 + 1024 + h * 64;
        const float* vb = kb + 1024;
        #pragma unroll
        for (int i = 0; i < 2; i++) {
            int idx = tid + i * 512;
            int r = idx >> 4, c4 = (idx & 15) << 2;
            float4 kv = *(const float4*)(kb + (long long)r * 3072 + c4);
            __nv_bfloat16 h0,l0,h1,l1,h2,l2,h3,l3;
            split_bf16(kv.x, h0, l0); split_bf16(kv.y, h1, l1);
            split_bf16(kv.z, h2, l2); split_bf16(kv.w, h3, l3);
            int c2 = c4 >> 1;
            Khi[r][c2]     = pack2(h0, h1);
            Khi[r][c2 + 1] = pack2(h2, h3);
            Klo[r][c2]     = pack2(l0, l1);
            Klo[r][c2 + 1] = pack2(l2, l3);
            float4 vv = *(const float4*)(vb + (long long)r * 3072 + c4);
            __nv_bfloat16 vh, vl;
            split_bf16(vv.x, vh, vl); Vthi[c4 + 0][r] = vh; Vtlo[c4 + 0][r] = vl;
            split_bf16(vv.y, vh, vl); Vthi[c4 + 1][r] = vh; Vtlo[c4 + 1][r] = vl;
            split_bf16(vv.z, vh, vl); Vthi[c4 + 2][r] = vh; Vtlo[c4 + 2][r] = vl;
            split_bf16(vv.w, vh, vl); Vthi[c4 + 3][r] = vh; Vtlo[c4 + 3][r] = vl;
        }
        __syncthreads();

        float s[8][4];
        #pragma unroll
        for (int j = 0; j < 8; j++)
            #pragma unroll
            for (int r = 0; r < 4; r++) s[j][r] = 0.f;
        #pragma unroll
        for (int kc = 0; kc < 4; kc++) {
            #pragma unroll
            for (int jn = 0; jn < 8; jn++) {
                int n = jn * 8 + lr;
                uint32_t bhf[2], blf[2];
                bhf[0] = Khi[n][kc * 8 + lc];
                bhf[1] = Khi[n][kc * 8 + lc + 4];
                blf[0] = Klo[n][kc * 8 + lc];
                blf[1] = Klo[n][kc * 8 + lc + 4];
                mma_bf16(s[jn], qhi[kc], blf);
                mma_bf16(s[jn], qlo[kc], bhf);
                mma_bf16(s[jn], qhi[kc], bhf);
            }
        }

        float t0 = -1e30f, t1 = -1e30f;
        #pragma unroll
        for (int jn = 0; jn < 8; jn++) {
            t0 = fmaxf(t0, fmaxf(s[jn][0], s[jn][1]));
            t1 = fmaxf(t1, fmaxf(s[jn][2], s[jn][3]));
        }
        t0 = fmaxf(t0, __shfl_xor_sync(0xffffffffu, t0, 1));
        t0 = fmaxf(t0, __shfl_xor_sync(0xffffffffu, t0, 2));
        t1 = fmaxf(t1, __shfl_xor_sync(0xffffffffu, t1, 1));
        t1 = fmaxf(t1, __shfl_xor_sync(0xffffffffu, t1, 2));
        float m0n = fmaxf(mrow0, t0), m1n = fmaxf(mrow1, t1);
        float sc0 = __expf(mrow0 - m0n), sc1 = __expf(mrow1 - m1n);
        mrow0 = m0n; mrow1 = m1n;
        lrow0 *= sc0; lrow1 *= sc1;
        #pragma unroll
        for (int j = 0; j < 8; j++) {
            o_acc[j][0] *= sc0; o_acc[j][1] *= sc0;
            o_acc[j][2] *= sc1; o_acc[j][3] *= sc1;
        }

        uint32_t phi[4][4], plo[4][4];
        #pragma unroll
        for (int jn = 0; jn < 8; jn++) {
            float p0 = __expf(s[jn][0] - m0n);
            float p1 = __expf(s[jn][1] - m0n);
            float p2 = __expf(s[jn][2] - m1n);
            float p3 = __expf(s[jn][3] - m1n);
            lrow0 += p0 + p1;
            lrow1 += p2 + p3;
            __nv_bfloat16 h0,l0,h1,l1,h2,l2,h3,l3;
            split_bf16(p0, h0, l0); split_bf16(p1, h1, l1);
            split_bf16(p2, h2, l2); split_bf16(p3, h3, l3);
            int kc = jn >> 1;
            int off = (jn & 1) * 2;
            phi[kc][off]     = pack2(h0, h1);
            phi[kc][off + 1] = pack2(h2, h3);
            plo[kc][off]     = pack2(l0, l1);
            plo[kc][off + 1] = pack2(l2, l3);
        }

        #pragma unroll
        for (int kc = 0; kc < 4; kc++) {
            #pragma unroll
            for (int jd = 0; jd < 8; jd++) {
                int d = jd * 8 + lr;
                uint32_t bhf[2], blf[2];
                bhf[0] = *(const uint32_t*)&Vthi[d][2 * (kc * 8 + lc)];
                bhf[1] = *(const uint32_t*)&Vthi[d][2 * (kc * 8 + lc + 4)];
                blf[0] = *(const uint32_t*)&Vtlo[d][2 * (kc * 8 + lc)];
                blf[1] = *(const uint32_t*)&Vtlo[d][2 * (kc * 8 + lc + 4)];
                mma_bf16(o_acc[jd], phi[kc], blf);
                mma_bf16(o_acc[jd], plo[kc], bhf);
                mma_bf16(o_acc[jd], phi[kc], bhf);
            }
        }
        __syncthreads();
    }

    lrow0 += __shfl_xor_sync(0xffffffffu, lrow0, 1);
    lrow0 += __shfl_xor_sync(0xffffffffu, lrow0, 2);
    lrow1 += __shfl_xor_sync(0xffffffffu, lrow1, 1);
    lrow1 += __shfl_xor_sync(0xffffffffu, lrow1, 2);
    float inv0 = 1.f / lrow0, inv1 = 1.f / lrow1;
    #pragma unroll
    for (int jd = 0; jd < 8; jd++) {
        int col = h * 64 + jd * 8 + 2 * lc;
        float* p0 = o + (long long)(b * L_ + qrow0 + lr) * DM + col;
        p0[0] = o_acc[jd][0] * inv0;
        p0[1] = o_acc[jd][1] * inv0;
        float* p1 = o + (long long)(b * L_ + qrow0 + lr + 8) * DM + col;
        p1[0] = o_acc[jd][2] * inv1;
        p1[1] = o_acc[jd][3] * inv1;
    }
}

// ---------------- tensor-core SSD chunk-states + fused chunk cumsum ----------------
__global__ __launch_bounds__(256)
void states_tc_kernel(const float* __restrict__ xbc, const float* __restrict__ xdt,
                      const float* __restrict__ dtb_t, const float* __restrict__ A_log,
                      float* __restrict__ Acs, float* __restrict__ states)
{
    extern __shared__ uint32_t dynst[];
    uint32_t* Ah = dynst;
    uint32_t* Al = Ah + 128 * 36;
    uint32_t* Bh = Al + 128 * 36;
    uint32_t* Bl = Bh + 64 * 36;
    float* dec_sh = (float*)(Bl + 64 * 36);       // 256
    float* wsum   = dec_sh + 256;                 // 8
    __nv_bfloat16* Ah_e = (__nv_bfloat16*)Ah;
    __nv_bfloat16* Al_e = (__nv_bfloat16*)Al;
    __nv_bfloat16* Bh_e = (__nv_bfloat16*)Bh;
    __nv_bfloat16* Bl_e = (__nv_bfloat16*)Bl;

    int blk = blockIdx.x;
    int ck = blk & 7;
    int bh = blk >> 3;
    int h = bh & 31, b = bh >> 5;
    int tid = threadIdx.x;
    int wid = tid >> 5, lane = tid & 31;
    int lr = lane >> 2, lc = lane & 3;
    long long rowbase = (long long)(b * L_ + ck * 256);

    // ---- fused chunk cumsum (same math as old cumsum_kernel) ----
    {
        int wrp = tid >> 5;
        float a = -__expf(A_log[h]) * dtb_t[(long long)bh * L_ + ck * 256 + tid];
        #pragma unroll
        for (int off = 1; off < 32; off <<= 1) {
            float t = __shfl_up_sync(0xffffffffu, a, off);
            if (lane >= off) a += t;
        }
        if (lane == 31) wsum[wrp] = a;
        __syncthreads();
        float pre = 0.f, total = 0.f;
        #pragma unroll
        for (int wv = 0; wv < 8; wv++) {
            float sv = wsum[wv];
            pre += (wv < wrp) ? sv : 0.f;
            total += sv;
        }
        float acs = a + pre;
        Acs[(long long)bh * L_ + ck * 256 + tid] = acs;
        dec_sh[tid] = __expf(total - acs);
    }
    __syncthreads();

    float acc[8][4];
    #pragma unroll
    for (int j = 0; j < 8; j++)
        #pragma unroll
        for (int r = 0; r < 4; r++) acc[j][r] = 0.f;

    for (int kt = 0; kt < 4; kt++) {
        int l0 = kt * 64;
        #pragma unroll
        for (int i = 0; i < 32; i++) {
            int idx = tid + i * 256;
            int n = idx & 127;
            int c = idx >> 7;
            float v = xbc[(rowbase + l0 + c) * CONVD + DI + n] * dec_sh[l0 + c];
            __nv_bfloat16 hi, lo; split_bf16(v, hi, lo);
            Ah_e[n * 72 + c] = hi;
            Al_e[n * 72 + c] = lo;
        }
        #pragma unroll
        for (int i = 0; i < 16; i++) {
            int idx = tid + i * 256;
            int p = idx & 63;
            int c = idx >> 6;
            float v = xdt[(rowbase + l0 + c) * DI + h * 64 + p];
            __nv_bfloat16 hi, lo; split_bf16(v, hi, lo);
            Bh_e[p * 72 + c] = hi;
            Bl_e[p * 72 + c] = lo;
        }
        __syncthreads();
        #pragma unroll
        for (int kk2 = 0; kk2 < 32; kk2 += 8) {
            int r = wid * 16 + lr;
            uint32_t ah[4], al[4];
            ah[0] = Ah[r * 36 + kk2 + lc];
            ah[1] = Ah[(r + 8) * 36 + kk2 + lc];
            ah[2] = Ah[r * 36 + kk2 + lc + 4];
            ah[3] = Ah[(r + 8) * 36 + kk2 + lc + 4];
            al[0] = Al[r * 36 + kk2 + lc];
            al[1] = Al[(r + 8) * 36 + kk2 + lc];
            al[2] = Al[r * 36 + kk2 + lc + 4];
            al[3] = Al[(r + 8) * 36 + kk2 + lc + 4];
            #pragma unroll
            for (int jn = 0; jn < 8; jn++) {
                int n = jn * 8 + lr;
                uint32_t bhf[2], blf[2];
                bhf[0] = Bh[n * 36 + kk2 + lc];
                bhf[1] = Bh[n * 36 + kk2 + lc + 4];
                blf[0] = Bl[n * 36 + kk2 + lc];
                blf[1] = Bl[n * 36 + kk2 + lc + 4];
                mma_bf16(acc[jn], ah, blf);
                mma_bf16(acc[jn], al, bhf);
                mma_bf16(acc[jn], ah, bhf);
            }
        }
        __syncthreads();
    }

    float* base = states + (long long)(bh * NC + ck) * 8192;
    int n0 = wid * 16 + lr;
    #pragma unroll
    for (int jn = 0; jn < 8; jn++) {
        int p = jn * 8 + 2 * lc;
        float* p0 = base + n0 * 64 + p;
        p0[0] = acc[jn][0];
        p0[1] = acc[jn][1];
        float* p1 = base + (n0 + 8) * 64 + p;
        p1[0] = acc[jn][2];
        p1[1] = acc[jn][3];
    }
}

// ---------------- tensor-core SSD output ----------------
// Diagonal decay factorized with per-16-row-band anchors:
// exp(acs_l - acs_s) = exp(acs_l - acs_band) * exp(acs_band - acs_s).
// Both factor exponents are bounded by the band span (<= ~30), so no
// clamp/underflow interaction in any region with non-negligible true value.
__global__ __launch_bounds__(256)
void y_tc_kernel(const float* __restrict__ xbc, const float* __restrict__ xdt,
                 const float* __restrict__ Acs, const float* __restrict__ CB,
                 const float* __restrict__ Sprev, const float* __restrict__ Dv,
                 float* __restrict__ Y)
{
    extern __shared__ uint32_t dyny[];
    uint32_t* Ah = dyny;
    uint32_t* Al = Ah + 128 * 36;
    uint32_t* Bh = Al + 128 * 36;
    uint32_t* Bl = Bh + 64 * 36;
    float* acs_sh = (float*)(Bl + 64 * 36);   // 256
    float* eA_sh  = acs_sh + 256;             // 128
    float* eL_sh  = eA_sh + 128;              // 128 (band-anchored row factor)
    float* eS_sh  = eL_sh + 128;              // 8 bands x 64 cols = 512
    __nv_bfloat16* Ah_e = (__nv_bfloat16*)Ah;
    __nv_bfloat16* Al_e = (__nv_bfloat16*)Al;
    __nv_bfloat16* Bh_e = (__nv_bfloat16*)Bh;
    __nv_bfloat16* Bl_e = (__nv_bfloat16*)Bl;

    int blk = blockIdx.x;
    int lh = blk & 1;
    int ck = (blk >> 1) & 7;
    int bh = blk >> 4;
    int h = bh & 31, b = bh >> 5;
    int tid = threadIdx.x;
    int wid = tid >> 5, lane = tid & 31;
    int lr = lane >> 2, lc = lane & 3;
    long long rowbase = (long long)(b * L_ + ck * 256);

    acs_sh[tid] = Acs[(long long)bh * L_ + ck * 256 + tid];
    __syncthreads();
    if (tid < 128) {
        eA_sh[tid] = __expf(acs_sh[lh * 128 + tid]);
        // band-anchored row factor: anchor = band start (tid & ~15)
        eL_sh[tid] = __expf(acs_sh[lh * 128 + tid] - acs_sh[lh * 128 + (tid & ~15)]);
    }
    // (eA/eL consumed after per-tile barriers below)

    float acc[8][4];
    #pragma unroll
    for (int j = 0; j < 8; j++)
        #pragma unroll
        for (int r = 0; r < 4; r++) acc[j][r] = 0.f;

    const float* cbp = CB + (long long)(b * NC + ck) * (CH * CH);
    int ndiag = (lh == 0) ? 2 : 4;

    for (int kt = 0; kt < ndiag + 2; kt++) {
        if (kt < ndiag) {
            int s0 = kt * 64;
            // per-tile col factors: eS[band][s] = exp(acs_band - acs_{s0+s})
            #pragma unroll
            for (int i = 0; i < 2; i++) {
                int idx = tid + i * 256;
                int band = idx >> 6;        // 0..7
                int s = idx & 63;
                float e = acs_sh[lh * 128 + band * 16] - acs_sh[s0 + s];
                eS_sh[idx] = __expf(fminf(e, 80.f));
            }
            __syncthreads();
            #pragma unroll
            for (int i = 0; i < 32; i++) {
                int idx = tid + i * 256;
                int l = idx & 127;
                int s = idx >> 7;
                int gl = lh * 128 + l;
                int gs = s0 + s;
                float v = 0.f;
                if (gs <= gl) v = cbp[gs * 256 + gl] * eL_sh[l] * eS_sh[(l >> 4) * 64 + s];
                __nv_bfloat16 hi, lo; split_bf16(v, hi, lo);
                Ah_e[l * 72 + s] = hi;
                Al_e[l * 72 + s] = lo;
            }
            #pragma unroll
            for (int i = 0; i < 16; i++) {
                int idx = tid + i * 256;
                int p = idx & 63;
                int s = idx >> 6;
                float v = xdt[(rowbase + s0 + s) * DI + h * 64 + p];
                __nv_bfloat16 hi, lo; split_bf16(v, hi, lo);
                Bh_e[p * 72 + s] = hi;
                Bl_e[p * 72 + s] = lo;
            }
        } else {
            int n0 = (kt - ndiag) * 64;
            #pragma unroll
            for (int i = 0; i < 32; i++) {
                int idx = tid + i * 256;
                int c = idx & 63;
                int l = idx >> 6;
                float v = xbc[(rowbase + lh * 128 + l) * CONVD + DI + NST + n0 + c] * eA_sh[l];
                __nv_bfloat16 hi, lo; split_bf16(v, hi, lo);
                Ah_e[l * 72 + c] = hi;
                Al_e[l * 72 + c] = lo;
            }
            #pragma unroll
            for (int i = 0; i < 16; i++) {
                int idx = tid + i * 256;
                int p = idx & 63;
                int c = idx >> 6;
                float v = Sprev[(long long)(bh * NC + ck) * 8192 + (n0 + c) * 64 + p];
                __nv_bfloat16 hi, lo; split_bf16(v, hi, lo);
                Bh_e[p * 72 + c] = hi;
                Bl_e[p * 72 + c] = lo;
            }
        }
        __syncthreads();
        #pragma unroll
        for (int kk2 = 0; kk2 < 32; kk2 += 8) {
            int r = wid * 16 + lr;
            uint32_t ah[4], al[4];
            ah[0] = Ah[r * 36 + kk2 + lc];
            ah[1] = Ah[(r + 8) * 36 + kk2 + lc];
            ah[2] = Ah[r * 36 + kk2 + lc + 4];
            ah[3] = Ah[(r + 8) * 36 + kk2 + lc + 4];
            al[0] = Al[r * 36 + kk2 + lc];
            al[1] = Al[(r + 8) * 36 + kk2 + lc];
            al[2] = Al[r * 36 + kk2 + lc + 4];
            al[3] = Al[(r + 8) * 36 + kk2 + lc + 4];
            #pragma unroll
            for (int jn = 0; jn < 8; jn++) {
                int n = jn * 8 + lr;
                uint32_t bhf[2], blf[2];
                bhf[0] = Bh[n * 36 + kk2 + lc];
                bhf[1] = Bh[n * 36 + kk2 + lc + 4];
                blf[0] = Bl[n * 36 + kk2 + lc];
                blf[1] = Bl[n * 36 + kk2 + lc + 4];
                mma_bf16(acc[jn], ah, blf);
                mma_bf16(acc[jn], al, bhf);
                mma_bf16(acc[jn], ah, bhf);
            }
        }
        __syncthreads();
    }

    float Dh = Dv[h];
    int r0 = wid * 16 + lr;
    #pragma unroll
    for (int jn = 0; jn < 8; jn++) {
        int col = jn * 8 + 2 * lc;
        long long grow0 = rowbase + lh * 128 + r0;
        const float* xs0 = xbc + grow0 * CONVD + h * 64 + col;
        float* yp0 = Y + grow0 * DI + h * 64 + col;
        yp0[0] = acc[jn][0] + Dh * xs0[0];
        yp0[1] = acc[jn][1] + Dh * xs0[1];
        long long grow1 = grow0 + 8;
        const float* xs1 = xbc + grow1 * CONVD + h * 64 + col;
        float* yp1 = Y + grow1 * DI + h * 64 + col;
        yp1[0] = acc[jn][2] + Dh * xs1[0];
        yp1[1] = acc[jn][3] + Dh * xs1[1];
    }
}

// ---------------- rmsnorm (float4) ----------------
__global__ void rmsnorm_kernel(const float* __restrict__ a, const float* __restrict__ b,
                               float alpha, const float* __restrict__ w,
                               float* __restrict__ out, int D)
{
    long long row = blockIdx.x;
    const float4* ap = (const float4*)(a + row * D);
    const float4* bp = b ? (const float4*)(b + row * D) : nullptr;
    int per = D >> 10;
    float4 v[2];
    float ss = 0.f;
    for (int j = 0; j < per; j++) {
        int i = threadIdx.x + j * 256;
        float4 x = ap[i];
        if (bp) {
            float4 y = bp[i];
            x.x += alpha * y.x; x.y += alpha * y.y;
            x.z += alpha * y.z; x.w += alpha * y.w;
        }
        v[j] = x;
        ss += x.x * x.x + x.y * x.y + x.z * x.z + x.w * x.w;
    }
    __shared__ float red[256];
    red[threadIdx.x] = ss;
    __syncthreads();
    for (int off = 128; off; off >>= 1) {
        if (threadIdx.x < off) red[threadIdx.x] += red[threadIdx.x + off];
        __syncthreads();
    }
    float scale = rsqrtf(red[0] / D + EPSN);
    const float4* wp = (const float4*)w;
    float4* op = (float4*)(out + row * D);
    for (int j = 0; j < per; j++) {
        int i = threadIdx.x + j * 256;
        float4 x = v[j], ww = wp[i];
        float4 r;
        r.x = x.x * scale * ww.x; r.y = x.y * scale * ww.y;
        r.z = x.z * scale * ww.z; r.w = x.w * scale * ww.w;
        op[i] = r;
    }
}

// ---------------- gated rmsnorm (float4), D=2048 ----------------
__global__ void gated_rmsnorm_kernel(const float* __restrict__ y, const float* __restrict__ z,
                                     int ldz, const float* __restrict__ w,
                                     float* __restrict__ out)
{
    long long row = blockIdx.x;
    const float4* yp = (const float4*)(y + row * DI);
    const float4* zp = (const float4*)(z + row * (long long)ldz);
    float4 v[2];
    float ss = 0.f;
    #pragma unroll
    for (int j = 0; j < 2; j++) {
        int i = threadIdx.x + j * 256;
        float4 yv = yp[i], zv = zp[i];
        float4 x;
        x.x = yv.x * silu_f(zv.x); x.y = yv.y * silu_f(zv.y);
        x.z = yv.z * silu_f(zv.z); x.w = yv.w * silu_f(zv.w);
        v[j] = x;
        ss += x.x * x.x + x.y * x.y + x.z * x.z + x.w * x.w;
    }
    __shared__ float red[256];
    red[threadIdx.x] = ss;
    __syncthreads();
    for (int off = 128; off; off >>= 1) {
        if (threadIdx.x < off) red[threadIdx.x] += red[threadIdx.x + off];
        __syncthreads();
    }
    float scale = rsqrtf(red[0] / DI + EPSN);
    const float4* wp = (const float4*)w;
    float4* op = (float4*)(out + row * DI);
    #pragma unroll
    for (int j = 0; j < 2; j++) {
        int i = threadIdx.x + j * 256;
        float4 x = v[j], ww = wp[i];
        float4 r;
        r.x = x.x * scale * ww.x; r.y = x.y * scale * ww.y;
        r.z = x.z * scale * ww.z; r.w = x.w * scale * ww.w;
        op[i] = r;
    }
}

// ---------------- depthwise causal conv (k=4) + bias + silu, float4 over channels ----------------
__global__ void conv_kernel(const float* __restrict__ zx, const float* __restrict__ cw,
                            const float* __restrict__ cb, float* __restrict__ xbc)
{
    int idx = blockIdx.x * 256 + threadIdx.x;
    if (idx >= ROWS * (CONVD / 4)) return;
    int c4 = (idx % (CONVD / 4)) << 2;
    int row = idx / (CONVD / 4);
    int t = row % L_;
    int b = row / L_;
    float4 s = *(const float4*)(cb + c4);
    float4 w0 = *(const float4*)(cw + (c4 + 0) * 4);
    float4 w1 = *(const float4*)(cw + (c4 + 1) * 4);
    float4 w2 = *(const float4*)(cw + (c4 + 2) * 4);
    float4 w3 = *(const float4*)(cw + (c4 + 3) * 4);
    const float* wa0 = (const float*)&w0;
    const float* wa1 = (const float*)&w1;
    const float* wa2 = (const float*)&w2;
    const float* wa3 = (const float*)&w3;
    #pragma unroll
    for (int k = 0; k < 4; k++) {
        int tt = t - 3 + k;
        if (tt >= 0) {
            float4 z = *(const float4*)(zx + ((long long)(b * L_ + tt) * DINP) + DI + c4);
            s.x += z.x * wa0[k];
            s.y += z.y * wa1[k];
            s.z += z.z * wa2[k];
            s.w += z.w * wa3[k];
        }
    }
    float4 r;
    r.x = silu_f(s.x); r.y = silu_f(s.y);
    r.z = silu_f(s.z); r.w = silu_f(s.w);
    *(float4*)(xbc + (long long)row * CONVD + c4) = r;
}

// ---------------- dt (softplus) and xdt = xs*dt, float4; dtb written TRANSPOSED ----------------
__global__ void dtxdt_kernel(const float* __restrict__ zx, const float* __restrict__ xbc,
                             const float* __restrict__ dt_bias,
                             float* __restrict__ dtb_t, float* __restrict__ xdt)
{
    int idx = blockIdx.x * 256 + threadIdx.x;
    if (idx >= ROWS * (DI / 4)) return;
    int c = (idx % (DI / 4)) << 2;
    long long row = idx / (DI / 4);
    int h = c >> 6;
    float raw = zx[row * DINP + DI + CONVD + h] + dt_bias[h];
    float d = softplus_f(raw);
    float4 xv = *(const float4*)(xbc + row * CONVD + c);
    float4 r;
    r.x = xv.x * d; r.y = xv.y * d; r.z = xv.z * d; r.w = xv.w * d;
    *(float4*)(xdt + row * DI + c) = r;
    if ((c & 63) == 0) {
        int b = (int)(row / L_);
        int t = (int)(row % L_);
        dtb_t[(long long)(b * HS + h) * L_ + t] = d;
    }
}

// ---------------- inter-chunk scan (float4, 8x parallel) ----------------
__global__ void scan_kernel(const float* __restrict__ states, const float* __restrict__ Acs,
                            float* __restrict__ Sprev)
{
    __shared__ float dc_sh[NC];
    int g = blockIdx.x;
    int seg = g & 7;
    int bh = g >> 3;
    int tid = threadIdx.x;
    if (tid < NC) dc_sh[tid] = __expf(Acs[(long long)bh * L_ + tid * 256 + 255]);
    __syncthreads();
    int off4 = seg * 256 + tid;
    float4 S = make_float4(0.f, 0.f, 0.f, 0.f);
    for (int c = 0; c < NC; c++) {
        float dc = dc_sh[c];
        long long base = ((long long)(bh * NC + c) * 8192) >> 2;
        const float4* sp = (const float4*)states + base + off4;
        float4* pp = (float4*)Sprev + base + off4;
        *pp = S;
        float4 sv = *sp;
        S.x = S.x * dc + sv.x;
        S.y = S.y * dc + sv.y;
        S.z = S.z * dc + sv.z;
        S.w = S.w * dc + sv.w;
    }
}

// ---------------- swiglu (float4) ----------------
__global__ void swiglu_kernel(const float* __restrict__ y, float* __restrict__ ff)
{
    int idx = blockIdx.x * 256 + threadIdx.x;
    if (idx >= ROWS * (DFF / 4)) return;
    long long row = idx / (DFF / 4);
    int f4 = idx % (DFF / 4);
    const float4* yp = (const float4*)(y + row * (2 * DFF));
    float4 a = yp[f4];
    float4 g = yp[f4 + DFF / 4];
    float4 r;
    r.x = a.x * silu_f(g.x); r.y = a.y * silu_f(g.y);
    r.z = a.z * silu_f(g.z); r.w = a.w * silu_f(g.w);
    *(float4*)(ff + row * DFF + f4 * 4) = r;
}

// ---------------- host launcher ----------------
#define SSD_SMEM 59392

extern "C" void kernel_launch(void* const* d_in, const int* in_sizes, int n_in,
                              void* d_out, int out_size)
{
    const float* x_in       = (const float*)d_in[0];
    const float* attn_norm  = (const float*)d_in[1];
    const float* Wqkv       = (const float*)d_in[2];
    const float* Wqkv_b     = (const float*)d_in[3];
    const float* attn_out_w = (const float*)d_in[4];
    const float* attn_out_b = (const float*)d_in[5];
    const float* normf_w    = (const float*)d_in[6];
    const float* m_in_w     = (const float*)d_in[7];
    const float* m_conv_w   = (const float*)d_in[8];
    const float* m_conv_b   = (const float*)d_in[9];
    const float* m_dt_bias  = (const float*)d_in[10];
    const float* m_A_log    = (const float*)d_in[11];
    const float* m_D        = (const float*)d_in[12];
    const float* m_norm_w   = (const float*)d_in[13];
    const float* m_out_w    = (const float*)d_in[14];
    const float* fc1_w      = (const float*)d_in[15];
    const float* fc2_w      = (const float*)d_in[16];
    const float* final_norm = (const float*)d_in[17];
    float* out = (float*)d_out;

    float* scr = nullptr;
    cudaGetSymbolAddress((void**)&scr, g_scratch);

    cudaFuncSetAttribute(states_tc_kernel, cudaFuncAttributeMaxDynamicSharedMemorySize, SSD_SMEM);
    cudaFuncSetAttribute(y_tc_kernel, cudaFuncAttributeMaxDynamicSharedMemorySize, SSD_SMEM);

    float* bBIG = scr + OFF_BIG;
    float* bH   = scr + OFF_H;
    float* bO   = scr + OFF_O;
    float* bX   = scr + OFF_X;
    float* bXBC = scr + OFF_XBC;
    float* bDT  = scr + OFF_DT;
    float* bXDT = scr + OFF_XDT;
    float* bACS = scr + OFF_ACS;
    float* bCB  = scr + OFF_CB;
    float* bSTA = scr + OFF_STA;
    float* bSPR = scr + OFF_SPR;
    float* bY   = scr + OFF_Y;
    float* bFF  = scr + OFF_FF;

    // ---- attention block ----
    rmsnorm_kernel<<<ROWS, 256>>>(x_in, nullptr, 0.f, attn_norm, bH, DM);
    gemm_tc<<<dim3(3072/128, ROWS/128, 1), 256>>>(bH, Wqkv, Wqkv_b, bBIG,
        ROWS, 3072, DM, DM, DM, 3072, 0, 0, 0);
    attn_tc_kernel<<<dim3(L_/256, B_*NH), 512>>>(bBIG, bO);
    gemm_tc<<<dim3(DM/128, ROWS/128, 1), 256>>>(bO, attn_out_w, attn_out_b, bH,
        ROWS, DM, DM, DM, DM, DM, 0, 0, 0);
    rmsnorm_kernel<<<ROWS, 256>>>(bH, x_in, 1.f, normf_w, bX, DM);

    // ---- mamba layers ----
    for (int i = 0; i < 4; i++) {
        const float* in_w   = m_in_w   + (long long)i * DINP * DM;
        const float* conv_w = m_conv_w + (long long)i * CONVD * 4;
        const float* conv_b = m_conv_b + (long long)i * CONVD;
        const float* dtbias = m_dt_bias+ (long long)i * HS;
        const float* Alog   = m_A_log  + (long long)i * HS;
        const float* Dv     = m_D      + (long long)i * HS;
        const float* nw     = m_norm_w + (long long)i * DI;
        const float* ow     = m_out_w  + (long long)i * DM * DI;

        gemm_tc<<<dim3((DINP+127)/128, ROWS/128, 1), 256>>>(bX, in_w, nullptr, bBIG,
            ROWS, DINP, DM, DM, DM, DINP, 0, 0, 0);
        conv_kernel<<<(ROWS*(CONVD/4))/256, 256>>>(bBIG, conv_w, conv_b, bXBC);
        dtxdt_kernel<<<(ROWS*(DI/4))/256, 256>>>(bBIG, bXBC, dtbias, bDT, bXDT);
        gemm_tc<<<dim3(2, 2, B_*NC), 256>>>(
            bXBC + DI, bXBC + DI + NST, nullptr, bCB,
            CH, CH, NST, CONVD, CONVD, CH,
            (long long)CH * CONVD, (long long)CH * CONVD, (long long)CH * CH);
        states_tc_kernel<<<B_*HS*NC, 256, SSD_SMEM>>>(bXBC, bXDT, bDT, Alog, bACS, bSTA);
        scan_kernel<<<B_*HS*8, 256>>>(bSTA, bACS, bSPR);
        y_tc_kernel<<<B_*HS*NC*2, 256, SSD_SMEM>>>(bXBC, bXDT, bACS, bCB, bSPR, Dv, bY);
        gated_rmsnorm_kernel<<<ROWS, 256>>>(bY, bBIG, DINP, nw, bY);
        gemm_tc<<<dim3(DM/128, ROWS/128, 1), 256>>>(bY, ow, nullptr, bX,
            ROWS, DM, DI, DI, DI, DM, 0, 0, 0);
    }

    // ---- MLP + final norm ----
    gemm_tc<<<dim3((2*DFF)/128, ROWS/128, 1), 256>>>(bX, fc1_w, nullptr, bBIG,
        ROWS, 2*DFF, DM, DM, DM, 2*DFF, 0, 0, 0);
    swiglu_kernel<<<(ROWS*(DFF/4))/256, 256>>>(bBIG, bFF);
    gemm_tc<<<dim3(DM/128, ROWS/128, 1), 256>>>(bFF, fc2_w, nullptr, bH,
        ROWS, DM, DFF, DFF, DFF, DM, 0, 0, 0);
    rmsnorm_kernel<<<ROWS, 256>>>(bH, bX, ALPHA, final_norm, out, DM);
}